// round 11
// baseline (speedup 1.0000x reference)
#include <cuda_runtime.h>
#include <cuda_bf16.h>
#include <cstdint>
#include <math.h>

#define Bn     64
#define Tn     1024
#define FRAMEn 512
#define ENCn   256
#define HIDn   512
#define G4n    2048
#define NBLK   128
#define GSIZE  32
#define WROW   516
#define APAD   40      // smem row stride (bf16) for mma tiles

// ---------------- static device scratch (no cudaMalloc allowed) --------------
__device__ float g_encoded[(size_t)Bn * Tn * ENCn];
__device__ float g_buf[(size_t)Bn * Tn * ENCn];
__device__ float g_pre[(size_t)Bn * Tn * G4n];
__device__ float g_x1[(size_t)Bn * Tn * HIDn];
__device__ float g_h[2][Bn * HIDn];
__device__ unsigned g_cnt[4];       // init-barrier per b-block
__device__ unsigned g_gen[4];
__device__ unsigned g_cnt2[16];     // sub-group barriers (bb*4+s), counting
__device__ unsigned g_gen2[16];
__device__ __nv_bfloat16 g_ah[(size_t)Bn * Tn * HIDn];
__device__ __nv_bfloat16 g_al[(size_t)Bn * Tn * HIDn];
__device__ __nv_bfloat16 g_wh[(size_t)G4n * HIDn];
__device__ __nv_bfloat16 g_wl[(size_t)G4n * HIDn];

// ---------------- acquire/release primitives ---------------------------------
__device__ __forceinline__ unsigned atom_add_release(unsigned* p, unsigned v) {
    unsigned old;
    asm volatile("atom.add.release.gpu.global.u32 %0, [%1], %2;"
                 : "=r"(old) : "l"(p), "r"(v) : "memory");
    return old;
}
__device__ __forceinline__ unsigned ld_acquire(const unsigned* p) {
    unsigned v;
    asm volatile("ld.acquire.gpu.global.u32 %0, [%1];" : "=r"(v) : "l"(p) : "memory");
    return v;
}
__device__ __forceinline__ void st_relaxed(unsigned* p, unsigned v) {
    asm volatile("st.relaxed.gpu.global.u32 [%0], %1;" :: "l"(p), "r"(v) : "memory");
}
__device__ __forceinline__ void red_add_release(unsigned* p, unsigned v) {
    asm volatile("red.add.release.gpu.global.u32 [%0], %1;" :: "l"(p), "r"(v) : "memory");
}
__device__ __forceinline__ void group_sync(int g) {
    __syncthreads();
    if (threadIdx.x == 0) {
        const unsigned gen = ld_acquire(&g_gen[g]);
        if (atom_add_release(&g_cnt[g], 1u) == GSIZE - 1) {
            st_relaxed(&g_cnt[g], 0u);
            red_add_release(&g_gen[g], 1u);
        } else {
            while (ld_acquire(&g_gen[g]) == gen) { }
        }
    }
    __syncthreads();
}

// ---------------- packed f32x2 helpers ----------------------------------------
__device__ __forceinline__ void fma2(unsigned long long& d,
                                     unsigned long long a, unsigned long long b) {
    asm("fma.rn.f32x2 %0, %1, %2, %0;" : "+l"(d) : "l"(a), "l"(b));
}
__device__ __forceinline__ unsigned long long bcast2(float v) {
    unsigned long long d;
    asm("mov.b64 %0, {%1, %1};" : "=l"(d) : "r"(__float_as_uint(v)));
    return d;
}
__device__ __forceinline__ float lo2(unsigned long long v) {
    return __uint_as_float((unsigned)v);
}
__device__ __forceinline__ float hi2(unsigned long long v) {
    return __uint_as_float((unsigned)(v >> 32));
}
__device__ __forceinline__ float psum(unsigned long long v) { return lo2(v) + hi2(v); }

// ---------------- mma.sync helpers ---------------------------------------------
__device__ __forceinline__ uint32_t smem_u32(const void* p) {
    uint32_t a;
    asm("{ .reg .u64 t; cvta.to.shared.u64 t, %1; cvt.u32.u64 %0, t; }" : "=r"(a) : "l"(p));
    return a;
}
__device__ __forceinline__ void ldmx4(uint32_t& r0, uint32_t& r1, uint32_t& r2,
                                      uint32_t& r3, uint32_t addr) {
    asm volatile("ldmatrix.sync.aligned.m8n8.x4.shared.b16 {%0,%1,%2,%3}, [%4];"
                 : "=r"(r0), "=r"(r1), "=r"(r2), "=r"(r3) : "r"(addr));
}
__device__ __forceinline__ void mma16816(float* d, const uint32_t* a,
                                         const uint32_t* b) {
    asm volatile(
        "mma.sync.aligned.m16n8k16.row.col.f32.bf16.bf16.f32 "
        "{%0,%1,%2,%3}, {%4,%5,%6,%7}, {%8,%9}, {%0,%1,%2,%3};"
        : "+f"(d[0]), "+f"(d[1]), "+f"(d[2]), "+f"(d[3])
        : "r"(a[0]), "r"(a[1]), "r"(a[2]), "r"(a[3]), "r"(b[0]), "r"(b[1]));
}

// =============================================================================
// split-bf16 HMMA GEMM: C[M,N] = (Ah+Al)[M,K] @ (Bh+Bl)[N,K]^T + b1[n]+b2[n]
// =============================================================================
__global__ void __launch_bounds__(256) gemm_mma(
    const __nv_bfloat16* __restrict__ Ah, const __nv_bfloat16* __restrict__ Al,
    const __nv_bfloat16* __restrict__ Bh, const __nv_bfloat16* __restrict__ Bl,
    float* __restrict__ C, const float* __restrict__ b1, const float* __restrict__ b2,
    int M, int N, int K)
{
    __shared__ __nv_bfloat16 sAh[128 * APAD], sAl[128 * APAD];
    __shared__ __nv_bfloat16 sBh[128 * APAD], sBl[128 * APAD];

    const int tid  = threadIdx.x;
    const int wid  = tid >> 5, lane = tid & 31;
    const int wm   = wid >> 2;
    const int wn   = wid & 3;
    const int n0   = blockIdx.x * 128;
    const size_t m0 = (size_t)blockIdx.y * 128;

    const uint32_t bAh = smem_u32(sAh), bAl = smem_u32(sAl);
    const uint32_t bBh = smem_u32(sBh), bBl = smem_u32(sBl);

    const int lq = lane >> 3, lr = lane & 7;
    const int aRow = (lq & 1) * 8 + lr;
    const int aK   = (lq >> 1) * 8;
    const int bRow = (lq >> 1) * 8 + lr;
    const int bK   = (lq & 1) * 8;

    float acc[4][4][4];
#pragma unroll
    for (int i = 0; i < 4; i++)
#pragma unroll
        for (int j = 0; j < 4; j++)
#pragma unroll
            for (int k = 0; k < 4; k++) acc[i][j][k] = 0.f;

    const int nch = K >> 5;
    for (int ch = 0; ch < nch; ch++) {
        const int k0 = ch << 5;
#pragma unroll
        for (int j = 0; j < 2; j++) {
            const int idx = tid + j * 256;
            const int r = idx >> 2, s = idx & 3;
            const size_t ga = (m0 + r) * K + k0 + s * 8;
            const size_t gb = (size_t)(n0 + r) * K + k0 + s * 8;
            *(uint4*)(sAh + r * APAD + s * 8) = *(const uint4*)(Ah + ga);
            *(uint4*)(sAl + r * APAD + s * 8) = *(const uint4*)(Al + ga);
            *(uint4*)(sBh + r * APAD + s * 8) = *(const uint4*)(Bh + gb);
            *(uint4*)(sBl + r * APAD + s * 8) = *(const uint4*)(Bl + gb);
        }
        __syncthreads();

#pragma unroll
        for (int ks = 0; ks < 2; ks++) {
            uint32_t ah[4][4], al[4][4], bh[4][2], bl[4][2];
#pragma unroll
            for (int mt = 0; mt < 4; mt++) {
                const uint32_t off =
                    (uint32_t)((wm * 64 + mt * 16 + aRow) * APAD + ks * 16 + aK) * 2;
                ldmx4(ah[mt][0], ah[mt][1], ah[mt][2], ah[mt][3], bAh + off);
                ldmx4(al[mt][0], al[mt][1], al[mt][2], al[mt][3], bAl + off);
            }
#pragma unroll
            for (int p = 0; p < 2; p++) {
                const uint32_t off =
                    (uint32_t)((wn * 32 + p * 16 + bRow) * APAD + ks * 16 + bK) * 2;
                uint32_t r0, r1, r2, r3;
                ldmx4(r0, r1, r2, r3, bBh + off);
                bh[p * 2][0] = r0; bh[p * 2][1] = r1;
                bh[p * 2 + 1][0] = r2; bh[p * 2 + 1][1] = r3;
                ldmx4(r0, r1, r2, r3, bBl + off);
                bl[p * 2][0] = r0; bl[p * 2][1] = r1;
                bl[p * 2 + 1][0] = r2; bl[p * 2 + 1][1] = r3;
            }
#pragma unroll
            for (int mt = 0; mt < 4; mt++)
#pragma unroll
                for (int nt = 0; nt < 4; nt++) {
                    mma16816(acc[mt][nt], ah[mt], bh[nt]);
                    mma16816(acc[mt][nt], ah[mt], bl[nt]);
                    mma16816(acc[mt][nt], al[mt], bh[nt]);
                }
        }
        __syncthreads();
    }

    const int g = lane >> 2;
    const int cl = (lane & 3) * 2;
#pragma unroll
    for (int nt = 0; nt < 4; nt++) {
        const int n = n0 + wn * 32 + nt * 8 + cl;
        const float bx = b1[n] + b2[n];
        const float by = b1[n + 1] + b2[n + 1];
#pragma unroll
        for (int mt = 0; mt < 4; mt++) {
            const size_t r0 = m0 + wm * 64 + mt * 16 + g;
            float2 v0 = make_float2(acc[mt][nt][0] + bx, acc[mt][nt][1] + by);
            float2 v1 = make_float2(acc[mt][nt][2] + bx, acc[mt][nt][3] + by);
            *(float2*)(C + r0 * N + n)       = v0;
            *(float2*)(C + (r0 + 8) * N + n) = v1;
        }
    }
}

// ---------------- fp32 -> (hi, lo) bf16 splitter ------------------------------
__global__ void __launch_bounds__(256) split_kernel(
    const float* __restrict__ x, __nv_bfloat16* __restrict__ hi,
    __nv_bfloat16* __restrict__ lo, int n4)
{
    const int i = blockIdx.x * 256 + threadIdx.x;
    if (i >= n4) return;
    const float4 v = ((const float4*)x)[i];
    __nv_bfloat162 h0 = __floats2bfloat162_rn(v.x, v.y);
    __nv_bfloat162 h1 = __floats2bfloat162_rn(v.z, v.w);
    __nv_bfloat162 l0 = __floats2bfloat162_rn(v.x - __bfloat162float(h0.x),
                                              v.y - __bfloat162float(h0.y));
    __nv_bfloat162 l1 = __floats2bfloat162_rn(v.z - __bfloat162float(h1.x),
                                              v.w - __bfloat162float(h1.y));
    ((__nv_bfloat162*)hi)[i * 2]     = h0;
    ((__nv_bfloat162*)hi)[i * 2 + 1] = h1;
    ((__nv_bfloat162*)lo)[i * 2]     = l0;
    ((__nv_bfloat162*)lo)[i * 2 + 1] = l1;
}

// =============================================================================
// SIMT fp32 GEMM (f32x2 accumulators, double-buffered) for enc/mask/dec.
// =============================================================================
template <int TRANS_A, int EPI>
__global__ void __launch_bounds__(256, 2) gemm_k(
    const float* __restrict__ A, const float* __restrict__ Bm,
    float* __restrict__ C, const float* __restrict__ E,
    const float* __restrict__ bias1, const float* __restrict__ bias2,
    int M, int N, int K, size_t sA, size_t sB, size_t sC)
{
    __shared__ float As[2][8 * 128];
    __shared__ float Bs[2][8 * 128];

    const int tid = threadIdx.x;
    const size_t z = blockIdx.z;
    const float* Ab = A + z * sA;
    const float* Bb = Bm + z * sB;
    float*       Cb = C + z * sC;
    const float* Eb = (EPI == 2) ? (E + z * sC) : (const float*)0;

    const int n0 = blockIdx.x * 128;
    const int m0 = blockIdx.y * 128;
    const int tx = tid & 15;
    const int ty = tid >> 4;
    const int row  = tid >> 1;
    const int half = tid & 1;
    const int kr   = tid >> 5;
    const int mc   = tid & 31;

    unsigned long long acc2[4][8];
#pragma unroll
    for (int ip = 0; ip < 4; ip++)
#pragma unroll
        for (int j = 0; j < 8; j++) acc2[ip][j] = 0ull;

    float4 pa, pb;
    if (TRANS_A) pa = *(const float4*)(Ab + (size_t)kr * M + m0 + mc * 4);
    else         pa = *(const float4*)(Ab + (size_t)(m0 + row) * K + half * 4);
    pb = *(const float4*)(Bb + (size_t)(n0 + row) * K + half * 4);

    if (TRANS_A) {
        *(float4*)&As[0][kr * 128 + mc * 4] = pa;
    } else {
        As[0][(half * 4 + 0) * 128 + row] = pa.x;
        As[0][(half * 4 + 1) * 128 + row] = pa.y;
        As[0][(half * 4 + 2) * 128 + row] = pa.z;
        As[0][(half * 4 + 3) * 128 + row] = pa.w;
    }
    Bs[0][(half * 4 + 0) * 128 + row] = pb.x;
    Bs[0][(half * 4 + 1) * 128 + row] = pb.y;
    Bs[0][(half * 4 + 2) * 128 + row] = pb.z;
    Bs[0][(half * 4 + 3) * 128 + row] = pb.w;
    __syncthreads();

    int buf = 0;
    for (int k0 = 0; k0 < K; k0 += 8) {
        const bool more = (k0 + 8 < K);
        if (more) {
            if (TRANS_A) pa = *(const float4*)(Ab + (size_t)(k0 + 8 + kr) * M + m0 + mc * 4);
            else         pa = *(const float4*)(Ab + (size_t)(m0 + row) * K + k0 + 8 + half * 4);
            pb = *(const float4*)(Bb + (size_t)(n0 + row) * K + k0 + 8 + half * 4);
        }
#pragma unroll
        for (int kk = 0; kk < 8; kk++) {
            ulonglong2 aA = *(const ulonglong2*)&As[buf][kk * 128 + ty * 8];
            ulonglong2 aB = *(const ulonglong2*)&As[buf][kk * 128 + ty * 8 + 4];
            float bv[8];
            *(float4*)(bv)     = *(const float4*)&Bs[buf][kk * 128 + tx * 8];
            *(float4*)(bv + 4) = *(const float4*)&Bs[buf][kk * 128 + tx * 8 + 4];
#pragma unroll
            for (int j = 0; j < 8; j++) {
                const unsigned long long bj = bcast2(bv[j]);
                fma2(acc2[0][j], aA.x, bj);
                fma2(acc2[1][j], aA.y, bj);
                fma2(acc2[2][j], aB.x, bj);
                fma2(acc2[3][j], aB.y, bj);
            }
        }
        if (more) {
            const int nb = buf ^ 1;
            if (TRANS_A) {
                *(float4*)&As[nb][kr * 128 + mc * 4] = pa;
            } else {
                As[nb][(half * 4 + 0) * 128 + row] = pa.x;
                As[nb][(half * 4 + 1) * 128 + row] = pa.y;
                As[nb][(half * 4 + 2) * 128 + row] = pa.z;
                As[nb][(half * 4 + 3) * 128 + row] = pa.w;
            }
            Bs[nb][(half * 4 + 0) * 128 + row] = pb.x;
            Bs[nb][(half * 4 + 1) * 128 + row] = pb.y;
            Bs[nb][(half * 4 + 2) * 128 + row] = pb.z;
            Bs[nb][(half * 4 + 3) * 128 + row] = pb.w;
            __syncthreads();
            buf = nb;
        }
    }

#pragma unroll
    for (int ip = 0; ip < 4; ip++) {
#pragma unroll
        for (int hf = 0; hf < 2; hf++) {
            const int i = ip * 2 + hf;
            const int m = m0 + ty * 8 + i;
            float* crow = Cb + (size_t)m * N;
#pragma unroll
            for (int j = 0; j < 8; j += 4) {
                const int n = n0 + tx * 8 + j;
                float4 v;
                v.x = hf ? hi2(acc2[ip][j])     : lo2(acc2[ip][j]);
                v.y = hf ? hi2(acc2[ip][j + 1]) : lo2(acc2[ip][j + 1]);
                v.z = hf ? hi2(acc2[ip][j + 2]) : lo2(acc2[ip][j + 2]);
                v.w = hf ? hi2(acc2[ip][j + 3]) : lo2(acc2[ip][j + 3]);
                if (EPI == 1) {
                    v.x += bias1[n]     + bias2[n];
                    v.y += bias1[n + 1] + bias2[n + 1];
                    v.z += bias1[n + 2] + bias2[n + 2];
                    v.w += bias1[n + 3] + bias2[n + 3];
                } else if (EPI == 2) {
                    float4 e = *(const float4*)(Eb + (size_t)m * N + n);
                    v.x = e.x / (1.f + expf(-(v.x + bias1[n])));
                    v.y = e.y / (1.f + expf(-(v.y + bias1[n + 1])));
                    v.z = e.z / (1.f + expf(-(v.z + bias1[n + 2])));
                    v.w = e.w / (1.f + expf(-(v.w + bias1[n + 3])));
                }
                *(float4*)(crow + n) = v;
            }
        }
    }
}

// ---------------- layernorm -> bf16 hi/lo -------------------------------------
__global__ void __launch_bounds__(256) ln_kernel(
    const float* __restrict__ in, __nv_bfloat16* __restrict__ hi,
    __nv_bfloat16* __restrict__ lo,
    const float* __restrict__ gam, const float* __restrict__ bet)
{
    const int row  = blockIdx.x * 8 + (threadIdx.x >> 5);
    const int lane = threadIdx.x & 31;
    const float* r = in + (size_t)row * ENCn + lane * 8;
    float4 a  = *(const float4*)r;
    float4 b4 = *(const float4*)(r + 4);
    float s  = a.x + a.y + a.z + a.w + b4.x + b4.y + b4.z + b4.w;
    float sq = a.x*a.x + a.y*a.y + a.z*a.z + a.w*a.w
             + b4.x*b4.x + b4.y*b4.y + b4.z*b4.z + b4.w*b4.w;
#pragma unroll
    for (int o = 16; o; o >>= 1) {
        s  += __shfl_xor_sync(0xFFFFFFFFu, s,  o);
        sq += __shfl_xor_sync(0xFFFFFFFFu, sq, o);
    }
    const float mu   = s * (1.f / 256.f);
    const float var  = sq * (1.f / 256.f) - mu * mu;
    const float rstd = rsqrtf(var + 1e-5f);

    const float* gg = gam + lane * 8;
    const float* bb = bet + lane * 8;
    float4 ga = *(const float4*)gg,  gb  = *(const float4*)(gg + 4);
    float4 ba = *(const float4*)bb,  bbv = *(const float4*)(bb + 4);
    float o8[8];
    o8[0] = (a.x  - mu) * rstd * ga.x + ba.x;
    o8[1] = (a.y  - mu) * rstd * ga.y + ba.y;
    o8[2] = (a.z  - mu) * rstd * ga.z + ba.z;
    o8[3] = (a.w  - mu) * rstd * ga.w + ba.w;
    o8[4] = (b4.x - mu) * rstd * gb.x + bbv.x;
    o8[5] = (b4.y - mu) * rstd * gb.y + bbv.y;
    o8[6] = (b4.z - mu) * rstd * gb.z + bbv.z;
    o8[7] = (b4.w - mu) * rstd * gb.w + bbv.w;

    const size_t base = (size_t)row * ENCn + lane * 8;
#pragma unroll
    for (int k = 0; k < 8; k += 2) {
        __nv_bfloat162 h = __floats2bfloat162_rn(o8[k], o8[k + 1]);
        __nv_bfloat162 l = __floats2bfloat162_rn(o8[k]     - __bfloat162float(h.x),
                                                 o8[k + 1] - __bfloat162float(h.y));
        *(__nv_bfloat162*)(hi + base + k) = h;
        *(__nv_bfloat162*)(lo + base + k) = l;
    }
}

// =============================================================================
// persistent LSTM v6: 4 pipelined sub-groups of 4 batches per b-block.
// Grid 128 = 32 ub x 4 bb; 512 threads. Main map: thread = (ks 0..31, ul 0..15).
// Sub-iteration: wait(s) -> h load -> compute -> reduce -> epilogue(64thr) -> arrive.
// Barrier round-trip hidden behind the other 3 sub-groups' compute.
// =============================================================================
__global__ void __launch_bounds__(512) lstm_kernel(
    const float* __restrict__ pre, const float* __restrict__ Whh,
    const float* __restrict__ h0,  const float* __restrict__ c0,
    float* __restrict__ xout, __nv_bfloat16* __restrict__ bfh,
    __nv_bfloat16* __restrict__ bfl,
    float* __restrict__ hout, float* __restrict__ cout)
{
    extern __shared__ float sm[];
    float* sW = sm;                       // 64 x WROW
    float* sH = sm + 64 * WROW;           // 4 x WROW
    float* sR = sm + 68 * WROW;           // 32 x 64 x float4 = 8192 floats

    const int tid = threadIdx.x, cta = blockIdx.x;
    const int ub  = cta & 31, bb = cta >> 5;
    const int ks  = tid >> 4;             // 0..31 k-part (16 k each)
    const int ul  = tid & 15;             // unit-local
    const bool e_on = (tid < 64);
    const int ul_e  = tid >> 2;           // epilogue unit (0..15)
    const int b_e   = tid & 3;            // epilogue batch within sub
    const int gu    = ub * 16 + ul_e;

    // load Whh slice (rows g*512 + ub*16+r)
    for (int i = tid; i < 64 * 128; i += 512) {
        const int r  = i >> 7;
        const int k4 = i & 127;
        const int g  = r >> 4;
        const int uu = ub * 16 + (r & 15);
        *(float4*)(sW + r * WROW + k4 * 4) =
            *(const float4*)(Whh + ((size_t)(g * HIDn + uu)) * HIDn + k4 * 4);
    }
    if (tid < 256) g_h[0][cta * 256 + tid] = h0[cta * 256 + tid];

    float c[4], hl[4];
    if (e_on) {
#pragma unroll
        for (int s = 0; s < 4; s++)
            c[s] = c0[(bb * 16 + s * 4 + b_e) * HIDn + gu];
    }
    group_sync(bb);
    // read monotonic bases for the 4 sub-barriers (uniform across threads)
    unsigned base[4];
#pragma unroll
    for (int s = 0; s < 4; s++) base[s] = ld_acquire(&g_gen2[bb * 4 + s]);
    group_sync(bb);   // nobody arrives before everyone has read the bases

    const float* wp0 = sW + (0 * 16 + ul) * WROW + ks * 16;
    const float* wp1 = sW + (1 * 16 + ul) * WROW + ks * 16;
    const float* wp2 = sW + (2 * 16 + ul) * WROW + ks * 16;
    const float* wp3 = sW + (3 * 16 + ul) * WROW + ks * 16;
    const float* hp  = sH + ks * 16;

    for (int t = 0; t < Tn; t++) {
#pragma unroll 1
        for (int s = 0; s < 4; s++) {
            const int g = bb * 4 + s;
            // pre prefetch (independent of barrier; consumed at epilogue)
            float p0 = 0.f, p1 = 0.f, p2 = 0.f, p3 = 0.f;
            if (e_on) {
                const float* pb = pre +
                    ((size_t)(bb * 16 + s * 4 + b_e) * Tn + t) * G4n + gu;
                p0 = pb[0]; p1 = pb[512]; p2 = pb[1024]; p3 = pb[1536];
            }
            // wait for this sub's h(t) from all 32 CTAs
            if (t > 0 && tid == 0) {
                const unsigned bs = base[s];
                while ((int)(ld_acquire(&g_gen2[g]) - bs) < t) { }
            }
            __syncthreads();
            // cooperative h(s) load: 4 rows x 512 = 512 float4 (one per thread)
            {
                const int row = tid >> 7, k4 = tid & 127;
                *(float4*)(sH + row * WROW + k4 * 4) =
                    *(const float4*)(g_h[t & 1] +
                        (size_t)(bb * 16 + s * 4 + row) * HIDn + k4 * 4);
            }
            __syncthreads();

            unsigned long long acc[16];   // [g*4 + b]
#pragma unroll
            for (int i = 0; i < 16; i++) acc[i] = 0ull;
#pragma unroll
            for (int i = 0; i < 4; i++) {
                const ulonglong2 h0q = *(const ulonglong2*)(hp + 0 * WROW + i * 4);
                const ulonglong2 h1q = *(const ulonglong2*)(hp + 1 * WROW + i * 4);
                const ulonglong2 h2q = *(const ulonglong2*)(hp + 2 * WROW + i * 4);
                const ulonglong2 h3q = *(const ulonglong2*)(hp + 3 * WROW + i * 4);
                ulonglong2 w;
                w = *(const ulonglong2*)(wp0 + i * 4);
                fma2(acc[0], w.x, h0q.x);  fma2(acc[0], w.y, h0q.y);
                fma2(acc[1], w.x, h1q.x);  fma2(acc[1], w.y, h1q.y);
                fma2(acc[2], w.x, h2q.x);  fma2(acc[2], w.y, h2q.y);
                fma2(acc[3], w.x, h3q.x);  fma2(acc[3], w.y, h3q.y);
                w = *(const ulonglong2*)(wp1 + i * 4);
                fma2(acc[4], w.x, h0q.x);  fma2(acc[4], w.y, h0q.y);
                fma2(acc[5], w.x, h1q.x);  fma2(acc[5], w.y, h1q.y);
                fma2(acc[6], w.x, h2q.x);  fma2(acc[6], w.y, h2q.y);
                fma2(acc[7], w.x, h3q.x);  fma2(acc[7], w.y, h3q.y);
                w = *(const ulonglong2*)(wp2 + i * 4);
                fma2(acc[8], w.x, h0q.x);  fma2(acc[8], w.y, h0q.y);
                fma2(acc[9], w.x, h1q.x);  fma2(acc[9], w.y, h1q.y);
                fma2(acc[10], w.x, h2q.x); fma2(acc[10], w.y, h2q.y);
                fma2(acc[11], w.x, h3q.x); fma2(acc[11], w.y, h3q.y);
                w = *(const ulonglong2*)(wp3 + i * 4);
                fma2(acc[12], w.x, h0q.x); fma2(acc[12], w.y, h0q.y);
                fma2(acc[13], w.x, h1q.x); fma2(acc[13], w.y, h1q.y);
                fma2(acc[14], w.x, h2q.x); fma2(acc[14], w.y, h2q.y);
                fma2(acc[15], w.x, h3q.x); fma2(acc[15], w.y, h3q.y);
            }
            // partials: [ks][slot=ul*4+b] float4 = gates i,f,g,o
#pragma unroll
            for (int b = 0; b < 4; b++)
                *(float4*)(sR + (size_t)(ks * 64 + ul * 4 + b) * 4) =
                    make_float4(psum(acc[b]), psum(acc[4 + b]),
                                psum(acc[8 + b]), psum(acc[12 + b]));
            __syncthreads();

            if (e_on) {   // 64 threads: slot == tid; conflict-free column reads
                float gi = p0, gf = p1, gc = p2, go = p3;
#pragma unroll 8
                for (int k2 = 0; k2 < 32; k2++) {
                    const float4 v = *(const float4*)(sR + (size_t)(k2 * 64 + tid) * 4);
                    gi += v.x; gf += v.y; gc += v.z; go += v.w;
                }
                const float si = __fdividef(1.f, 1.f + __expf(-gi));
                const float sf = __fdividef(1.f, 1.f + __expf(-gf));
                const float so = __fdividef(1.f, 1.f + __expf(-go));
                const float tg = 2.f * __fdividef(1.f, 1.f + __expf(-2.f * gc)) - 1.f;
                c[s] = sf * c[s] + si * tg;
                const float tc = 2.f * __fdividef(1.f, 1.f + __expf(-2.f * c[s])) - 1.f;
                const float hn = so * tc;
                hl[s] = hn;
                const int gbat = bb * 16 + s * 4 + b_e;
                const size_t xo = ((size_t)gbat * Tn + t) * HIDn + gu;
                if (bfh) {
                    __nv_bfloat16 hh = __float2bfloat16(hn);
                    bfh[xo] = hh;
                    bfl[xo] = __float2bfloat16(hn - __bfloat162float(hh));
                } else {
                    xout[xo] = hn;
                }
                g_h[(t + 1) & 1][gbat * HIDn + gu] = hn;
            }
            __syncthreads();
            if (tid == 0) {
                if (atom_add_release(&g_cnt2[g], 1u) == GSIZE - 1) {
                    st_relaxed(&g_cnt2[g], 0u);
                    red_add_release(&g_gen2[g], 1u);
                }
            }
        }
    }

    if (e_on) {
#pragma unroll
        for (int s = 0; s < 4; s++) {
            const int gbat = bb * 16 + s * 4 + b_e;
            hout[gbat * HIDn + gu] = hl[s];
            cout[gbat * HIDn + gu] = c[s];
        }
    }
}

// =============================================================================
extern "C" void kernel_launch(void* const* d_in, const int* in_sizes, int n_in,
                              void* d_out, int out_size)
{
    const float* x      = (const float*)d_in[0];
    const float* states = (const float*)d_in[1];
    const float* W_enc  = (const float*)d_in[2];
    const float* ln_g   = (const float*)d_in[3];
    const float* ln_b   = (const float*)d_in[4];
    const float* Wih1   = (const float*)d_in[5];
    const float* Whh1   = (const float*)d_in[6];
    const float* bih1   = (const float*)d_in[7];
    const float* bhh1   = (const float*)d_in[8];
    const float* Wih2   = (const float*)d_in[9];
    const float* Whh2   = (const float*)d_in[10];
    const float* bih2   = (const float*)d_in[11];
    const float* bhh2   = (const float*)d_in[12];
    const float* Wlin   = (const float*)d_in[13];
    const float* blin   = (const float*)d_in[14];
    const float* W_dec  = (const float*)d_in[15];

    float* out     = (float*)d_out;
    float* dstates = out + (size_t)Bn * FRAMEn * Tn;

    float *encoded, *buf, *pre, *x1;
    __nv_bfloat16 *ah, *al, *wh, *wl;
    cudaGetSymbolAddress((void**)&encoded, g_encoded);
    cudaGetSymbolAddress((void**)&buf,     g_buf);
    cudaGetSymbolAddress((void**)&pre,     g_pre);
    cudaGetSymbolAddress((void**)&x1,      g_x1);
    cudaGetSymbolAddress((void**)&ah,      g_ah);
    cudaGetSymbolAddress((void**)&al,      g_al);
    cudaGetSymbolAddress((void**)&wh,      g_wh);
    cudaGetSymbolAddress((void**)&wl,      g_wl);

    static int attr_set = 0;
    const int LSTM_SMEM = (68 * WROW + 32 * 64 * 4) * 4;   // 173,120 B
    if (!attr_set) {
        cudaFuncSetAttribute(lstm_kernel,
                             cudaFuncAttributeMaxDynamicSharedMemorySize, LSTM_SMEM);
        attr_set = 1;
    }

    const int BH = Bn * HIDn;

    // 1) encoder (fp32 SIMT)
    gemm_k<1, 0><<<dim3(ENCn / 128, Tn / 128, Bn), 256>>>(
        x, W_enc, encoded, 0, 0, 0,
        Tn, ENCn, FRAMEn, (size_t)FRAMEn * Tn, 0, (size_t)Tn * ENCn);

    // 2) layernorm -> bf16 hi/lo
    ln_kernel<<<(Bn * Tn) / 8, 256>>>(encoded, ah, al, ln_g, ln_b);

    // 3) pre1 (HMMA split-bf16)
    split_kernel<<<(G4n * ENCn / 4 + 255) / 256, 256>>>(Wih1, wh, wl, G4n * ENCn / 4);
    gemm_mma<<<dim3(G4n / 128, (Bn * Tn) / 128), 256>>>(
        ah, al, wh, wl, pre, bih1, bhh1, Bn * Tn, G4n, ENCn);

    // 4) LSTM layer 1 (emits x1 as bf16 hi/lo)
    lstm_kernel<<<NBLK, 512, LSTM_SMEM>>>(
        pre, Whh1, states + 0 * BH, states + 1 * BH,
        x1, ah, al, dstates + 0 * BH, dstates + 1 * BH);

    // 5) pre2 (HMMA split-bf16)
    split_kernel<<<(G4n * HIDn / 4 + 255) / 256, 256>>>(Wih2, wh, wl, G4n * HIDn / 4);
    gemm_mma<<<dim3(G4n / 128, (Bn * Tn) / 128), 256>>>(
        ah, al, wh, wl, pre, bih2, bhh2, Bn * Tn, G4n, HIDn);

    // 6) LSTM layer 2 (fp32 x2 -> g_x1)
    lstm_kernel<<<NBLK, 512, LSTM_SMEM>>>(
        pre, Whh2, states + 2 * BH, states + 3 * BH,
        x1, (__nv_bfloat16*)0, (__nv_bfloat16*)0,
        dstates + 2 * BH, dstates + 3 * BH);

    // 7) est = sigmoid(x2 @ Wlin^T + blin) * encoded
    gemm_k<0, 2><<<dim3(ENCn / 128, (Bn * Tn) / 128, 1), 256>>>(
        x1, Wlin, buf, encoded, blin, 0,
        Bn * Tn, ENCn, HIDn, 0, 0, 0);

    // 8) decoder
    gemm_k<0, 0><<<dim3(Tn / 128, FRAMEn / 128, Bn), 256>>>(
        W_dec, buf, out, 0, 0, 0,
        FRAMEn, Tn, ENCn, 0, (size_t)Tn * ENCn, (size_t)FRAMEn * Tn);
}

// round 12
// speedup vs baseline: 2.1221x; 2.1221x over previous
#include <cuda_runtime.h>
#include <cuda_bf16.h>
#include <cstdint>
#include <math.h>

#define Bn     64
#define Tn     1024
#define FRAMEn 512
#define ENCn   256
#define HIDn   512
#define G4n    2048
#define NBLK   128
#define GSIZE  32
#define WROW   516
#define RSTR   20
#define APAD   40      // smem row stride (bf16) for mma tiles

// ---------------- static device scratch (no cudaMalloc allowed) --------------
__device__ float g_encoded[(size_t)Bn * Tn * ENCn];
__device__ float g_buf[(size_t)Bn * Tn * ENCn];
__device__ float g_pre[(size_t)Bn * Tn * G4n];
__device__ float g_x1[(size_t)Bn * Tn * HIDn];
__device__ float g_h[2][Bn * HIDn];
__device__ unsigned g_cnt[4];          // init barriers (self-resetting)
__device__ unsigned g_gen[4];
__device__ unsigned g_flag[NBLK * 32]; // per-CTA monotonic flags, 128B apart
__device__ __nv_bfloat16 g_ah[(size_t)Bn * Tn * HIDn];
__device__ __nv_bfloat16 g_al[(size_t)Bn * Tn * HIDn];
__device__ __nv_bfloat16 g_wh[(size_t)G4n * HIDn];
__device__ __nv_bfloat16 g_wl[(size_t)G4n * HIDn];

// ---------------- acquire/release primitives ---------------------------------
__device__ __forceinline__ unsigned atom_add_release(unsigned* p, unsigned v) {
    unsigned old;
    asm volatile("atom.add.release.gpu.global.u32 %0, [%1], %2;"
                 : "=r"(old) : "l"(p), "r"(v) : "memory");
    return old;
}
__device__ __forceinline__ unsigned ld_acquire(const unsigned* p) {
    unsigned v;
    asm volatile("ld.acquire.gpu.global.u32 %0, [%1];" : "=r"(v) : "l"(p) : "memory");
    return v;
}
__device__ __forceinline__ void st_relaxed(unsigned* p, unsigned v) {
    asm volatile("st.relaxed.gpu.global.u32 [%0], %1;" :: "l"(p), "r"(v) : "memory");
}
__device__ __forceinline__ void st_release(unsigned* p, unsigned v) {
    asm volatile("st.release.gpu.global.u32 [%0], %1;" :: "l"(p), "r"(v) : "memory");
}
__device__ __forceinline__ void red_add_release(unsigned* p, unsigned v) {
    asm volatile("red.add.release.gpu.global.u32 [%0], %1;" :: "l"(p), "r"(v) : "memory");
}
__device__ __forceinline__ void group_sync(int g) {   // init-time only
    __syncthreads();
    if (threadIdx.x == 0) {
        const unsigned gen = ld_acquire(&g_gen[g]);
        if (atom_add_release(&g_cnt[g], 1u) == GSIZE - 1) {
            st_relaxed(&g_cnt[g], 0u);
            red_add_release(&g_gen[g], 1u);
        } else {
            while (ld_acquire(&g_gen[g]) == gen) { }
        }
    }
    __syncthreads();
}

// ---------------- packed f32x2 helpers ----------------------------------------
__device__ __forceinline__ void fma2(unsigned long long& d,
                                     unsigned long long a, unsigned long long b) {
    asm("fma.rn.f32x2 %0, %1, %2, %0;" : "+l"(d) : "l"(a), "l"(b));
}
__device__ __forceinline__ unsigned long long bcast2(float v) {
    unsigned long long d;
    asm("mov.b64 %0, {%1, %1};" : "=l"(d) : "r"(__float_as_uint(v)));
    return d;
}
__device__ __forceinline__ float lo2(unsigned long long v) {
    return __uint_as_float((unsigned)v);
}
__device__ __forceinline__ float hi2(unsigned long long v) {
    return __uint_as_float((unsigned)(v >> 32));
}
__device__ __forceinline__ float psum(unsigned long long v) { return lo2(v) + hi2(v); }

// ---------------- mma.sync helpers ---------------------------------------------
__device__ __forceinline__ uint32_t smem_u32(const void* p) {
    uint32_t a;
    asm("{ .reg .u64 t; cvta.to.shared.u64 t, %1; cvt.u32.u64 %0, t; }" : "=r"(a) : "l"(p));
    return a;
}
__device__ __forceinline__ void ldmx4(uint32_t& r0, uint32_t& r1, uint32_t& r2,
                                      uint32_t& r3, uint32_t addr) {
    asm volatile("ldmatrix.sync.aligned.m8n8.x4.shared.b16 {%0,%1,%2,%3}, [%4];"
                 : "=r"(r0), "=r"(r1), "=r"(r2), "=r"(r3) : "r"(addr));
}
__device__ __forceinline__ void mma16816(float* d, const uint32_t* a,
                                         const uint32_t* b) {
    asm volatile(
        "mma.sync.aligned.m16n8k16.row.col.f32.bf16.bf16.f32 "
        "{%0,%1,%2,%3}, {%4,%5,%6,%7}, {%8,%9}, {%0,%1,%2,%3};"
        : "+f"(d[0]), "+f"(d[1]), "+f"(d[2]), "+f"(d[3])
        : "r"(a[0]), "r"(a[1]), "r"(a[2]), "r"(a[3]), "r"(b[0]), "r"(b[1]));
}

// =============================================================================
// split-bf16 HMMA GEMM: C[M,N] = (Ah+Al)[M,K] @ (Bh+Bl)[N,K]^T + b1[n]+b2[n]
// 3 passes (hh, hl, lh). Tile 128x128, BK=32, 256 threads; 2 CTAs/SM.
// =============================================================================
__global__ void __launch_bounds__(256, 2) gemm_mma(
    const __nv_bfloat16* __restrict__ Ah, const __nv_bfloat16* __restrict__ Al,
    const __nv_bfloat16* __restrict__ Bh, const __nv_bfloat16* __restrict__ Bl,
    float* __restrict__ C, const float* __restrict__ b1, const float* __restrict__ b2,
    int M, int N, int K)
{
    __shared__ __nv_bfloat16 sAh[128 * APAD], sAl[128 * APAD];
    __shared__ __nv_bfloat16 sBh[128 * APAD], sBl[128 * APAD];

    const int tid  = threadIdx.x;
    const int wid  = tid >> 5, lane = tid & 31;
    const int wm   = wid >> 2;
    const int wn   = wid & 3;
    const int n0   = blockIdx.x * 128;
    const size_t m0 = (size_t)blockIdx.y * 128;

    const uint32_t bAh = smem_u32(sAh), bAl = smem_u32(sAl);
    const uint32_t bBh = smem_u32(sBh), bBl = smem_u32(sBl);

    const int lq = lane >> 3, lr = lane & 7;
    const int aRow = (lq & 1) * 8 + lr;
    const int aK   = (lq >> 1) * 8;
    const int bRow = (lq >> 1) * 8 + lr;
    const int bK   = (lq & 1) * 8;

    float acc[4][4][4];
#pragma unroll
    for (int i = 0; i < 4; i++)
#pragma unroll
        for (int j = 0; j < 4; j++)
#pragma unroll
            for (int k = 0; k < 4; k++) acc[i][j][k] = 0.f;

    const int nch = K >> 5;
    for (int ch = 0; ch < nch; ch++) {
        const int k0 = ch << 5;
#pragma unroll
        for (int j = 0; j < 2; j++) {
            const int idx = tid + j * 256;
            const int r = idx >> 2, s = idx & 3;
            const size_t ga = (m0 + r) * K + k0 + s * 8;
            const size_t gb = (size_t)(n0 + r) * K + k0 + s * 8;
            *(uint4*)(sAh + r * APAD + s * 8) = *(const uint4*)(Ah + ga);
            *(uint4*)(sAl + r * APAD + s * 8) = *(const uint4*)(Al + ga);
            *(uint4*)(sBh + r * APAD + s * 8) = *(const uint4*)(Bh + gb);
            *(uint4*)(sBl + r * APAD + s * 8) = *(const uint4*)(Bl + gb);
        }
        __syncthreads();

#pragma unroll
        for (int ks = 0; ks < 2; ks++) {
            uint32_t ah[4][4], al[4][4], bh[4][2], bl[4][2];
#pragma unroll
            for (int mt = 0; mt < 4; mt++) {
                const uint32_t off =
                    (uint32_t)((wm * 64 + mt * 16 + aRow) * APAD + ks * 16 + aK) * 2;
                ldmx4(ah[mt][0], ah[mt][1], ah[mt][2], ah[mt][3], bAh + off);
                ldmx4(al[mt][0], al[mt][1], al[mt][2], al[mt][3], bAl + off);
            }
#pragma unroll
            for (int p = 0; p < 2; p++) {
                const uint32_t off =
                    (uint32_t)((wn * 32 + p * 16 + bRow) * APAD + ks * 16 + bK) * 2;
                uint32_t r0, r1, r2, r3;
                ldmx4(r0, r1, r2, r3, bBh + off);
                bh[p * 2][0] = r0; bh[p * 2][1] = r1;
                bh[p * 2 + 1][0] = r2; bh[p * 2 + 1][1] = r3;
                ldmx4(r0, r1, r2, r3, bBl + off);
                bl[p * 2][0] = r0; bl[p * 2][1] = r1;
                bl[p * 2 + 1][0] = r2; bl[p * 2 + 1][1] = r3;
            }
#pragma unroll
            for (int mt = 0; mt < 4; mt++)
#pragma unroll
                for (int nt = 0; nt < 4; nt++) {
                    mma16816(acc[mt][nt], ah[mt], bh[nt]);
                    mma16816(acc[mt][nt], ah[mt], bl[nt]);
                    mma16816(acc[mt][nt], al[mt], bh[nt]);
                }
        }
        __syncthreads();
    }

    const int g = lane >> 2;
    const int cl = (lane & 3) * 2;
#pragma unroll
    for (int nt = 0; nt < 4; nt++) {
        const int n = n0 + wn * 32 + nt * 8 + cl;
        const float bx = b1[n] + b2[n];
        const float by = b1[n + 1] + b2[n + 1];
#pragma unroll
        for (int mt = 0; mt < 4; mt++) {
            const size_t r0 = m0 + wm * 64 + mt * 16 + g;
            float2 v0 = make_float2(acc[mt][nt][0] + bx, acc[mt][nt][1] + by);
            float2 v1 = make_float2(acc[mt][nt][2] + bx, acc[mt][nt][3] + by);
            *(float2*)(C + r0 * N + n)       = v0;
            *(float2*)(C + (r0 + 8) * N + n) = v1;
        }
    }
}

// ---------------- fp32 -> (hi, lo) bf16 splitter ------------------------------
__global__ void __launch_bounds__(256) split_kernel(
    const float* __restrict__ x, __nv_bfloat16* __restrict__ hi,
    __nv_bfloat16* __restrict__ lo, int n4)
{
    const int i = blockIdx.x * 256 + threadIdx.x;
    if (i >= n4) return;
    const float4 v = ((const float4*)x)[i];
    __nv_bfloat162 h0 = __floats2bfloat162_rn(v.x, v.y);
    __nv_bfloat162 h1 = __floats2bfloat162_rn(v.z, v.w);
    __nv_bfloat162 l0 = __floats2bfloat162_rn(v.x - __bfloat162float(h0.x),
                                              v.y - __bfloat162float(h0.y));
    __nv_bfloat162 l1 = __floats2bfloat162_rn(v.z - __bfloat162float(h1.x),
                                              v.w - __bfloat162float(h1.y));
    ((__nv_bfloat162*)hi)[i * 2]     = h0;
    ((__nv_bfloat162*)hi)[i * 2 + 1] = h1;
    ((__nv_bfloat162*)lo)[i * 2]     = l0;
    ((__nv_bfloat162*)lo)[i * 2 + 1] = l1;
}

// =============================================================================
// SIMT fp32 GEMM (f32x2 accumulators, double-buffered) for enc/mask/dec.
// =============================================================================
template <int TRANS_A, int EPI>
__global__ void __launch_bounds__(256, 2) gemm_k(
    const float* __restrict__ A, const float* __restrict__ Bm,
    float* __restrict__ C, const float* __restrict__ E,
    const float* __restrict__ bias1, const float* __restrict__ bias2,
    int M, int N, int K, size_t sA, size_t sB, size_t sC)
{
    __shared__ float As[2][8 * 128];
    __shared__ float Bs[2][8 * 128];

    const int tid = threadIdx.x;
    const size_t z = blockIdx.z;
    const float* Ab = A + z * sA;
    const float* Bb = Bm + z * sB;
    float*       Cb = C + z * sC;
    const float* Eb = (EPI == 2) ? (E + z * sC) : (const float*)0;

    const int n0 = blockIdx.x * 128;
    const int m0 = blockIdx.y * 128;
    const int tx = tid & 15;
    const int ty = tid >> 4;
    const int row  = tid >> 1;
    const int half = tid & 1;
    const int kr   = tid >> 5;
    const int mc   = tid & 31;

    unsigned long long acc2[4][8];
#pragma unroll
    for (int ip = 0; ip < 4; ip++)
#pragma unroll
        for (int j = 0; j < 8; j++) acc2[ip][j] = 0ull;

    float4 pa, pb;
    if (TRANS_A) pa = *(const float4*)(Ab + (size_t)kr * M + m0 + mc * 4);
    else         pa = *(const float4*)(Ab + (size_t)(m0 + row) * K + half * 4);
    pb = *(const float4*)(Bb + (size_t)(n0 + row) * K + half * 4);

    if (TRANS_A) {
        *(float4*)&As[0][kr * 128 + mc * 4] = pa;
    } else {
        As[0][(half * 4 + 0) * 128 + row] = pa.x;
        As[0][(half * 4 + 1) * 128 + row] = pa.y;
        As[0][(half * 4 + 2) * 128 + row] = pa.z;
        As[0][(half * 4 + 3) * 128 + row] = pa.w;
    }
    Bs[0][(half * 4 + 0) * 128 + row] = pb.x;
    Bs[0][(half * 4 + 1) * 128 + row] = pb.y;
    Bs[0][(half * 4 + 2) * 128 + row] = pb.z;
    Bs[0][(half * 4 + 3) * 128 + row] = pb.w;
    __syncthreads();

    int buf = 0;
    for (int k0 = 0; k0 < K; k0 += 8) {
        const bool more = (k0 + 8 < K);
        if (more) {
            if (TRANS_A) pa = *(const float4*)(Ab + (size_t)(k0 + 8 + kr) * M + m0 + mc * 4);
            else         pa = *(const float4*)(Ab + (size_t)(m0 + row) * K + k0 + 8 + half * 4);
            pb = *(const float4*)(Bb + (size_t)(n0 + row) * K + k0 + 8 + half * 4);
        }
#pragma unroll
        for (int kk = 0; kk < 8; kk++) {
            ulonglong2 aA = *(const ulonglong2*)&As[buf][kk * 128 + ty * 8];
            ulonglong2 aB = *(const ulonglong2*)&As[buf][kk * 128 + ty * 8 + 4];
            float bv[8];
            *(float4*)(bv)     = *(const float4*)&Bs[buf][kk * 128 + tx * 8];
            *(float4*)(bv + 4) = *(const float4*)&Bs[buf][kk * 128 + tx * 8 + 4];
#pragma unroll
            for (int j = 0; j < 8; j++) {
                const unsigned long long bj = bcast2(bv[j]);
                fma2(acc2[0][j], aA.x, bj);
                fma2(acc2[1][j], aA.y, bj);
                fma2(acc2[2][j], aB.x, bj);
                fma2(acc2[3][j], aB.y, bj);
            }
        }
        if (more) {
            const int nb = buf ^ 1;
            if (TRANS_A) {
                *(float4*)&As[nb][kr * 128 + mc * 4] = pa;
            } else {
                As[nb][(half * 4 + 0) * 128 + row] = pa.x;
                As[nb][(half * 4 + 1) * 128 + row] = pa.y;
                As[nb][(half * 4 + 2) * 128 + row] = pa.z;
                As[nb][(half * 4 + 3) * 128 + row] = pa.w;
            }
            Bs[nb][(half * 4 + 0) * 128 + row] = pb.x;
            Bs[nb][(half * 4 + 1) * 128 + row] = pb.y;
            Bs[nb][(half * 4 + 2) * 128 + row] = pb.z;
            Bs[nb][(half * 4 + 3) * 128 + row] = pb.w;
            __syncthreads();
            buf = nb;
        }
    }

#pragma unroll
    for (int ip = 0; ip < 4; ip++) {
#pragma unroll
        for (int hf = 0; hf < 2; hf++) {
            const int i = ip * 2 + hf;
            const int m = m0 + ty * 8 + i;
            float* crow = Cb + (size_t)m * N;
#pragma unroll
            for (int j = 0; j < 8; j += 4) {
                const int n = n0 + tx * 8 + j;
                float4 v;
                v.x = hf ? hi2(acc2[ip][j])     : lo2(acc2[ip][j]);
                v.y = hf ? hi2(acc2[ip][j + 1]) : lo2(acc2[ip][j + 1]);
                v.z = hf ? hi2(acc2[ip][j + 2]) : lo2(acc2[ip][j + 2]);
                v.w = hf ? hi2(acc2[ip][j + 3]) : lo2(acc2[ip][j + 3]);
                if (EPI == 1) {
                    v.x += bias1[n]     + bias2[n];
                    v.y += bias1[n + 1] + bias2[n + 1];
                    v.z += bias1[n + 2] + bias2[n + 2];
                    v.w += bias1[n + 3] + bias2[n + 3];
                } else if (EPI == 2) {
                    float4 e = *(const float4*)(Eb + (size_t)m * N + n);
                    v.x = e.x / (1.f + expf(-(v.x + bias1[n])));
                    v.y = e.y / (1.f + expf(-(v.y + bias1[n + 1])));
                    v.z = e.z / (1.f + expf(-(v.z + bias1[n + 2])));
                    v.w = e.w / (1.f + expf(-(v.w + bias1[n + 3])));
                }
                *(float4*)(crow + n) = v;
            }
        }
    }
}

// ---------------- layernorm -> bf16 hi/lo -------------------------------------
__global__ void __launch_bounds__(256) ln_kernel(
    const float* __restrict__ in, __nv_bfloat16* __restrict__ hi,
    __nv_bfloat16* __restrict__ lo,
    const float* __restrict__ gam, const float* __restrict__ bet)
{
    const int row  = blockIdx.x * 8 + (threadIdx.x >> 5);
    const int lane = threadIdx.x & 31;
    const float* r = in + (size_t)row * ENCn + lane * 8;
    float4 a  = *(const float4*)r;
    float4 b4 = *(const float4*)(r + 4);
    float s  = a.x + a.y + a.z + a.w + b4.x + b4.y + b4.z + b4.w;
    float sq = a.x*a.x + a.y*a.y + a.z*a.z + a.w*a.w
             + b4.x*b4.x + b4.y*b4.y + b4.z*b4.z + b4.w*b4.w;
#pragma unroll
    for (int o = 16; o; o >>= 1) {
        s  += __shfl_xor_sync(0xFFFFFFFFu, s,  o);
        sq += __shfl_xor_sync(0xFFFFFFFFu, sq, o);
    }
    const float mu   = s * (1.f / 256.f);
    const float var  = sq * (1.f / 256.f) - mu * mu;
    const float rstd = rsqrtf(var + 1e-5f);

    const float* gg = gam + lane * 8;
    const float* bb = bet + lane * 8;
    float4 ga = *(const float4*)gg,  gb  = *(const float4*)(gg + 4);
    float4 ba = *(const float4*)bb,  bbv = *(const float4*)(bb + 4);
    float o8[8];
    o8[0] = (a.x  - mu) * rstd * ga.x + ba.x;
    o8[1] = (a.y  - mu) * rstd * ga.y + ba.y;
    o8[2] = (a.z  - mu) * rstd * ga.z + ba.z;
    o8[3] = (a.w  - mu) * rstd * ga.w + ba.w;
    o8[4] = (b4.x - mu) * rstd * gb.x + bbv.x;
    o8[5] = (b4.y - mu) * rstd * gb.y + bbv.y;
    o8[6] = (b4.z - mu) * rstd * gb.z + bbv.z;
    o8[7] = (b4.w - mu) * rstd * gb.w + bbv.w;

    const size_t base = (size_t)row * ENCn + lane * 8;
#pragma unroll
    for (int k = 0; k < 8; k += 2) {
        __nv_bfloat162 h = __floats2bfloat162_rn(o8[k], o8[k + 1]);
        __nv_bfloat162 l = __floats2bfloat162_rn(o8[k]     - __bfloat162float(h.x),
                                                 o8[k + 1] - __bfloat162float(h.y));
        *(__nv_bfloat162*)(hi + base + k) = h;
        *(__nv_bfloat162*)(lo + base + k) = l;
    }
}

// =============================================================================
// persistent LSTM v7: R9 structure (512 threads, 8-way k) with distributed
// per-CTA flag barrier (release-store to own 128B line; warp-0 polls 32 lines).
// =============================================================================
__global__ void __launch_bounds__(512) lstm_kernel(
    const float* __restrict__ pre, const float* __restrict__ Whh,
    const float* __restrict__ h0,  const float* __restrict__ c0,
    float* __restrict__ xout, __nv_bfloat16* __restrict__ bfh,
    __nv_bfloat16* __restrict__ bfl,
    float* __restrict__ hout, float* __restrict__ cout)
{
    extern __shared__ float sm[];
    float* sW = sm;
    float* sH = sm + 64 * WROW;
    float* sR = sm + 80 * WROW;

    const int tid  = threadIdx.x, cta = blockIdx.x;
    const int ub   = cta & 31, bb = cta >> 5;
    const int warp = tid >> 5, lane = tid & 31;
    const int ks    = warp & 7;
    const int bq_hi = warp >> 3;
    const int ul    = lane & 15;
    const int bq_lo = lane >> 4;
    const int bq    = bq_hi * 2 + bq_lo;
    const int slot  = bq * 16 + ul;
    const int e_u   = tid & 15;
    const int e_b   = (tid >> 4) & 15;
    const int eslot = (e_b >> 2) * 16 + e_u;
    const int ej    = e_b & 3;
    const int gb    = bb * 16 + e_b;
    const int gu    = ub * 16 + e_u;
    const bool epi  = (tid < 256);

    for (int i = tid; i < 64 * 128; i += 512) {
        const int r  = i >> 7;
        const int k4 = i & 127;
        const int g  = r >> 4;
        const int uu = ub * 16 + (r & 15);
        *(float4*)(sW + r * WROW + k4 * 4) =
            *(const float4*)(Whh + ((size_t)(g * HIDn + uu)) * HIDn + k4 * 4);
    }
    if (epi) g_h[0][cta * 256 + tid] = h0[cta * 256 + tid];
    float c = 0.f, hlast = 0.f;
    if (epi) c = c0[gb * HIDn + gu];
    group_sync(bb);
    // read monotonic flag bases (warp 0 lanes: one group member each)
    unsigned base_lane = 0, base_self = 0;
    if (tid < 32) {
        base_lane = ld_acquire(&g_flag[(bb * 32 + tid) * 32]);
        base_self = __shfl_sync(0xFFFFFFFFu, base_lane, ub);
    }
    group_sync(bb);   // nobody publishes before all bases are read

    const float* w0r = sW + (0 * 16 + ul) * WROW + ks * 64;
    const float* w1r = sW + (1 * 16 + ul) * WROW + ks * 64;
    const float* w2r = sW + (2 * 16 + ul) * WROW + ks * 64;
    const float* w3r = sW + (3 * 16 + ul) * WROW + ks * 64;
    const float* hb0 = sH + (bq * 4 + 0) * WROW + ks * 64;
    const float* hb1 = sH + (bq * 4 + 1) * WROW + ks * 64;
    const float* hb2 = sH + (bq * 4 + 2) * WROW + ks * 64;
    const float* hb3 = sH + (bq * 4 + 3) * WROW + ks * 64;

    for (int t = 0; t < Tn; t++) {
        // wait: all 32 group CTAs have published h(t) (flag >= base + t)
        if (t > 0 && tid < 32) {
            const unsigned tgt = base_lane + (unsigned)t;
            unsigned f = ld_acquire(&g_flag[(bb * 32 + tid) * 32]);
            bool done = ((int)(f - tgt) >= 0);
            while (!__all_sync(0xFFFFFFFFu, done)) {
                if (!done) {
                    f = ld_acquire(&g_flag[(bb * 32 + tid) * 32]);
                    done = ((int)(f - tgt) >= 0);
                }
            }
        }
        __syncthreads();

        const float* hr = g_h[t & 1] + (size_t)bb * 16 * HIDn;
        for (int i = tid; i < 16 * 128; i += 512) {
            const int rr = i >> 7, k4 = i & 127;
            *(float4*)(sH + rr * WROW + k4 * 4) =
                *(const float4*)(hr + (size_t)rr * HIDn + k4 * 4);
        }
        float p0 = 0.f, p1 = 0.f, p2 = 0.f, p3 = 0.f;
        if (epi) {
            const float* pb = pre + ((size_t)gb * Tn + t) * G4n + gu;
            p0 = pb[0]; p1 = pb[512]; p2 = pb[1024]; p3 = pb[1536];
        }
        __syncthreads();

        unsigned long long acc[16];
#pragma unroll
        for (int i = 0; i < 16; i++) acc[i] = 0ull;

#pragma unroll 8
        for (int q = 0; q < 16; q++) {
            const int k = q * 4;
            const ulonglong2 ha  = *(const ulonglong2*)(hb0 + k);
            const ulonglong2 hbv = *(const ulonglong2*)(hb1 + k);
            const ulonglong2 hc  = *(const ulonglong2*)(hb2 + k);
            const ulonglong2 hd  = *(const ulonglong2*)(hb3 + k);
            ulonglong2 w;
            w = *(const ulonglong2*)(w0r + k);
            fma2(acc[0], w.x, ha.x);  fma2(acc[0], w.y, ha.y);
            fma2(acc[1], w.x, hbv.x); fma2(acc[1], w.y, hbv.y);
            fma2(acc[2], w.x, hc.x);  fma2(acc[2], w.y, hc.y);
            fma2(acc[3], w.x, hd.x);  fma2(acc[3], w.y, hd.y);
            w = *(const ulonglong2*)(w1r + k);
            fma2(acc[4], w.x, ha.x);  fma2(acc[4], w.y, ha.y);
            fma2(acc[5], w.x, hbv.x); fma2(acc[5], w.y, hbv.y);
            fma2(acc[6], w.x, hc.x);  fma2(acc[6], w.y, hc.y);
            fma2(acc[7], w.x, hd.x);  fma2(acc[7], w.y, hd.y);
            w = *(const ulonglong2*)(w2r + k);
            fma2(acc[8], w.x, ha.x);  fma2(acc[8], w.y, ha.y);
            fma2(acc[9], w.x, hbv.x); fma2(acc[9], w.y, hbv.y);
            fma2(acc[10], w.x, hc.x); fma2(acc[10], w.y, hc.y);
            fma2(acc[11], w.x, hd.x); fma2(acc[11], w.y, hd.y);
            w = *(const ulonglong2*)(w3r + k);
            fma2(acc[12], w.x, ha.x); fma2(acc[12], w.y, ha.y);
            fma2(acc[13], w.x, hbv.x);fma2(acc[13], w.y, hbv.y);
            fma2(acc[14], w.x, hc.x); fma2(acc[14], w.y, hc.y);
            fma2(acc[15], w.x, hd.x); fma2(acc[15], w.y, hd.y);
        }

        float* rp = sR + (ks * 64 + slot) * RSTR;
        *(float4*)(rp + 0)  = make_float4(psum(acc[0]), psum(acc[4]), psum(acc[8]),  psum(acc[12]));
        *(float4*)(rp + 4)  = make_float4(psum(acc[1]), psum(acc[5]), psum(acc[9]),  psum(acc[13]));
        *(float4*)(rp + 8)  = make_float4(psum(acc[2]), psum(acc[6]), psum(acc[10]), psum(acc[14]));
        *(float4*)(rp + 12) = make_float4(psum(acc[3]), psum(acc[7]), psum(acc[11]), psum(acc[15]));
        __syncthreads();

        if (epi) {
            float4 s = *(const float4*)(sR + (0 * 64 + eslot) * RSTR + ej * 4);
            float gi = s.x, gf = s.y, gc = s.z, go = s.w;
#pragma unroll
            for (int kk = 1; kk < 8; kk++) {
                const float4 sk = *(const float4*)(sR + (kk * 64 + eslot) * RSTR + ej * 4);
                gi += sk.x; gf += sk.y; gc += sk.z; go += sk.w;
            }
            gi += p0; gf += p1; gc += p2; go += p3;
            const float si = __fdividef(1.f, 1.f + __expf(-gi));
            const float sf = __fdividef(1.f, 1.f + __expf(-gf));
            const float so = __fdividef(1.f, 1.f + __expf(-go));
            const float tg = 2.f * __fdividef(1.f, 1.f + __expf(-2.f * gc)) - 1.f;
            c = sf * c + si * tg;
            const float tc = 2.f * __fdividef(1.f, 1.f + __expf(-2.f * c)) - 1.f;
            const float hn = so * tc;
            hlast = hn;
            const size_t xo = ((size_t)gb * Tn + t) * HIDn + gu;
            if (bfh) {
                __nv_bfloat16 hh = __float2bfloat16(hn);
                bfh[xo] = hh;
                bfl[xo] = __float2bfloat16(hn - __bfloat162float(hh));
            } else {
                xout[xo] = hn;
            }
            g_h[(t + 1) & 1][gb * HIDn + gu] = hn;
        }
        __syncthreads();
        if (tid == 0) st_release(&g_flag[cta * 32], base_self + (unsigned)(t + 1));
    }

    if (epi) {
        hout[gb * HIDn + gu] = hlast;
        cout[gb * HIDn + gu] = c;
    }
}

// =============================================================================
extern "C" void kernel_launch(void* const* d_in, const int* in_sizes, int n_in,
                              void* d_out, int out_size)
{
    const float* x      = (const float*)d_in[0];
    const float* states = (const float*)d_in[1];
    const float* W_enc  = (const float*)d_in[2];
    const float* ln_g   = (const float*)d_in[3];
    const float* ln_b   = (const float*)d_in[4];
    const float* Wih1   = (const float*)d_in[5];
    const float* Whh1   = (const float*)d_in[6];
    const float* bih1   = (const float*)d_in[7];
    const float* bhh1   = (const float*)d_in[8];
    const float* Wih2   = (const float*)d_in[9];
    const float* Whh2   = (const float*)d_in[10];
    const float* bih2   = (const float*)d_in[11];
    const float* bhh2   = (const float*)d_in[12];
    const float* Wlin   = (const float*)d_in[13];
    const float* blin   = (const float*)d_in[14];
    const float* W_dec  = (const float*)d_in[15];

    float* out     = (float*)d_out;
    float* dstates = out + (size_t)Bn * FRAMEn * Tn;

    float *encoded, *buf, *pre, *x1;
    __nv_bfloat16 *ah, *al, *wh, *wl;
    cudaGetSymbolAddress((void**)&encoded, g_encoded);
    cudaGetSymbolAddress((void**)&buf,     g_buf);
    cudaGetSymbolAddress((void**)&pre,     g_pre);
    cudaGetSymbolAddress((void**)&x1,      g_x1);
    cudaGetSymbolAddress((void**)&ah,      g_ah);
    cudaGetSymbolAddress((void**)&al,      g_al);
    cudaGetSymbolAddress((void**)&wh,      g_wh);
    cudaGetSymbolAddress((void**)&wl,      g_wl);

    static int attr_set = 0;
    const int LSTM_SMEM = (80 * WROW + 8 * 64 * RSTR) * 4;   // 206,080 B
    if (!attr_set) {
        cudaFuncSetAttribute(lstm_kernel,
                             cudaFuncAttributeMaxDynamicSharedMemorySize, LSTM_SMEM);
        attr_set = 1;
    }

    const int BH = Bn * HIDn;

    // 1) encoder (fp32 SIMT)
    gemm_k<1, 0><<<dim3(ENCn / 128, Tn / 128, Bn), 256>>>(
        x, W_enc, encoded, 0, 0, 0,
        Tn, ENCn, FRAMEn, (size_t)FRAMEn * Tn, 0, (size_t)Tn * ENCn);

    // 2) layernorm -> bf16 hi/lo
    ln_kernel<<<(Bn * Tn) / 8, 256>>>(encoded, ah, al, ln_g, ln_b);

    // 3) pre1 (HMMA split-bf16)
    split_kernel<<<(G4n * ENCn / 4 + 255) / 256, 256>>>(Wih1, wh, wl, G4n * ENCn / 4);
    gemm_mma<<<dim3(G4n / 128, (Bn * Tn) / 128), 256>>>(
        ah, al, wh, wl, pre, bih1, bhh1, Bn * Tn, G4n, ENCn);

    // 4) LSTM layer 1 (emits x1 as bf16 hi/lo)
    lstm_kernel<<<NBLK, 512, LSTM_SMEM>>>(
        pre, Whh1, states + 0 * BH, states + 1 * BH,
        x1, ah, al, dstates + 0 * BH, dstates + 1 * BH);

    // 5) pre2 (HMMA split-bf16)
    split_kernel<<<(G4n * HIDn / 4 + 255) / 256, 256>>>(Wih2, wh, wl, G4n * HIDn / 4);
    gemm_mma<<<dim3(G4n / 128, (Bn * Tn) / 128), 256>>>(
        ah, al, wh, wl, pre, bih2, bhh2, Bn * Tn, G4n, HIDn);

    // 6) LSTM layer 2 (fp32 x2 -> g_x1)
    lstm_kernel<<<NBLK, 512, LSTM_SMEM>>>(
        pre, Whh2, states + 2 * BH, states + 3 * BH,
        x1, (__nv_bfloat16*)0, (__nv_bfloat16*)0,
        dstates + 2 * BH, dstates + 3 * BH);

    // 7) est = sigmoid(x2 @ Wlin^T + blin) * encoded
    gemm_k<0, 2><<<dim3(ENCn / 128, (Bn * Tn) / 128, 1), 256>>>(
        x1, Wlin, buf, encoded, blin, 0,
        Bn * Tn, ENCn, HIDn, 0, 0, 0);

    // 8) decoder
    gemm_k<0, 0><<<dim3(Tn / 128, FRAMEn / 128, Bn), 256>>>(
        W_dec, buf, out, 0, 0, 0,
        FRAMEn, Tn, ENCn, 0, (size_t)Tn * ENCn, (size_t)FRAMEn * Tn);
}

// round 13
// speedup vs baseline: 2.1348x; 1.0060x over previous
#include <cuda_runtime.h>
#include <cuda_bf16.h>
#include <cstdint>
#include <math.h>

#define Bn     64
#define Tn     1024
#define FRAMEn 512
#define ENCn   256
#define HIDn   512
#define G4n    2048
#define NBLK   128
#define GSIZE  32
#define WROW   516
#define RSTR   20
#define APAD   40      // smem row stride (bf16) for mma tiles

// ---------------- static device scratch (no cudaMalloc allowed) --------------
__device__ float g_encoded[(size_t)Bn * Tn * ENCn];
__device__ float g_buf[(size_t)Bn * Tn * ENCn];
__device__ float g_pre[(size_t)Bn * Tn * G4n];
__device__ float g_x1[(size_t)Bn * Tn * HIDn];
__device__ float g_h[2][Bn * HIDn];
__device__ unsigned g_cnt[4];          // init barriers (self-resetting)
__device__ unsigned g_gen[4];
__device__ unsigned g_flag[NBLK * 32]; // per-CTA monotonic flags, 128B apart
__device__ __nv_bfloat16 g_ah[(size_t)Bn * Tn * HIDn];
__device__ __nv_bfloat16 g_al[(size_t)Bn * Tn * HIDn];
__device__ __nv_bfloat16 g_wh[(size_t)G4n * HIDn];
__device__ __nv_bfloat16 g_wl[(size_t)G4n * HIDn];

// ---------------- acquire/release primitives ---------------------------------
__device__ __forceinline__ unsigned atom_add_release(unsigned* p, unsigned v) {
    unsigned old;
    asm volatile("atom.add.release.gpu.global.u32 %0, [%1], %2;"
                 : "=r"(old) : "l"(p), "r"(v) : "memory");
    return old;
}
__device__ __forceinline__ unsigned ld_acquire(const unsigned* p) {
    unsigned v;
    asm volatile("ld.acquire.gpu.global.u32 %0, [%1];" : "=r"(v) : "l"(p) : "memory");
    return v;
}
__device__ __forceinline__ void st_relaxed(unsigned* p, unsigned v) {
    asm volatile("st.relaxed.gpu.global.u32 [%0], %1;" :: "l"(p), "r"(v) : "memory");
}
__device__ __forceinline__ void st_release(unsigned* p, unsigned v) {
    asm volatile("st.release.gpu.global.u32 [%0], %1;" :: "l"(p), "r"(v) : "memory");
}
__device__ __forceinline__ void red_add_release(unsigned* p, unsigned v) {
    asm volatile("red.add.release.gpu.global.u32 [%0], %1;" :: "l"(p), "r"(v) : "memory");
}
__device__ __forceinline__ void group_sync(int g) {   // init-time only
    __syncthreads();
    if (threadIdx.x == 0) {
        const unsigned gen = ld_acquire(&g_gen[g]);
        if (atom_add_release(&g_cnt[g], 1u) == GSIZE - 1) {
            st_relaxed(&g_cnt[g], 0u);
            red_add_release(&g_gen[g], 1u);
        } else {
            while (ld_acquire(&g_gen[g]) == gen) { }
        }
    }
    __syncthreads();
}

// ---------------- packed f32x2 helpers ----------------------------------------
__device__ __forceinline__ void fma2(unsigned long long& d,
                                     unsigned long long a, unsigned long long b) {
    asm("fma.rn.f32x2 %0, %1, %2, %0;" : "+l"(d) : "l"(a), "l"(b));
}
__device__ __forceinline__ unsigned long long bcast2(float v) {
    unsigned long long d;
    asm("mov.b64 %0, {%1, %1};" : "=l"(d) : "r"(__float_as_uint(v)));
    return d;
}
__device__ __forceinline__ float lo2(unsigned long long v) {
    return __uint_as_float((unsigned)v);
}
__device__ __forceinline__ float hi2(unsigned long long v) {
    return __uint_as_float((unsigned)(v >> 32));
}
__device__ __forceinline__ float psum(unsigned long long v) { return lo2(v) + hi2(v); }

// ---------------- mma.sync helpers ---------------------------------------------
__device__ __forceinline__ uint32_t smem_u32(const void* p) {
    uint32_t a;
    asm("{ .reg .u64 t; cvta.to.shared.u64 t, %1; cvt.u32.u64 %0, t; }" : "=r"(a) : "l"(p));
    return a;
}
__device__ __forceinline__ void ldmx4(uint32_t& r0, uint32_t& r1, uint32_t& r2,
                                      uint32_t& r3, uint32_t addr) {
    asm volatile("ldmatrix.sync.aligned.m8n8.x4.shared.b16 {%0,%1,%2,%3}, [%4];"
                 : "=r"(r0), "=r"(r1), "=r"(r2), "=r"(r3) : "r"(addr));
}
__device__ __forceinline__ void mma16816(float* d, const uint32_t* a,
                                         const uint32_t* b) {
    asm volatile(
        "mma.sync.aligned.m16n8k16.row.col.f32.bf16.bf16.f32 "
        "{%0,%1,%2,%3}, {%4,%5,%6,%7}, {%8,%9}, {%0,%1,%2,%3};"
        : "+f"(d[0]), "+f"(d[1]), "+f"(d[2]), "+f"(d[3])
        : "r"(a[0]), "r"(a[1]), "r"(a[2]), "r"(a[3]), "r"(b[0]), "r"(b[1]));
}

// =============================================================================
// split-bf16 HMMA GEMM: C[M,N] = (Ah+Al)[M,K] @ (Bh+Bl)[N,K]^T + b1[n]+b2[n]
// 3 passes (hh, hl, lh). Tile 128x128, BK=32, 256 threads; 2 CTAs/SM.
// =============================================================================
__global__ void __launch_bounds__(256, 2) gemm_mma(
    const __nv_bfloat16* __restrict__ Ah, const __nv_bfloat16* __restrict__ Al,
    const __nv_bfloat16* __restrict__ Bh, const __nv_bfloat16* __restrict__ Bl,
    float* __restrict__ C, const float* __restrict__ b1, const float* __restrict__ b2,
    int M, int N, int K)
{
    __shared__ __nv_bfloat16 sAh[128 * APAD], sAl[128 * APAD];
    __shared__ __nv_bfloat16 sBh[128 * APAD], sBl[128 * APAD];

    const int tid  = threadIdx.x;
    const int wid  = tid >> 5, lane = tid & 31;
    const int wm   = wid >> 2;
    const int wn   = wid & 3;
    const int n0   = blockIdx.x * 128;
    const size_t m0 = (size_t)blockIdx.y * 128;

    const uint32_t bAh = smem_u32(sAh), bAl = smem_u32(sAl);
    const uint32_t bBh = smem_u32(sBh), bBl = smem_u32(sBl);

    const int lq = lane >> 3, lr = lane & 7;
    const int aRow = (lq & 1) * 8 + lr;
    const int aK   = (lq >> 1) * 8;
    const int bRow = (lq >> 1) * 8 + lr;
    const int bK   = (lq & 1) * 8;

    float acc[4][4][4];
#pragma unroll
    for (int i = 0; i < 4; i++)
#pragma unroll
        for (int j = 0; j < 4; j++)
#pragma unroll
            for (int k = 0; k < 4; k++) acc[i][j][k] = 0.f;

    const int nch = K >> 5;
    for (int ch = 0; ch < nch; ch++) {
        const int k0 = ch << 5;
#pragma unroll
        for (int j = 0; j < 2; j++) {
            const int idx = tid + j * 256;
            const int r = idx >> 2, s = idx & 3;
            const size_t ga = (m0 + r) * K + k0 + s * 8;
            const size_t gb = (size_t)(n0 + r) * K + k0 + s * 8;
            *(uint4*)(sAh + r * APAD + s * 8) = *(const uint4*)(Ah + ga);
            *(uint4*)(sAl + r * APAD + s * 8) = *(const uint4*)(Al + ga);
            *(uint4*)(sBh + r * APAD + s * 8) = *(const uint4*)(Bh + gb);
            *(uint4*)(sBl + r * APAD + s * 8) = *(const uint4*)(Bl + gb);
        }
        __syncthreads();

#pragma unroll
        for (int ks = 0; ks < 2; ks++) {
            uint32_t ah[4][4], al[4][4], bh[4][2], bl[4][2];
#pragma unroll
            for (int mt = 0; mt < 4; mt++) {
                const uint32_t off =
                    (uint32_t)((wm * 64 + mt * 16 + aRow) * APAD + ks * 16 + aK) * 2;
                ldmx4(ah[mt][0], ah[mt][1], ah[mt][2], ah[mt][3], bAh + off);
                ldmx4(al[mt][0], al[mt][1], al[mt][2], al[mt][3], bAl + off);
            }
#pragma unroll
            for (int p = 0; p < 2; p++) {
                const uint32_t off =
                    (uint32_t)((wn * 32 + p * 16 + bRow) * APAD + ks * 16 + bK) * 2;
                uint32_t r0, r1, r2, r3;
                ldmx4(r0, r1, r2, r3, bBh + off);
                bh[p * 2][0] = r0; bh[p * 2][1] = r1;
                bh[p * 2 + 1][0] = r2; bh[p * 2 + 1][1] = r3;
                ldmx4(r0, r1, r2, r3, bBl + off);
                bl[p * 2][0] = r0; bl[p * 2][1] = r1;
                bl[p * 2 + 1][0] = r2; bl[p * 2 + 1][1] = r3;
            }
#pragma unroll
            for (int mt = 0; mt < 4; mt++)
#pragma unroll
                for (int nt = 0; nt < 4; nt++) {
                    mma16816(acc[mt][nt], ah[mt], bh[nt]);
                    mma16816(acc[mt][nt], ah[mt], bl[nt]);
                    mma16816(acc[mt][nt], al[mt], bh[nt]);
                }
        }
        __syncthreads();
    }

    const int g = lane >> 2;
    const int cl = (lane & 3) * 2;
#pragma unroll
    for (int nt = 0; nt < 4; nt++) {
        const int n = n0 + wn * 32 + nt * 8 + cl;
        const float bx = b1[n] + b2[n];
        const float by = b1[n + 1] + b2[n + 1];
#pragma unroll
        for (int mt = 0; mt < 4; mt++) {
            const size_t r0 = m0 + wm * 64 + mt * 16 + g;
            float2 v0 = make_float2(acc[mt][nt][0] + bx, acc[mt][nt][1] + by);
            float2 v1 = make_float2(acc[mt][nt][2] + bx, acc[mt][nt][3] + by);
            *(float2*)(C + r0 * N + n)       = v0;
            *(float2*)(C + (r0 + 8) * N + n) = v1;
        }
    }
}

// ---------------- fp32 -> (hi, lo) bf16 splitter ------------------------------
__global__ void __launch_bounds__(256) split_kernel(
    const float* __restrict__ x, __nv_bfloat16* __restrict__ hi,
    __nv_bfloat16* __restrict__ lo, int n4)
{
    const int i = blockIdx.x * 256 + threadIdx.x;
    if (i >= n4) return;
    const float4 v = ((const float4*)x)[i];
    __nv_bfloat162 h0 = __floats2bfloat162_rn(v.x, v.y);
    __nv_bfloat162 h1 = __floats2bfloat162_rn(v.z, v.w);
    __nv_bfloat162 l0 = __floats2bfloat162_rn(v.x - __bfloat162float(h0.x),
                                              v.y - __bfloat162float(h0.y));
    __nv_bfloat162 l1 = __floats2bfloat162_rn(v.z - __bfloat162float(h1.x),
                                              v.w - __bfloat162float(h1.y));
    ((__nv_bfloat162*)hi)[i * 2]     = h0;
    ((__nv_bfloat162*)hi)[i * 2 + 1] = h1;
    ((__nv_bfloat162*)lo)[i * 2]     = l0;
    ((__nv_bfloat162*)lo)[i * 2 + 1] = l1;
}

// =============================================================================
// SIMT fp32 GEMM (f32x2 accumulators, double-buffered) for enc/mask/dec.
// =============================================================================
template <int TRANS_A, int EPI>
__global__ void __launch_bounds__(256, 2) gemm_k(
    const float* __restrict__ A, const float* __restrict__ Bm,
    float* __restrict__ C, const float* __restrict__ E,
    const float* __restrict__ bias1, const float* __restrict__ bias2,
    int M, int N, int K, size_t sA, size_t sB, size_t sC)
{
    __shared__ float As[2][8 * 128];
    __shared__ float Bs[2][8 * 128];

    const int tid = threadIdx.x;
    const size_t z = blockIdx.z;
    const float* Ab = A + z * sA;
    const float* Bb = Bm + z * sB;
    float*       Cb = C + z * sC;
    const float* Eb = (EPI == 2) ? (E + z * sC) : (const float*)0;

    const int n0 = blockIdx.x * 128;
    const int m0 = blockIdx.y * 128;
    const int tx = tid & 15;
    const int ty = tid >> 4;
    const int row  = tid >> 1;
    const int half = tid & 1;
    const int kr   = tid >> 5;
    const int mc   = tid & 31;

    unsigned long long acc2[4][8];
#pragma unroll
    for (int ip = 0; ip < 4; ip++)
#pragma unroll
        for (int j = 0; j < 8; j++) acc2[ip][j] = 0ull;

    float4 pa, pb;
    if (TRANS_A) pa = *(const float4*)(Ab + (size_t)kr * M + m0 + mc * 4);
    else         pa = *(const float4*)(Ab + (size_t)(m0 + row) * K + half * 4);
    pb = *(const float4*)(Bb + (size_t)(n0 + row) * K + half * 4);

    if (TRANS_A) {
        *(float4*)&As[0][kr * 128 + mc * 4] = pa;
    } else {
        As[0][(half * 4 + 0) * 128 + row] = pa.x;
        As[0][(half * 4 + 1) * 128 + row] = pa.y;
        As[0][(half * 4 + 2) * 128 + row] = pa.z;
        As[0][(half * 4 + 3) * 128 + row] = pa.w;
    }
    Bs[0][(half * 4 + 0) * 128 + row] = pb.x;
    Bs[0][(half * 4 + 1) * 128 + row] = pb.y;
    Bs[0][(half * 4 + 2) * 128 + row] = pb.z;
    Bs[0][(half * 4 + 3) * 128 + row] = pb.w;
    __syncthreads();

    int buf = 0;
    for (int k0 = 0; k0 < K; k0 += 8) {
        const bool more = (k0 + 8 < K);
        if (more) {
            if (TRANS_A) pa = *(const float4*)(Ab + (size_t)(k0 + 8 + kr) * M + m0 + mc * 4);
            else         pa = *(const float4*)(Ab + (size_t)(m0 + row) * K + k0 + 8 + half * 4);
            pb = *(const float4*)(Bb + (size_t)(n0 + row) * K + k0 + 8 + half * 4);
        }
#pragma unroll
        for (int kk = 0; kk < 8; kk++) {
            ulonglong2 aA = *(const ulonglong2*)&As[buf][kk * 128 + ty * 8];
            ulonglong2 aB = *(const ulonglong2*)&As[buf][kk * 128 + ty * 8 + 4];
            float bv[8];
            *(float4*)(bv)     = *(const float4*)&Bs[buf][kk * 128 + tx * 8];
            *(float4*)(bv + 4) = *(const float4*)&Bs[buf][kk * 128 + tx * 8 + 4];
#pragma unroll
            for (int j = 0; j < 8; j++) {
                const unsigned long long bj = bcast2(bv[j]);
                fma2(acc2[0][j], aA.x, bj);
                fma2(acc2[1][j], aA.y, bj);
                fma2(acc2[2][j], aB.x, bj);
                fma2(acc2[3][j], aB.y, bj);
            }
        }
        if (more) {
            const int nb = buf ^ 1;
            if (TRANS_A) {
                *(float4*)&As[nb][kr * 128 + mc * 4] = pa;
            } else {
                As[nb][(half * 4 + 0) * 128 + row] = pa.x;
                As[nb][(half * 4 + 1) * 128 + row] = pa.y;
                As[nb][(half * 4 + 2) * 128 + row] = pa.z;
                As[nb][(half * 4 + 3) * 128 + row] = pa.w;
            }
            Bs[nb][(half * 4 + 0) * 128 + row] = pb.x;
            Bs[nb][(half * 4 + 1) * 128 + row] = pb.y;
            Bs[nb][(half * 4 + 2) * 128 + row] = pb.z;
            Bs[nb][(half * 4 + 3) * 128 + row] = pb.w;
            __syncthreads();
            buf = nb;
        }
    }

#pragma unroll
    for (int ip = 0; ip < 4; ip++) {
#pragma unroll
        for (int hf = 0; hf < 2; hf++) {
            const int i = ip * 2 + hf;
            const int m = m0 + ty * 8 + i;
            float* crow = Cb + (size_t)m * N;
#pragma unroll
            for (int j = 0; j < 8; j += 4) {
                const int n = n0 + tx * 8 + j;
                float4 v;
                v.x = hf ? hi2(acc2[ip][j])     : lo2(acc2[ip][j]);
                v.y = hf ? hi2(acc2[ip][j + 1]) : lo2(acc2[ip][j + 1]);
                v.z = hf ? hi2(acc2[ip][j + 2]) : lo2(acc2[ip][j + 2]);
                v.w = hf ? hi2(acc2[ip][j + 3]) : lo2(acc2[ip][j + 3]);
                if (EPI == 1) {
                    v.x += bias1[n]     + bias2[n];
                    v.y += bias1[n + 1] + bias2[n + 1];
                    v.z += bias1[n + 2] + bias2[n + 2];
                    v.w += bias1[n + 3] + bias2[n + 3];
                } else if (EPI == 2) {
                    float4 e = *(const float4*)(Eb + (size_t)m * N + n);
                    v.x = e.x / (1.f + expf(-(v.x + bias1[n])));
                    v.y = e.y / (1.f + expf(-(v.y + bias1[n + 1])));
                    v.z = e.z / (1.f + expf(-(v.z + bias1[n + 2])));
                    v.w = e.w / (1.f + expf(-(v.w + bias1[n + 3])));
                }
                *(float4*)(crow + n) = v;
            }
        }
    }
}

// ---------------- layernorm -> bf16 hi/lo -------------------------------------
__global__ void __launch_bounds__(256) ln_kernel(
    const float* __restrict__ in, __nv_bfloat16* __restrict__ hi,
    __nv_bfloat16* __restrict__ lo,
    const float* __restrict__ gam, const float* __restrict__ bet)
{
    const int row  = blockIdx.x * 8 + (threadIdx.x >> 5);
    const int lane = threadIdx.x & 31;
    const float* r = in + (size_t)row * ENCn + lane * 8;
    float4 a  = *(const float4*)r;
    float4 b4 = *(const float4*)(r + 4);
    float s  = a.x + a.y + a.z + a.w + b4.x + b4.y + b4.z + b4.w;
    float sq = a.x*a.x + a.y*a.y + a.z*a.z + a.w*a.w
             + b4.x*b4.x + b4.y*b4.y + b4.z*b4.z + b4.w*b4.w;
#pragma unroll
    for (int o = 16; o; o >>= 1) {
        s  += __shfl_xor_sync(0xFFFFFFFFu, s,  o);
        sq += __shfl_xor_sync(0xFFFFFFFFu, sq, o);
    }
    const float mu   = s * (1.f / 256.f);
    const float var  = sq * (1.f / 256.f) - mu * mu;
    const float rstd = rsqrtf(var + 1e-5f);

    const float* gg = gam + lane * 8;
    const float* bb = bet + lane * 8;
    float4 ga = *(const float4*)gg,  gb  = *(const float4*)(gg + 4);
    float4 ba = *(const float4*)bb,  bbv = *(const float4*)(bb + 4);
    float o8[8];
    o8[0] = (a.x  - mu) * rstd * ga.x + ba.x;
    o8[1] = (a.y  - mu) * rstd * ga.y + ba.y;
    o8[2] = (a.z  - mu) * rstd * ga.z + ba.z;
    o8[3] = (a.w  - mu) * rstd * ga.w + ba.w;
    o8[4] = (b4.x - mu) * rstd * gb.x + bbv.x;
    o8[5] = (b4.y - mu) * rstd * gb.y + bbv.y;
    o8[6] = (b4.z - mu) * rstd * gb.z + bbv.z;
    o8[7] = (b4.w - mu) * rstd * gb.w + bbv.w;

    const size_t base = (size_t)row * ENCn + lane * 8;
#pragma unroll
    for (int k = 0; k < 8; k += 2) {
        __nv_bfloat162 h = __floats2bfloat162_rn(o8[k], o8[k + 1]);
        __nv_bfloat162 l = __floats2bfloat162_rn(o8[k]     - __bfloat162float(h.x),
                                                 o8[k + 1] - __bfloat162float(h.y));
        *(__nv_bfloat162*)(hi + base + k) = h;
        *(__nv_bfloat162*)(lo + base + k) = l;
    }
}

// =============================================================================
// persistent LSTM v7: R9 structure (512 threads, 8-way k) with distributed
// per-CTA flag barrier (release-store to own 128B line; warp-0 polls 32 lines).
// =============================================================================
__global__ void __launch_bounds__(512) lstm_kernel(
    const float* __restrict__ pre, const float* __restrict__ Whh,
    const float* __restrict__ h0,  const float* __restrict__ c0,
    float* __restrict__ xout, __nv_bfloat16* __restrict__ bfh,
    __nv_bfloat16* __restrict__ bfl,
    float* __restrict__ hout, float* __restrict__ cout)
{
    extern __shared__ float sm[];
    float* sW = sm;
    float* sH = sm + 64 * WROW;
    float* sR = sm + 80 * WROW;

    const int tid  = threadIdx.x, cta = blockIdx.x;
    const int ub   = cta & 31, bb = cta >> 5;
    const int warp = tid >> 5, lane = tid & 31;
    const int ks    = warp & 7;
    const int bq_hi = warp >> 3;
    const int ul    = lane & 15;
    const int bq_lo = lane >> 4;
    const int bq    = bq_hi * 2 + bq_lo;
    const int slot  = bq * 16 + ul;
    const int e_u   = tid & 15;
    const int e_b   = (tid >> 4) & 15;
    const int eslot = (e_b >> 2) * 16 + e_u;
    const int ej    = e_b & 3;
    const int gb    = bb * 16 + e_b;
    const int gu    = ub * 16 + e_u;
    const bool epi  = (tid < 256);

    for (int i = tid; i < 64 * 128; i += 512) {
        const int r  = i >> 7;
        const int k4 = i & 127;
        const int g  = r >> 4;
        const int uu = ub * 16 + (r & 15);
        *(float4*)(sW + r * WROW + k4 * 4) =
            *(const float4*)(Whh + ((size_t)(g * HIDn + uu)) * HIDn + k4 * 4);
    }
    if (epi) g_h[0][cta * 256 + tid] = h0[cta * 256 + tid];
    float c = 0.f, hlast = 0.f;
    if (epi) c = c0[gb * HIDn + gu];
    group_sync(bb);
    // read monotonic flag bases (warp 0 lanes: one group member each)
    unsigned base_lane = 0, base_self = 0;
    if (tid < 32) {
        base_lane = ld_acquire(&g_flag[(bb * 32 + tid) * 32]);
        base_self = __shfl_sync(0xFFFFFFFFu, base_lane, ub);
    }
    group_sync(bb);   // nobody publishes before all bases are read

    const float* w0r = sW + (0 * 16 + ul) * WROW + ks * 64;
    const float* w1r = sW + (1 * 16 + ul) * WROW + ks * 64;
    const float* w2r = sW + (2 * 16 + ul) * WROW + ks * 64;
    const float* w3r = sW + (3 * 16 + ul) * WROW + ks * 64;
    const float* hb0 = sH + (bq * 4 + 0) * WROW + ks * 64;
    const float* hb1 = sH + (bq * 4 + 1) * WROW + ks * 64;
    const float* hb2 = sH + (bq * 4 + 2) * WROW + ks * 64;
    const float* hb3 = sH + (bq * 4 + 3) * WROW + ks * 64;

    for (int t = 0; t < Tn; t++) {
        // wait: all 32 group CTAs have published h(t) (flag >= base + t)
        if (t > 0 && tid < 32) {
            const unsigned tgt = base_lane + (unsigned)t;
            unsigned f = ld_acquire(&g_flag[(bb * 32 + tid) * 32]);
            bool done = ((int)(f - tgt) >= 0);
            while (!__all_sync(0xFFFFFFFFu, done)) {
                if (!done) {
                    f = ld_acquire(&g_flag[(bb * 32 + tid) * 32]);
                    done = ((int)(f - tgt) >= 0);
                }
            }
        }
        __syncthreads();

        const float* hr = g_h[t & 1] + (size_t)bb * 16 * HIDn;
        for (int i = tid; i < 16 * 128; i += 512) {
            const int rr = i >> 7, k4 = i & 127;
            *(float4*)(sH + rr * WROW + k4 * 4) =
                *(const float4*)(hr + (size_t)rr * HIDn + k4 * 4);
        }
        float p0 = 0.f, p1 = 0.f, p2 = 0.f, p3 = 0.f;
        if (epi) {
            const float* pb = pre + ((size_t)gb * Tn + t) * G4n + gu;
            p0 = pb[0]; p1 = pb[512]; p2 = pb[1024]; p3 = pb[1536];
        }
        __syncthreads();

        unsigned long long acc[16];
#pragma unroll
        for (int i = 0; i < 16; i++) acc[i] = 0ull;

#pragma unroll 8
        for (int q = 0; q < 16; q++) {
            const int k = q * 4;
            const ulonglong2 ha  = *(const ulonglong2*)(hb0 + k);
            const ulonglong2 hbv = *(const ulonglong2*)(hb1 + k);
            const ulonglong2 hc  = *(const ulonglong2*)(hb2 + k);
            const ulonglong2 hd  = *(const ulonglong2*)(hb3 + k);
            ulonglong2 w;
            w = *(const ulonglong2*)(w0r + k);
            fma2(acc[0], w.x, ha.x);  fma2(acc[0], w.y, ha.y);
            fma2(acc[1], w.x, hbv.x); fma2(acc[1], w.y, hbv.y);
            fma2(acc[2], w.x, hc.x);  fma2(acc[2], w.y, hc.y);
            fma2(acc[3], w.x, hd.x);  fma2(acc[3], w.y, hd.y);
            w = *(const ulonglong2*)(w1r + k);
            fma2(acc[4], w.x, ha.x);  fma2(acc[4], w.y, ha.y);
            fma2(acc[5], w.x, hbv.x); fma2(acc[5], w.y, hbv.y);
            fma2(acc[6], w.x, hc.x);  fma2(acc[6], w.y, hc.y);
            fma2(acc[7], w.x, hd.x);  fma2(acc[7], w.y, hd.y);
            w = *(const ulonglong2*)(w2r + k);
            fma2(acc[8], w.x, ha.x);  fma2(acc[8], w.y, ha.y);
            fma2(acc[9], w.x, hbv.x); fma2(acc[9], w.y, hbv.y);
            fma2(acc[10], w.x, hc.x); fma2(acc[10], w.y, hc.y);
            fma2(acc[11], w.x, hd.x); fma2(acc[11], w.y, hd.y);
            w = *(const ulonglong2*)(w3r + k);
            fma2(acc[12], w.x, ha.x); fma2(acc[12], w.y, ha.y);
            fma2(acc[13], w.x, hbv.x);fma2(acc[13], w.y, hbv.y);
            fma2(acc[14], w.x, hc.x); fma2(acc[14], w.y, hc.y);
            fma2(acc[15], w.x, hd.x); fma2(acc[15], w.y, hd.y);
        }

        float* rp = sR + (ks * 64 + slot) * RSTR;
        *(float4*)(rp + 0)  = make_float4(psum(acc[0]), psum(acc[4]), psum(acc[8]),  psum(acc[12]));
        *(float4*)(rp + 4)  = make_float4(psum(acc[1]), psum(acc[5]), psum(acc[9]),  psum(acc[13]));
        *(float4*)(rp + 8)  = make_float4(psum(acc[2]), psum(acc[6]), psum(acc[10]), psum(acc[14]));
        *(float4*)(rp + 12) = make_float4(psum(acc[3]), psum(acc[7]), psum(acc[11]), psum(acc[15]));
        __syncthreads();

        if (epi) {
            float4 s = *(const float4*)(sR + (0 * 64 + eslot) * RSTR + ej * 4);
            float gi = s.x, gf = s.y, gc = s.z, go = s.w;
#pragma unroll
            for (int kk = 1; kk < 8; kk++) {
                const float4 sk = *(const float4*)(sR + (kk * 64 + eslot) * RSTR + ej * 4);
                gi += sk.x; gf += sk.y; gc += sk.z; go += sk.w;
            }
            gi += p0; gf += p1; gc += p2; go += p3;
            const float si = __fdividef(1.f, 1.f + __expf(-gi));
            const float sf = __fdividef(1.f, 1.f + __expf(-gf));
            const float so = __fdividef(1.f, 1.f + __expf(-go));
            const float tg = 2.f * __fdividef(1.f, 1.f + __expf(-2.f * gc)) - 1.f;
            c = sf * c + si * tg;
            const float tc = 2.f * __fdividef(1.f, 1.f + __expf(-2.f * c)) - 1.f;
            const float hn = so * tc;
            hlast = hn;
            const size_t xo = ((size_t)gb * Tn + t) * HIDn + gu;
            if (bfh) {
                __nv_bfloat16 hh = __float2bfloat16(hn);
                bfh[xo] = hh;
                bfl[xo] = __float2bfloat16(hn - __bfloat162float(hh));
            } else {
                xout[xo] = hn;
            }
            g_h[(t + 1) & 1][gb * HIDn + gu] = hn;
        }
        __syncthreads();
        if (tid == 0) st_release(&g_flag[cta * 32], base_self + (unsigned)(t + 1));
    }

    if (epi) {
        hout[gb * HIDn + gu] = hlast;
        cout[gb * HIDn + gu] = c;
    }
}

// =============================================================================
extern "C" void kernel_launch(void* const* d_in, const int* in_sizes, int n_in,
                              void* d_out, int out_size)
{
    const float* x      = (const float*)d_in[0];
    const float* states = (const float*)d_in[1];
    const float* W_enc  = (const float*)d_in[2];
    const float* ln_g   = (const float*)d_in[3];
    const float* ln_b   = (const float*)d_in[4];
    const float* Wih1   = (const float*)d_in[5];
    const float* Whh1   = (const float*)d_in[6];
    const float* bih1   = (const float*)d_in[7];
    const float* bhh1   = (const float*)d_in[8];
    const float* Wih2   = (const float*)d_in[9];
    const float* Whh2   = (const float*)d_in[10];
    const float* bih2   = (const float*)d_in[11];
    const float* bhh2   = (const float*)d_in[12];
    const float* Wlin   = (const float*)d_in[13];
    const float* blin   = (const float*)d_in[14];
    const float* W_dec  = (const float*)d_in[15];

    float* out     = (float*)d_out;
    float* dstates = out + (size_t)Bn * FRAMEn * Tn;

    float *encoded, *buf, *pre, *x1;
    __nv_bfloat16 *ah, *al, *wh, *wl;
    cudaGetSymbolAddress((void**)&encoded, g_encoded);
    cudaGetSymbolAddress((void**)&buf,     g_buf);
    cudaGetSymbolAddress((void**)&pre,     g_pre);
    cudaGetSymbolAddress((void**)&x1,      g_x1);
    cudaGetSymbolAddress((void**)&ah,      g_ah);
    cudaGetSymbolAddress((void**)&al,      g_al);
    cudaGetSymbolAddress((void**)&wh,      g_wh);
    cudaGetSymbolAddress((void**)&wl,      g_wl);

    static int attr_set = 0;
    const int LSTM_SMEM = (80 * WROW + 8 * 64 * RSTR) * 4;   // 206,080 B
    if (!attr_set) {
        cudaFuncSetAttribute(lstm_kernel,
                             cudaFuncAttributeMaxDynamicSharedMemorySize, LSTM_SMEM);
        attr_set = 1;
    }

    const int BH = Bn * HIDn;

    // 1) encoder (fp32 SIMT)
    gemm_k<1, 0><<<dim3(ENCn / 128, Tn / 128, Bn), 256>>>(
        x, W_enc, encoded, 0, 0, 0,
        Tn, ENCn, FRAMEn, (size_t)FRAMEn * Tn, 0, (size_t)Tn * ENCn);

    // 2) layernorm -> bf16 hi/lo
    ln_kernel<<<(Bn * Tn) / 8, 256>>>(encoded, ah, al, ln_g, ln_b);

    // 3) pre1 (HMMA split-bf16)
    split_kernel<<<(G4n * ENCn / 4 + 255) / 256, 256>>>(Wih1, wh, wl, G4n * ENCn / 4);
    gemm_mma<<<dim3(G4n / 128, (Bn * Tn) / 128), 256>>>(
        ah, al, wh, wl, pre, bih1, bhh1, Bn * Tn, G4n, ENCn);

    // 4) LSTM layer 1 (emits x1 as bf16 hi/lo)
    lstm_kernel<<<NBLK, 512, LSTM_SMEM>>>(
        pre, Whh1, states + 0 * BH, states + 1 * BH,
        x1, ah, al, dstates + 0 * BH, dstates + 1 * BH);

    // 5) pre2 (HMMA split-bf16)
    split_kernel<<<(G4n * HIDn / 4 + 255) / 256, 256>>>(Wih2, wh, wl, G4n * HIDn / 4);
    gemm_mma<<<dim3(G4n / 128, (Bn * Tn) / 128), 256>>>(
        ah, al, wh, wl, pre, bih2, bhh2, Bn * Tn, G4n, HIDn);

    // 6) LSTM layer 2 (fp32 x2 -> g_x1)
    lstm_kernel<<<NBLK, 512, LSTM_SMEM>>>(
        pre, Whh2, states + 2 * BH, states + 3 * BH,
        x1, (__nv_bfloat16*)0, (__nv_bfloat16*)0,
        dstates + 2 * BH, dstates + 3 * BH);

    // 7) est = sigmoid(x2 @ Wlin^T + blin) * encoded
    gemm_k<0, 2><<<dim3(ENCn / 128, (Bn * Tn) / 128, 1), 256>>>(
        x1, Wlin, buf, encoded, blin, 0,
        Bn * Tn, ENCn, HIDn, 0, 0, 0);

    // 8) decoder
    gemm_k<0, 0><<<dim3(Tn / 128, FRAMEn / 128, Bn), 256>>>(
        W_dec, buf, out, 0, 0, 0,
        FRAMEn, Tn, ENCn, 0, (size_t)Tn * ENCn, (size_t)FRAMEn * Tn);
}

// round 14
// speedup vs baseline: 2.2919x; 1.0736x over previous
#include <cuda_runtime.h>
#include <cuda_fp16.h>
#include <cstdint>
#include <math.h>

#define Bn     64
#define Tn     1024
#define FRAMEn 512
#define ENCn   256
#define HIDn   512
#define G4n    2048
#define NBLK   128
#define GSIZE  32
#define WROW   516
#define RSTR   20
#define APAD   40

__device__ float g_encoded[(size_t)Bn * Tn * ENCn];
__device__ float g_pre[(size_t)Bn * Tn * G4n];
__device__ float g_h[2][Bn * HIDn];
__device__ unsigned g_cnt[4];
__device__ unsigned g_gen[4];
__device__ unsigned g_flag[NBLK * 32];
__device__ __half g_ah[(size_t)Bn * Tn * HIDn];     // activations fp16 (ln/x1/x2)
__device__ __half g_esth[(size_t)Bn * Tn * ENCn];   // est hi
__device__ __half g_estl[(size_t)Bn * Tn * ENCn];   // est lo
__device__ __half g_wh[(size_t)G4n * HIDn];         // weight hi
__device__ __half g_wl[(size_t)G4n * HIDn];         // weight lo
__device__ __half g_wd[(size_t)FRAMEn * ENCn];      // W_dec fp16

// ---------------- sync primitives ---------------------------------------------
__device__ __forceinline__ unsigned atom_add_release(unsigned* p, unsigned v) {
    unsigned o; asm volatile("atom.add.release.gpu.global.u32 %0, [%1], %2;"
                             : "=r"(o) : "l"(p), "r"(v) : "memory"); return o;
}
__device__ __forceinline__ unsigned ld_acquire(const unsigned* p) {
    unsigned v; asm volatile("ld.acquire.gpu.global.u32 %0, [%1];" : "=r"(v) : "l"(p) : "memory"); return v;
}
__device__ __forceinline__ void st_relaxed(unsigned* p, unsigned v) {
    asm volatile("st.relaxed.gpu.global.u32 [%0], %1;" :: "l"(p), "r"(v) : "memory");
}
__device__ __forceinline__ void st_release(unsigned* p, unsigned v) {
    asm volatile("st.release.gpu.global.u32 [%0], %1;" :: "l"(p), "r"(v) : "memory");
}
__device__ __forceinline__ void red_add_release(unsigned* p, unsigned v) {
    asm volatile("red.add.release.gpu.global.u32 [%0], %1;" :: "l"(p), "r"(v) : "memory");
}
__device__ __forceinline__ void group_sync(int g) {
    __syncthreads();
    if (threadIdx.x == 0) {
        const unsigned gen = ld_acquire(&g_gen[g]);
        if (atom_add_release(&g_cnt[g], 1u) == GSIZE - 1) {
            st_relaxed(&g_cnt[g], 0u);
            red_add_release(&g_gen[g], 1u);
        } else {
            while (ld_acquire(&g_gen[g]) == gen) { }
        }
    }
    __syncthreads();
}

// ---------------- f32x2 helpers -------------------------------------------------
__device__ __forceinline__ void fma2(unsigned long long& d,
                                     unsigned long long a, unsigned long long b) {
    asm("fma.rn.f32x2 %0, %1, %2, %0;" : "+l"(d) : "l"(a), "l"(b));
}
__device__ __forceinline__ unsigned long long bcast2(float v) {
    unsigned long long d; asm("mov.b64 %0, {%1, %1};" : "=l"(d) : "r"(__float_as_uint(v))); return d;
}
__device__ __forceinline__ float lo2(unsigned long long v) { return __uint_as_float((unsigned)v); }
__device__ __forceinline__ float hi2(unsigned long long v) { return __uint_as_float((unsigned)(v >> 32)); }
__device__ __forceinline__ float psum(unsigned long long v) { return lo2(v) + hi2(v); }

// ---------------- mma helpers ----------------------------------------------------
__device__ __forceinline__ uint32_t smem_u32(const void* p) {
    uint32_t a;
    asm("{ .reg .u64 t; cvta.to.shared.u64 t, %1; cvt.u32.u64 %0, t; }" : "=r"(a) : "l"(p));
    return a;
}
__device__ __forceinline__ void ldmx4(uint32_t& r0, uint32_t& r1, uint32_t& r2,
                                      uint32_t& r3, uint32_t addr) {
    asm volatile("ldmatrix.sync.aligned.m8n8.x4.shared.b16 {%0,%1,%2,%3}, [%4];"
                 : "=r"(r0), "=r"(r1), "=r"(r2), "=r"(r3) : "r"(addr));
}
__device__ __forceinline__ void mma_h(float* d, const uint32_t* a, const uint32_t* b) {
    asm volatile(
        "mma.sync.aligned.m16n8k16.row.col.f32.f16.f16.f32 "
        "{%0,%1,%2,%3}, {%4,%5,%6,%7}, {%8,%9}, {%0,%1,%2,%3};"
        : "+f"(d[0]), "+f"(d[1]), "+f"(d[2]), "+f"(d[3])
        : "r"(a[0]), "r"(a[1]), "r"(a[2]), "r"(a[3]), "r"(b[0]), "r"(b[1]));
}

// =============================================================================
// fp16 2-pass HMMA GEMM: C[M,N] = A[M,K] @ (Bh+Bl)[N,K]^T
//   EPI 0: C = acc + b1[n] + b2[n]
//   EPI 1: v = sigmoid(acc + b1[n]) * E[m,n]; emit fp16 hi/lo -> Ch/Cl
//   EPI 2: C = acc (z-batched B and C)
// Tile 128x128, BK=32, 256 threads (8 warps 64x32), 2 CTAs/SM.
// =============================================================================
template <int EPI>
__global__ void __launch_bounds__(256, 2) gemm_h(
    const __half* __restrict__ A, const __half* __restrict__ Bh,
    const __half* __restrict__ Bl, float* __restrict__ C,
    const float* __restrict__ E, const float* __restrict__ b1,
    const float* __restrict__ b2, __half* __restrict__ Ch, __half* __restrict__ Cl,
    int M, int N, int K, size_t sB, size_t sC)
{
    __shared__ __half sA[128 * APAD], sBh[128 * APAD], sBl[128 * APAD];

    const int tid = threadIdx.x;
    const int wid = tid >> 5, lane = tid & 31;
    const int wm = wid >> 2, wn = wid & 3;
    const int n0 = blockIdx.x * 128;
    const size_t m0 = (size_t)blockIdx.y * 128;
    const size_t z = blockIdx.z;
    const __half* Bhb = Bh + z * sB;
    const __half* Blb = Bl + z * sB;
    float* Cb = C + z * sC;

    const uint32_t bA = smem_u32(sA), bBh = smem_u32(sBh), bBl = smem_u32(sBl);
    const int lq = lane >> 3, lr = lane & 7;
    const int aRow = (lq & 1) * 8 + lr, aK = (lq >> 1) * 8;
    const int bRow = (lq >> 1) * 8 + lr, bK = (lq & 1) * 8;

    float acc[4][4][4];
#pragma unroll
    for (int i = 0; i < 4; i++)
#pragma unroll
        for (int j = 0; j < 4; j++)
#pragma unroll
            for (int k = 0; k < 4; k++) acc[i][j][k] = 0.f;

    const int nch = K >> 5;
    for (int ch = 0; ch < nch; ch++) {
        const int k0 = ch << 5;
#pragma unroll
        for (int j = 0; j < 2; j++) {
            const int idx = tid + j * 256;
            const int r = idx >> 2, s = idx & 3;
            const size_t ga = (m0 + r) * K + k0 + s * 8;
            const size_t gb = (size_t)(n0 + r) * K + k0 + s * 8;
            *(uint4*)(sA  + r * APAD + s * 8) = *(const uint4*)(A   + ga);
            *(uint4*)(sBh + r * APAD + s * 8) = *(const uint4*)(Bhb + gb);
            *(uint4*)(sBl + r * APAD + s * 8) = *(const uint4*)(Blb + gb);
        }
        __syncthreads();

#pragma unroll
        for (int ks = 0; ks < 2; ks++) {
            uint32_t af[4][4], bhf[4][2], blf[4][2];
#pragma unroll
            for (int mt = 0; mt < 4; mt++) {
                const uint32_t off =
                    (uint32_t)((wm * 64 + mt * 16 + aRow) * APAD + ks * 16 + aK) * 2;
                ldmx4(af[mt][0], af[mt][1], af[mt][2], af[mt][3], bA + off);
            }
#pragma unroll
            for (int p = 0; p < 2; p++) {
                const uint32_t off =
                    (uint32_t)((wn * 32 + p * 16 + bRow) * APAD + ks * 16 + bK) * 2;
                uint32_t r0, r1, r2, r3;
                ldmx4(r0, r1, r2, r3, bBh + off);
                bhf[p * 2][0] = r0; bhf[p * 2][1] = r1;
                bhf[p * 2 + 1][0] = r2; bhf[p * 2 + 1][1] = r3;
                ldmx4(r0, r1, r2, r3, bBl + off);
                blf[p * 2][0] = r0; blf[p * 2][1] = r1;
                blf[p * 2 + 1][0] = r2; blf[p * 2 + 1][1] = r3;
            }
#pragma unroll
            for (int mt = 0; mt < 4; mt++)
#pragma unroll
                for (int nt = 0; nt < 4; nt++) {
                    mma_h(acc[mt][nt], af[mt], bhf[nt]);
                    mma_h(acc[mt][nt], af[mt], blf[nt]);
                }
        }
        __syncthreads();
    }

    const int g = lane >> 2;
    const int cl = (lane & 3) * 2;
#pragma unroll
    for (int nt = 0; nt < 4; nt++) {
        const int n = n0 + wn * 32 + nt * 8 + cl;
        float bx = 0.f, by = 0.f;
        if (EPI == 0) { bx = b1[n] + b2[n]; by = b1[n + 1] + b2[n + 1]; }
        if (EPI == 1) { bx = b1[n]; by = b1[n + 1]; }
#pragma unroll
        for (int mt = 0; mt < 4; mt++) {
            const size_t r0 = m0 + wm * 64 + mt * 16 + g;
#pragma unroll
            for (int hrow = 0; hrow < 2; hrow++) {
                const size_t m = r0 + hrow * 8;
                float vx = acc[mt][nt][hrow * 2]     + bx;
                float vy = acc[mt][nt][hrow * 2 + 1] + by;
                if (EPI == 1) {
                    const float2 e = *(const float2*)(E + m * N + n);
                    vx = e.x / (1.f + expf(-vx));
                    vy = e.y / (1.f + expf(-vy));
                    __half hx = __float2half_rn(vx), hy = __float2half_rn(vy);
                    __half2 hv; hv.x = hx; hv.y = hy;
                    __half2 lv;
                    lv.x = __float2half_rn(vx - __half2float(hx));
                    lv.y = __float2half_rn(vy - __half2float(hy));
                    *(__half2*)(Ch + m * N + n) = hv;
                    *(__half2*)(Cl + m * N + n) = lv;
                } else {
                    *(float2*)(Cb + m * N + n) = make_float2(vx, vy);
                }
            }
        }
    }
}

// ---------------- fp32 -> fp16 hi/lo splitter -----------------------------------
__global__ void __launch_bounds__(256) split_kernel(
    const float* __restrict__ x, __half* __restrict__ hi,
    __half* __restrict__ lo, int n4)
{
    const int i = blockIdx.x * 256 + threadIdx.x;
    if (i >= n4) return;
    const float4 v = ((const float4*)x)[i];
    __half2 a, b, c, d;
    a.x = __float2half_rn(v.x); a.y = __float2half_rn(v.y);
    b.x = __float2half_rn(v.z); b.y = __float2half_rn(v.w);
    c.x = __float2half_rn(v.x - __half2float(a.x));
    c.y = __float2half_rn(v.y - __half2float(a.y));
    d.x = __float2half_rn(v.z - __half2float(b.x));
    d.y = __float2half_rn(v.w - __half2float(b.y));
    ((__half2*)hi)[i * 2] = a; ((__half2*)hi)[i * 2 + 1] = b;
    ((__half2*)lo)[i * 2] = c; ((__half2*)lo)[i * 2 + 1] = d;
}

// ---------------- fp32 -> fp16 convert -------------------------------------------
__global__ void __launch_bounds__(256) cvt16_kernel(
    const float* __restrict__ x, __half* __restrict__ y, int n4)
{
    const int i = blockIdx.x * 256 + threadIdx.x;
    if (i >= n4) return;
    const float4 v = ((const float4*)x)[i];
    __half2 a, b;
    a.x = __float2half_rn(v.x); a.y = __float2half_rn(v.y);
    b.x = __float2half_rn(v.z); b.y = __float2half_rn(v.w);
    ((__half2*)y)[i * 2] = a; ((__half2*)y)[i * 2 + 1] = b;
}

// =============================================================================
// SIMT fp32 GEMM (encoder): C[M,N] = A^T @ B^T, A is [K,M] (lda=M), z-batched A,C
// =============================================================================
__global__ void __launch_bounds__(256, 2) gemm_enc(
    const float* __restrict__ A, const float* __restrict__ Bm,
    float* __restrict__ C, int M, int N, int K, size_t sA, size_t sC)
{
    __shared__ float As[2][8 * 128];
    __shared__ float Bs[2][8 * 128];

    const int tid = threadIdx.x;
    const size_t z = blockIdx.z;
    const float* Ab = A + z * sA;
    float* Cb = C + z * sC;

    const int n0 = blockIdx.x * 128;
    const int m0 = blockIdx.y * 128;
    const int tx = tid & 15, ty = tid >> 4;
    const int row = tid >> 1, half = tid & 1;
    const int kr = tid >> 5, mc = tid & 31;

    unsigned long long acc2[4][8];
#pragma unroll
    for (int ip = 0; ip < 4; ip++)
#pragma unroll
        for (int j = 0; j < 8; j++) acc2[ip][j] = 0ull;

    float4 pa = *(const float4*)(Ab + (size_t)kr * M + m0 + mc * 4);
    float4 pb = *(const float4*)(Bm + (size_t)(n0 + row) * K + half * 4);
    *(float4*)&As[0][kr * 128 + mc * 4] = pa;
    Bs[0][(half * 4 + 0) * 128 + row] = pb.x;
    Bs[0][(half * 4 + 1) * 128 + row] = pb.y;
    Bs[0][(half * 4 + 2) * 128 + row] = pb.z;
    Bs[0][(half * 4 + 3) * 128 + row] = pb.w;
    __syncthreads();

    int buf = 0;
    for (int k0 = 0; k0 < K; k0 += 8) {
        const bool more = (k0 + 8 < K);
        if (more) {
            pa = *(const float4*)(Ab + (size_t)(k0 + 8 + kr) * M + m0 + mc * 4);
            pb = *(const float4*)(Bm + (size_t)(n0 + row) * K + k0 + 8 + half * 4);
        }
#pragma unroll
        for (int kk = 0; kk < 8; kk++) {
            ulonglong2 aA = *(const ulonglong2*)&As[buf][kk * 128 + ty * 8];
            ulonglong2 aB = *(const ulonglong2*)&As[buf][kk * 128 + ty * 8 + 4];
            float bv[8];
            *(float4*)(bv)     = *(const float4*)&Bs[buf][kk * 128 + tx * 8];
            *(float4*)(bv + 4) = *(const float4*)&Bs[buf][kk * 128 + tx * 8 + 4];
#pragma unroll
            for (int j = 0; j < 8; j++) {
                const unsigned long long bj = bcast2(bv[j]);
                fma2(acc2[0][j], aA.x, bj);
                fma2(acc2[1][j], aA.y, bj);
                fma2(acc2[2][j], aB.x, bj);
                fma2(acc2[3][j], aB.y, bj);
            }
        }
        if (more) {
            const int nb = buf ^ 1;
            *(float4*)&As[nb][kr * 128 + mc * 4] = pa;
            Bs[nb][(half * 4 + 0) * 128 + row] = pb.x;
            Bs[nb][(half * 4 + 1) * 128 + row] = pb.y;
            Bs[nb][(half * 4 + 2) * 128 + row] = pb.z;
            Bs[nb][(half * 4 + 3) * 128 + row] = pb.w;
            __syncthreads();
            buf = nb;
        }
    }
#pragma unroll
    for (int ip = 0; ip < 4; ip++)
#pragma unroll
        for (int hf = 0; hf < 2; hf++) {
            const int m = m0 + ty * 8 + ip * 2 + hf;
            float* crow = Cb + (size_t)m * N;
#pragma unroll
            for (int j = 0; j < 8; j += 4) {
                const int n = n0 + tx * 8 + j;
                float4 v;
                v.x = hf ? hi2(acc2[ip][j])     : lo2(acc2[ip][j]);
                v.y = hf ? hi2(acc2[ip][j + 1]) : lo2(acc2[ip][j + 1]);
                v.z = hf ? hi2(acc2[ip][j + 2]) : lo2(acc2[ip][j + 2]);
                v.w = hf ? hi2(acc2[ip][j + 3]) : lo2(acc2[ip][j + 3]);
                *(float4*)(crow + n) = v;
            }
        }
}

// ---------------- layernorm -> fp16 ---------------------------------------------
__global__ void __launch_bounds__(256) ln_kernel(
    const float* __restrict__ in, __half* __restrict__ out16,
    const float* __restrict__ gam, const float* __restrict__ bet)
{
    const int row  = blockIdx.x * 8 + (threadIdx.x >> 5);
    const int lane = threadIdx.x & 31;
    const float* r = in + (size_t)row * ENCn + lane * 8;
    float4 a  = *(const float4*)r;
    float4 b4 = *(const float4*)(r + 4);
    float s  = a.x + a.y + a.z + a.w + b4.x + b4.y + b4.z + b4.w;
    float sq = a.x*a.x + a.y*a.y + a.z*a.z + a.w*a.w
             + b4.x*b4.x + b4.y*b4.y + b4.z*b4.z + b4.w*b4.w;
#pragma unroll
    for (int o = 16; o; o >>= 1) {
        s  += __shfl_xor_sync(0xFFFFFFFFu, s,  o);
        sq += __shfl_xor_sync(0xFFFFFFFFu, sq, o);
    }
    const float mu   = s * (1.f / 256.f);
    const float rstd = rsqrtf(sq * (1.f / 256.f) - mu * mu + 1e-5f);

    const float* gg = gam + lane * 8;
    const float* bb = bet + lane * 8;
    float4 ga = *(const float4*)gg, gb = *(const float4*)(gg + 4);
    float4 ba = *(const float4*)bb, bv = *(const float4*)(bb + 4);
    __half h8[8];
    h8[0] = __float2half_rn((a.x  - mu) * rstd * ga.x + ba.x);
    h8[1] = __float2half_rn((a.y  - mu) * rstd * ga.y + ba.y);
    h8[2] = __float2half_rn((a.z  - mu) * rstd * ga.z + ba.z);
    h8[3] = __float2half_rn((a.w  - mu) * rstd * ga.w + ba.w);
    h8[4] = __float2half_rn((b4.x - mu) * rstd * gb.x + bv.x);
    h8[5] = __float2half_rn((b4.y - mu) * rstd * gb.y + bv.y);
    h8[6] = __float2half_rn((b4.z - mu) * rstd * gb.z + bv.z);
    h8[7] = __float2half_rn((b4.w - mu) * rstd * gb.w + bv.w);
    *(uint4*)(out16 + (size_t)row * ENCn + lane * 8) = *(uint4*)h8;
}

// =============================================================================
// persistent LSTM (512 threads, 8-way k) with distributed per-CTA flag barrier.
// Emits x as fp16 to x16.
// =============================================================================
__global__ void __launch_bounds__(512) lstm_kernel(
    const float* __restrict__ pre, const float* __restrict__ Whh,
    const float* __restrict__ h0,  const float* __restrict__ c0,
    __half* __restrict__ x16, float* __restrict__ hout, float* __restrict__ cout)
{
    extern __shared__ float sm[];
    float* sW = sm;
    float* sH = sm + 64 * WROW;
    float* sR = sm + 80 * WROW;

    const int tid  = threadIdx.x, cta = blockIdx.x;
    const int ub   = cta & 31, bb = cta >> 5;
    const int warp = tid >> 5, lane = tid & 31;
    const int ks    = warp & 7;
    const int bq_hi = warp >> 3;
    const int ul    = lane & 15;
    const int bq_lo = lane >> 4;
    const int bq    = bq_hi * 2 + bq_lo;
    const int slot  = bq * 16 + ul;
    const int e_u   = tid & 15;
    const int e_b   = (tid >> 4) & 15;
    const int eslot = (e_b >> 2) * 16 + e_u;
    const int ej    = e_b & 3;
    const int gb    = bb * 16 + e_b;
    const int gu    = ub * 16 + e_u;
    const bool epi  = (tid < 256);

    for (int i = tid; i < 64 * 128; i += 512) {
        const int r = i >> 7, k4 = i & 127;
        const int g = r >> 4;
        const int uu = ub * 16 + (r & 15);
        *(float4*)(sW + r * WROW + k4 * 4) =
            *(const float4*)(Whh + ((size_t)(g * HIDn + uu)) * HIDn + k4 * 4);
    }
    if (epi) g_h[0][cta * 256 + tid] = h0[cta * 256 + tid];
    float c = 0.f, hlast = 0.f;
    if (epi) c = c0[gb * HIDn + gu];
    group_sync(bb);
    unsigned base_lane = 0, base_self = 0;
    if (tid < 32) {
        base_lane = ld_acquire(&g_flag[(bb * 32 + tid) * 32]);
        base_self = __shfl_sync(0xFFFFFFFFu, base_lane, ub);
    }
    group_sync(bb);

    const float* w0r = sW + (0 * 16 + ul) * WROW + ks * 64;
    const float* w1r = sW + (1 * 16 + ul) * WROW + ks * 64;
    const float* w2r = sW + (2 * 16 + ul) * WROW + ks * 64;
    const float* w3r = sW + (3 * 16 + ul) * WROW + ks * 64;
    const float* hb0 = sH + (bq * 4 + 0) * WROW + ks * 64;
    const float* hb1 = sH + (bq * 4 + 1) * WROW + ks * 64;
    const float* hb2 = sH + (bq * 4 + 2) * WROW + ks * 64;
    const float* hb3 = sH + (bq * 4 + 3) * WROW + ks * 64;

    for (int t = 0; t < Tn; t++) {
        if (t > 0 && tid < 32) {
            const unsigned tgt = base_lane + (unsigned)t;
            unsigned f = ld_acquire(&g_flag[(bb * 32 + tid) * 32]);
            bool done = ((int)(f - tgt) >= 0);
            while (!__all_sync(0xFFFFFFFFu, done)) {
                if (!done) {
                    f = ld_acquire(&g_flag[(bb * 32 + tid) * 32]);
                    done = ((int)(f - tgt) >= 0);
                }
            }
        }
        __syncthreads();

        const float* hr = g_h[t & 1] + (size_t)bb * 16 * HIDn;
        for (int i = tid; i < 16 * 128; i += 512) {
            const int rr = i >> 7, k4 = i & 127;
            *(float4*)(sH + rr * WROW + k4 * 4) =
                *(const float4*)(hr + (size_t)rr * HIDn + k4 * 4);
        }
        float p0 = 0.f, p1 = 0.f, p2 = 0.f, p3 = 0.f;
        if (epi) {
            const float* pb = pre + ((size_t)gb * Tn + t) * G4n + gu;
            p0 = pb[0]; p1 = pb[512]; p2 = pb[1024]; p3 = pb[1536];
        }
        __syncthreads();

        unsigned long long acc[16];
#pragma unroll
        for (int i = 0; i < 16; i++) acc[i] = 0ull;

#pragma unroll 8
        for (int q = 0; q < 16; q++) {
            const int k = q * 4;
            const ulonglong2 ha  = *(const ulonglong2*)(hb0 + k);
            const ulonglong2 hbv = *(const ulonglong2*)(hb1 + k);
            const ulonglong2 hc  = *(const ulonglong2*)(hb2 + k);
            const ulonglong2 hd  = *(const ulonglong2*)(hb3 + k);
            ulonglong2 w;
            w = *(const ulonglong2*)(w0r + k);
            fma2(acc[0], w.x, ha.x);  fma2(acc[0], w.y, ha.y);
            fma2(acc[1], w.x, hbv.x); fma2(acc[1], w.y, hbv.y);
            fma2(acc[2], w.x, hc.x);  fma2(acc[2], w.y, hc.y);
            fma2(acc[3], w.x, hd.x);  fma2(acc[3], w.y, hd.y);
            w = *(const ulonglong2*)(w1r + k);
            fma2(acc[4], w.x, ha.x);  fma2(acc[4], w.y, ha.y);
            fma2(acc[5], w.x, hbv.x); fma2(acc[5], w.y, hbv.y);
            fma2(acc[6], w.x, hc.x);  fma2(acc[6], w.y, hc.y);
            fma2(acc[7], w.x, hd.x);  fma2(acc[7], w.y, hd.y);
            w = *(const ulonglong2*)(w2r + k);
            fma2(acc[8], w.x, ha.x);  fma2(acc[8], w.y, ha.y);
            fma2(acc[9], w.x, hbv.x); fma2(acc[9], w.y, hbv.y);
            fma2(acc[10], w.x, hc.x); fma2(acc[10], w.y, hc.y);
            fma2(acc[11], w.x, hd.x); fma2(acc[11], w.y, hd.y);
            w = *(const ulonglong2*)(w3r + k);
            fma2(acc[12], w.x, ha.x); fma2(acc[12], w.y, ha.y);
            fma2(acc[13], w.x, hbv.x);fma2(acc[13], w.y, hbv.y);
            fma2(acc[14], w.x, hc.x); fma2(acc[14], w.y, hc.y);
            fma2(acc[15], w.x, hd.x); fma2(acc[15], w.y, hd.y);
        }

        float* rp = sR + (ks * 64 + slot) * RSTR;
        *(float4*)(rp + 0)  = make_float4(psum(acc[0]), psum(acc[4]), psum(acc[8]),  psum(acc[12]));
        *(float4*)(rp + 4)  = make_float4(psum(acc[1]), psum(acc[5]), psum(acc[9]),  psum(acc[13]));
        *(float4*)(rp + 8)  = make_float4(psum(acc[2]), psum(acc[6]), psum(acc[10]), psum(acc[14]));
        *(float4*)(rp + 12) = make_float4(psum(acc[3]), psum(acc[7]), psum(acc[11]), psum(acc[15]));
        __syncthreads();

        if (epi) {
            float4 s = *(const float4*)(sR + (0 * 64 + eslot) * RSTR + ej * 4);
            float gi = s.x, gf = s.y, gc = s.z, go = s.w;
#pragma unroll
            for (int kk = 1; kk < 8; kk++) {
                const float4 sk = *(const float4*)(sR + (kk * 64 + eslot) * RSTR + ej * 4);
                gi += sk.x; gf += sk.y; gc += sk.z; go += sk.w;
            }
            gi += p0; gf += p1; gc += p2; go += p3;
            const float si = __fdividef(1.f, 1.f + __expf(-gi));
            const float sf = __fdividef(1.f, 1.f + __expf(-gf));
            const float so = __fdividef(1.f, 1.f + __expf(-go));
            const float tg = 2.f * __fdividef(1.f, 1.f + __expf(-2.f * gc)) - 1.f;
            c = sf * c + si * tg;
            const float tc = 2.f * __fdividef(1.f, 1.f + __expf(-2.f * c)) - 1.f;
            const float hn = so * tc;
            hlast = hn;
            x16[((size_t)gb * Tn + t) * HIDn + gu] = __float2half_rn(hn);
            g_h[(t + 1) & 1][gb * HIDn + gu] = hn;
        }
        __syncthreads();
        if (tid == 0) st_release(&g_flag[cta * 32], base_self + (unsigned)(t + 1));
    }

    if (epi) {
        hout[gb * HIDn + gu] = hlast;
        cout[gb * HIDn + gu] = c;
    }
}

// =============================================================================
extern "C" void kernel_launch(void* const* d_in, const int* in_sizes, int n_in,
                              void* d_out, int out_size)
{
    const float* x      = (const float*)d_in[0];
    const float* states = (const float*)d_in[1];
    const float* W_enc  = (const float*)d_in[2];
    const float* ln_g   = (const float*)d_in[3];
    const float* ln_b   = (const float*)d_in[4];
    const float* Wih1   = (const float*)d_in[5];
    const float* Whh1   = (const float*)d_in[6];
    const float* bih1   = (const float*)d_in[7];
    const float* bhh1   = (const float*)d_in[8];
    const float* Wih2   = (const float*)d_in[9];
    const float* Whh2   = (const float*)d_in[10];
    const float* bih2   = (const float*)d_in[11];
    const float* bhh2   = (const float*)d_in[12];
    const float* Wlin   = (const float*)d_in[13];
    const float* blin   = (const float*)d_in[14];
    const float* W_dec  = (const float*)d_in[15];

    float* out     = (float*)d_out;
    float* dstates = out + (size_t)Bn * FRAMEn * Tn;

    float *encoded, *pre;
    __half *ah, *esth, *estl, *wh, *wl, *wd;
    cudaGetSymbolAddress((void**)&encoded, g_encoded);
    cudaGetSymbolAddress((void**)&pre,     g_pre);
    cudaGetSymbolAddress((void**)&ah,      g_ah);
    cudaGetSymbolAddress((void**)&esth,    g_esth);
    cudaGetSymbolAddress((void**)&estl,    g_estl);
    cudaGetSymbolAddress((void**)&wh,      g_wh);
    cudaGetSymbolAddress((void**)&wl,      g_wl);
    cudaGetSymbolAddress((void**)&wd,      g_wd);

    static int attr_set = 0;
    const int LSTM_SMEM = (80 * WROW + 8 * 64 * RSTR) * 4;   // 206,080 B
    if (!attr_set) {
        cudaFuncSetAttribute(lstm_kernel,
                             cudaFuncAttributeMaxDynamicSharedMemorySize, LSTM_SMEM);
        attr_set = 1;
    }

    const int BH = Bn * HIDn;
    const int BT = Bn * Tn;

    // 1) encoder (fp32 SIMT): encoded[b,t,o] = sum_c x[b,c,t] W_enc[o,c]
    gemm_enc<<<dim3(ENCn / 128, Tn / 128, Bn), 256>>>(
        x, W_enc, encoded, Tn, ENCn, FRAMEn,
        (size_t)FRAMEn * Tn, (size_t)Tn * ENCn);

    // 2) layernorm -> fp16 (A of pre1)
    ln_kernel<<<BT / 8, 256>>>(encoded, ah, ln_g, ln_b);

    // 3) pre1 = enc_norm @ Wih1^T + biases (fp16 2-pass HMMA)
    split_kernel<<<(G4n * ENCn / 4 + 255) / 256, 256>>>(Wih1, wh, wl, G4n * ENCn / 4);
    gemm_h<0><<<dim3(G4n / 128, BT / 128, 1), 256>>>(
        ah, wh, wl, pre, 0, bih1, bhh1, 0, 0, BT, G4n, ENCn, 0, 0);

    // 4) LSTM layer 1 (emits x1 fp16 into ah)
    lstm_kernel<<<NBLK, 512, LSTM_SMEM>>>(
        pre, Whh1, states + 0 * BH, states + 1 * BH,
        ah, dstates + 0 * BH, dstates + 1 * BH);

    // 5) pre2 = x1 @ Wih2^T + biases
    split_kernel<<<(G4n * HIDn / 4 + 255) / 256, 256>>>(Wih2, wh, wl, G4n * HIDn / 4);
    gemm_h<0><<<dim3(G4n / 128, BT / 128, 1), 256>>>(
        ah, wh, wl, pre, 0, bih2, bhh2, 0, 0, BT, G4n, HIDn, 0, 0);

    // 6) LSTM layer 2 (emits x2 fp16 into ah)
    lstm_kernel<<<NBLK, 512, LSTM_SMEM>>>(
        pre, Whh2, states + 2 * BH, states + 3 * BH,
        ah, dstates + 2 * BH, dstates + 3 * BH);

    // 7) est = sigmoid(x2 @ Wlin^T + blin) * encoded -> fp16 hi/lo
    split_kernel<<<(ENCn * HIDn / 4 + 255) / 256, 256>>>(Wlin, wh, wl, ENCn * HIDn / 4);
    gemm_h<1><<<dim3(ENCn / 128, BT / 128, 1), 256>>>(
        ah, wh, wl, 0, encoded, blin, 0, esth, estl, BT, ENCn, HIDn, 0, 0);

    // 8) decoder: out[b,f,t] = sum_o W_dec[f,o] est[b,t,o]  (fp16 2-pass, z=batch)
    cvt16_kernel<<<(FRAMEn * ENCn / 4 + 255) / 256, 256>>>(W_dec, wd, FRAMEn * ENCn / 4);
    gemm_h<2><<<dim3(Tn / 128, FRAMEn / 128, Bn), 256>>>(
        wd, esth, estl, out, 0, 0, 0, 0, 0, FRAMEn, Tn, ENCn,
        (size_t)Tn * ENCn, (size_t)FRAMEn * Tn);
}

// round 15
// speedup vs baseline: 2.3717x; 1.0348x over previous
#include <cuda_runtime.h>
#include <cuda_fp16.h>
#include <cstdint>
#include <math.h>

#define Bn     64
#define Tn     1024
#define FRAMEn 512
#define ENCn   256
#define HIDn   512
#define G4n    2048
#define NBLK   128
#define GSIZE  32
#define WROW   516
#define RSTR   20
#define APAD   40

__device__ float g_encoded[(size_t)Bn * Tn * ENCn];
__device__ float g_pre[(size_t)Bn * Tn * G4n];
__device__ float g_h[2][Bn * HIDn];
__device__ unsigned g_cnt[4];
__device__ unsigned g_gen[4];
__device__ unsigned g_flag[NBLK * 32];
__device__ __half g_ah[(size_t)Bn * Tn * HIDn];
__device__ __half g_esth[(size_t)Bn * Tn * ENCn];
__device__ __half g_estl[(size_t)Bn * Tn * ENCn];
__device__ __half g_wh[(size_t)G4n * HIDn];
__device__ __half g_wl[(size_t)G4n * HIDn];
__device__ __half g_wd[(size_t)FRAMEn * ENCn];

// ---------------- sync primitives ---------------------------------------------
__device__ __forceinline__ unsigned atom_add_release(unsigned* p, unsigned v) {
    unsigned o; asm volatile("atom.add.release.gpu.global.u32 %0, [%1], %2;"
                             : "=r"(o) : "l"(p), "r"(v) : "memory"); return o;
}
__device__ __forceinline__ unsigned ld_acquire(const unsigned* p) {
    unsigned v; asm volatile("ld.acquire.gpu.global.u32 %0, [%1];" : "=r"(v) : "l"(p) : "memory"); return v;
}
__device__ __forceinline__ void st_relaxed(unsigned* p, unsigned v) {
    asm volatile("st.relaxed.gpu.global.u32 [%0], %1;" :: "l"(p), "r"(v) : "memory");
}
__device__ __forceinline__ void st_release(unsigned* p, unsigned v) {
    asm volatile("st.release.gpu.global.u32 [%0], %1;" :: "l"(p), "r"(v) : "memory");
}
__device__ __forceinline__ void red_add_release(unsigned* p, unsigned v) {
    asm volatile("red.add.release.gpu.global.u32 [%0], %1;" :: "l"(p), "r"(v) : "memory");
}
__device__ __forceinline__ void group_sync(int g) {
    __syncthreads();
    if (threadIdx.x == 0) {
        const unsigned gen = ld_acquire(&g_gen[g]);
        if (atom_add_release(&g_cnt[g], 1u) == GSIZE - 1) {
            st_relaxed(&g_cnt[g], 0u);
            red_add_release(&g_gen[g], 1u);
        } else {
            while (ld_acquire(&g_gen[g]) == gen) { }
        }
    }
    __syncthreads();
}

// ---------------- f32x2 helpers -------------------------------------------------
__device__ __forceinline__ void fma2(unsigned long long& d,
                                     unsigned long long a, unsigned long long b) {
    asm("fma.rn.f32x2 %0, %1, %2, %0;" : "+l"(d) : "l"(a), "l"(b));
}
__device__ __forceinline__ unsigned long long bcast2(float v) {
    unsigned long long d; asm("mov.b64 %0, {%1, %1};" : "=l"(d) : "r"(__float_as_uint(v))); return d;
}
__device__ __forceinline__ float lo2(unsigned long long v) { return __uint_as_float((unsigned)v); }
__device__ __forceinline__ float hi2(unsigned long long v) { return __uint_as_float((unsigned)(v >> 32)); }
__device__ __forceinline__ float psum(unsigned long long v) { return lo2(v) + hi2(v); }

// ---------------- mma helpers ----------------------------------------------------
__device__ __forceinline__ uint32_t smem_u32(const void* p) {
    uint32_t a;
    asm("{ .reg .u64 t; cvta.to.shared.u64 t, %1; cvt.u32.u64 %0, t; }" : "=r"(a) : "l"(p));
    return a;
}
__device__ __forceinline__ void ldmx4(uint32_t& r0, uint32_t& r1, uint32_t& r2,
                                      uint32_t& r3, uint32_t addr) {
    asm volatile("ldmatrix.sync.aligned.m8n8.x4.shared.b16 {%0,%1,%2,%3}, [%4];"
                 : "=r"(r0), "=r"(r1), "=r"(r2), "=r"(r3) : "r"(addr));
}
__device__ __forceinline__ void mma_h(float* d, const uint32_t* a, const uint32_t* b) {
    asm volatile(
        "mma.sync.aligned.m16n8k16.row.col.f32.f16.f16.f32 "
        "{%0,%1,%2,%3}, {%4,%5,%6,%7}, {%8,%9}, {%0,%1,%2,%3};"
        : "+f"(d[0]), "+f"(d[1]), "+f"(d[2]), "+f"(d[3])
        : "r"(a[0]), "r"(a[1]), "r"(a[2]), "r"(a[3]), "r"(b[0]), "r"(b[1]));
}

// =============================================================================
// fp16 2-pass HMMA GEMM: C[M,N] = A[M,K] @ (Bh+Bl)[N,K]^T   (EPI as in R13)
// =============================================================================
template <int EPI>
__global__ void __launch_bounds__(256, 2) gemm_h(
    const __half* __restrict__ A, const __half* __restrict__ Bh,
    const __half* __restrict__ Bl, float* __restrict__ C,
    const float* __restrict__ E, const float* __restrict__ b1,
    const float* __restrict__ b2, __half* __restrict__ Ch, __half* __restrict__ Cl,
    int M, int N, int K, size_t sB, size_t sC)
{
    __shared__ __half sA[128 * APAD], sBh[128 * APAD], sBl[128 * APAD];

    const int tid = threadIdx.x;
    const int wid = tid >> 5, lane = tid & 31;
    const int wm = wid >> 2, wn = wid & 3;
    const int n0 = blockIdx.x * 128;
    const size_t m0 = (size_t)blockIdx.y * 128;
    const size_t z = blockIdx.z;
    const __half* Bhb = Bh + z * sB;
    const __half* Blb = Bl + z * sB;
    float* Cb = C + z * sC;

    const uint32_t bA = smem_u32(sA), bBh = smem_u32(sBh), bBl = smem_u32(sBl);
    const int lq = lane >> 3, lr = lane & 7;
    const int aRow = (lq & 1) * 8 + lr, aK = (lq >> 1) * 8;
    const int bRow = (lq >> 1) * 8 + lr, bK = (lq & 1) * 8;

    float acc[4][4][4];
#pragma unroll
    for (int i = 0; i < 4; i++)
#pragma unroll
        for (int j = 0; j < 4; j++)
#pragma unroll
            for (int k = 0; k < 4; k++) acc[i][j][k] = 0.f;

    const int nch = K >> 5;
    for (int ch = 0; ch < nch; ch++) {
        const int k0 = ch << 5;
#pragma unroll
        for (int j = 0; j < 2; j++) {
            const int idx = tid + j * 256;
            const int r = idx >> 2, s = idx & 3;
            const size_t ga = (m0 + r) * K + k0 + s * 8;
            const size_t gb = (size_t)(n0 + r) * K + k0 + s * 8;
            *(uint4*)(sA  + r * APAD + s * 8) = *(const uint4*)(A   + ga);
            *(uint4*)(sBh + r * APAD + s * 8) = *(const uint4*)(Bhb + gb);
            *(uint4*)(sBl + r * APAD + s * 8) = *(const uint4*)(Blb + gb);
        }
        __syncthreads();

#pragma unroll
        for (int ks = 0; ks < 2; ks++) {
            uint32_t af[4][4], bhf[4][2], blf[4][2];
#pragma unroll
            for (int mt = 0; mt < 4; mt++) {
                const uint32_t off =
                    (uint32_t)((wm * 64 + mt * 16 + aRow) * APAD + ks * 16 + aK) * 2;
                ldmx4(af[mt][0], af[mt][1], af[mt][2], af[mt][3], bA + off);
            }
#pragma unroll
            for (int p = 0; p < 2; p++) {
                const uint32_t off =
                    (uint32_t)((wn * 32 + p * 16 + bRow) * APAD + ks * 16 + bK) * 2;
                uint32_t r0, r1, r2, r3;
                ldmx4(r0, r1, r2, r3, bBh + off);
                bhf[p * 2][0] = r0; bhf[p * 2][1] = r1;
                bhf[p * 2 + 1][0] = r2; bhf[p * 2 + 1][1] = r3;
                ldmx4(r0, r1, r2, r3, bBl + off);
                blf[p * 2][0] = r0; blf[p * 2][1] = r1;
                blf[p * 2 + 1][0] = r2; blf[p * 2 + 1][1] = r3;
            }
#pragma unroll
            for (int mt = 0; mt < 4; mt++)
#pragma unroll
                for (int nt = 0; nt < 4; nt++) {
                    mma_h(acc[mt][nt], af[mt], bhf[nt]);
                    mma_h(acc[mt][nt], af[mt], blf[nt]);
                }
        }
        __syncthreads();
    }

    const int g = lane >> 2;
    const int cl = (lane & 3) * 2;
#pragma unroll
    for (int nt = 0; nt < 4; nt++) {
        const int n = n0 + wn * 32 + nt * 8 + cl;
        float bx = 0.f, by = 0.f;
        if (EPI == 0) { bx = b1[n] + b2[n]; by = b1[n + 1] + b2[n + 1]; }
        if (EPI == 1) { bx = b1[n]; by = b1[n + 1]; }
#pragma unroll
        for (int mt = 0; mt < 4; mt++) {
            const size_t r0 = m0 + wm * 64 + mt * 16 + g;
#pragma unroll
            for (int hrow = 0; hrow < 2; hrow++) {
                const size_t m = r0 + hrow * 8;
                float vx = acc[mt][nt][hrow * 2]     + bx;
                float vy = acc[mt][nt][hrow * 2 + 1] + by;
                if (EPI == 1) {
                    const float2 e = *(const float2*)(E + m * N + n);
                    vx = e.x / (1.f + expf(-vx));
                    vy = e.y / (1.f + expf(-vy));
                    __half hx = __float2half_rn(vx), hy = __float2half_rn(vy);
                    __half2 hv; hv.x = hx; hv.y = hy;
                    __half2 lv;
                    lv.x = __float2half_rn(vx - __half2float(hx));
                    lv.y = __float2half_rn(vy - __half2float(hy));
                    *(__half2*)(Ch + m * N + n) = hv;
                    *(__half2*)(Cl + m * N + n) = lv;
                } else {
                    *(float2*)(Cb + m * N + n) = make_float2(vx, vy);
                }
            }
        }
    }
}

// ---------------- fp32 -> fp16 hi/lo splitter -----------------------------------
__global__ void __launch_bounds__(256) split_kernel(
    const float* __restrict__ x, __half* __restrict__ hi,
    __half* __restrict__ lo, int n4)
{
    const int i = blockIdx.x * 256 + threadIdx.x;
    if (i >= n4) return;
    const float4 v = ((const float4*)x)[i];
    __half2 a, b, c, d;
    a.x = __float2half_rn(v.x); a.y = __float2half_rn(v.y);
    b.x = __float2half_rn(v.z); b.y = __float2half_rn(v.w);
    c.x = __float2half_rn(v.x - __half2float(a.x));
    c.y = __float2half_rn(v.y - __half2float(a.y));
    d.x = __float2half_rn(v.z - __half2float(b.x));
    d.y = __float2half_rn(v.w - __half2float(b.y));
    ((__half2*)hi)[i * 2] = a; ((__half2*)hi)[i * 2 + 1] = b;
    ((__half2*)lo)[i * 2] = c; ((__half2*)lo)[i * 2 + 1] = d;
}

// ---------------- fp32 -> fp16 convert -------------------------------------------
__global__ void __launch_bounds__(256) cvt16_kernel(
    const float* __restrict__ x, __half* __restrict__ y, int n4)
{
    const int i = blockIdx.x * 256 + threadIdx.x;
    if (i >= n4) return;
    const float4 v = ((const float4*)x)[i];
    __half2 a, b;
    a.x = __float2half_rn(v.x); a.y = __float2half_rn(v.y);
    b.x = __float2half_rn(v.z); b.y = __float2half_rn(v.w);
    ((__half2*)y)[i * 2] = a; ((__half2*)y)[i * 2 + 1] = b;
}

// =============================================================================
// SIMT fp32 GEMM (encoder): C[M,N] = A^T @ B^T, A is [K,M] (lda=M), z-batched A,C
// =============================================================================
__global__ void __launch_bounds__(256, 2) gemm_enc(
    const float* __restrict__ A, const float* __restrict__ Bm,
    float* __restrict__ C, int M, int N, int K, size_t sA, size_t sC)
{
    __shared__ float As[2][8 * 128];
    __shared__ float Bs[2][8 * 128];

    const int tid = threadIdx.x;
    const size_t z = blockIdx.z;
    const float* Ab = A + z * sA;
    float* Cb = C + z * sC;

    const int n0 = blockIdx.x * 128;
    const int m0 = blockIdx.y * 128;
    const int tx = tid & 15, ty = tid >> 4;
    const int row = tid >> 1, half = tid & 1;
    const int kr = tid >> 5, mc = tid & 31;

    unsigned long long acc2[4][8];
#pragma unroll
    for (int ip = 0; ip < 4; ip++)
#pragma unroll
        for (int j = 0; j < 8; j++) acc2[ip][j] = 0ull;

    float4 pa = *(const float4*)(Ab + (size_t)kr * M + m0 + mc * 4);
    float4 pb = *(const float4*)(Bm + (size_t)(n0 + row) * K + half * 4);
    *(float4*)&As[0][kr * 128 + mc * 4] = pa;
    Bs[0][(half * 4 + 0) * 128 + row] = pb.x;
    Bs[0][(half * 4 + 1) * 128 + row] = pb.y;
    Bs[0][(half * 4 + 2) * 128 + row] = pb.z;
    Bs[0][(half * 4 + 3) * 128 + row] = pb.w;
    __syncthreads();

    int buf = 0;
    for (int k0 = 0; k0 < K; k0 += 8) {
        const bool more = (k0 + 8 < K);
        if (more) {
            pa = *(const float4*)(Ab + (size_t)(k0 + 8 + kr) * M + m0 + mc * 4);
            pb = *(const float4*)(Bm + (size_t)(n0 + row) * K + k0 + 8 + half * 4);
        }
#pragma unroll
        for (int kk = 0; kk < 8; kk++) {
            ulonglong2 aA = *(const ulonglong2*)&As[buf][kk * 128 + ty * 8];
            ulonglong2 aB = *(const ulonglong2*)&As[buf][kk * 128 + ty * 8 + 4];
            float bv[8];
            *(float4*)(bv)     = *(const float4*)&Bs[buf][kk * 128 + tx * 8];
            *(float4*)(bv + 4) = *(const float4*)&Bs[buf][kk * 128 + tx * 8 + 4];
#pragma unroll
            for (int j = 0; j < 8; j++) {
                const unsigned long long bj = bcast2(bv[j]);
                fma2(acc2[0][j], aA.x, bj);
                fma2(acc2[1][j], aA.y, bj);
                fma2(acc2[2][j], aB.x, bj);
                fma2(acc2[3][j], aB.y, bj);
            }
        }
        if (more) {
            const int nb = buf ^ 1;
            *(float4*)&As[nb][kr * 128 + mc * 4] = pa;
            Bs[nb][(half * 4 + 0) * 128 + row] = pb.x;
            Bs[nb][(half * 4 + 1) * 128 + row] = pb.y;
            Bs[nb][(half * 4 + 2) * 128 + row] = pb.z;
            Bs[nb][(half * 4 + 3) * 128 + row] = pb.w;
            __syncthreads();
            buf = nb;
        }
    }
#pragma unroll
    for (int ip = 0; ip < 4; ip++)
#pragma unroll
        for (int hf = 0; hf < 2; hf++) {
            const int m = m0 + ty * 8 + ip * 2 + hf;
            float* crow = Cb + (size_t)m * N;
#pragma unroll
            for (int j = 0; j < 8; j += 4) {
                const int n = n0 + tx * 8 + j;
                float4 v;
                v.x = hf ? hi2(acc2[ip][j])     : lo2(acc2[ip][j]);
                v.y = hf ? hi2(acc2[ip][j + 1]) : lo2(acc2[ip][j + 1]);
                v.z = hf ? hi2(acc2[ip][j + 2]) : lo2(acc2[ip][j + 2]);
                v.w = hf ? hi2(acc2[ip][j + 3]) : lo2(acc2[ip][j + 3]);
                *(float4*)(crow + n) = v;
            }
        }
}

// ---------------- layernorm -> fp16 ---------------------------------------------
__global__ void __launch_bounds__(256) ln_kernel(
    const float* __restrict__ in, __half* __restrict__ out16,
    const float* __restrict__ gam, const float* __restrict__ bet)
{
    const int row  = blockIdx.x * 8 + (threadIdx.x >> 5);
    const int lane = threadIdx.x & 31;
    const float* r = in + (size_t)row * ENCn + lane * 8;
    float4 a  = *(const float4*)r;
    float4 b4 = *(const float4*)(r + 4);
    float s  = a.x + a.y + a.z + a.w + b4.x + b4.y + b4.z + b4.w;
    float sq = a.x*a.x + a.y*a.y + a.z*a.z + a.w*a.w
             + b4.x*b4.x + b4.y*b4.y + b4.z*b4.z + b4.w*b4.w;
#pragma unroll
    for (int o = 16; o; o >>= 1) {
        s  += __shfl_xor_sync(0xFFFFFFFFu, s,  o);
        sq += __shfl_xor_sync(0xFFFFFFFFu, sq, o);
    }
    const float mu   = s * (1.f / 256.f);
    const float rstd = rsqrtf(sq * (1.f / 256.f) - mu * mu + 1e-5f);

    const float* gg = gam + lane * 8;
    const float* bb = bet + lane * 8;
    float4 ga = *(const float4*)gg, gb = *(const float4*)(gg + 4);
    float4 ba = *(const float4*)bb, bv = *(const float4*)(bb + 4);
    __half h8[8];
    h8[0] = __float2half_rn((a.x  - mu) * rstd * ga.x + ba.x);
    h8[1] = __float2half_rn((a.y  - mu) * rstd * ga.y + ba.y);
    h8[2] = __float2half_rn((a.z  - mu) * rstd * ga.z + ba.z);
    h8[3] = __float2half_rn((a.w  - mu) * rstd * ga.w + ba.w);
    h8[4] = __float2half_rn((b4.x - mu) * rstd * gb.x + bv.x);
    h8[5] = __float2half_rn((b4.y - mu) * rstd * gb.y + bv.y);
    h8[6] = __float2half_rn((b4.z - mu) * rstd * gb.z + bv.z);
    h8[7] = __float2half_rn((b4.w - mu) * rstd * gb.w + bv.w);
    *(uint4*)(out16 + (size_t)row * ENCn + lane * 8) = *(uint4*)h8;
}

// =============================================================================
// persistent LSTM v8: fine-grained per-source h arrival.
// Each warp owns 2 source CTAs: lanes 0/1 spin on their flags, then the warp
// loads those 16-unit column slices. One __syncthreads before compute.
// =============================================================================
__global__ void __launch_bounds__(512) lstm_kernel(
    const float* __restrict__ pre, const float* __restrict__ Whh,
    const float* __restrict__ h0,  const float* __restrict__ c0,
    __half* __restrict__ x16, float* __restrict__ hout, float* __restrict__ cout)
{
    extern __shared__ float sm[];
    float* sW = sm;
    float* sH = sm + 64 * WROW;
    float* sR = sm + 80 * WROW;

    const int tid  = threadIdx.x, cta = blockIdx.x;
    const int ub   = cta & 31, bb = cta >> 5;
    const int warp = tid >> 5, lane = tid & 31;
    const int ks    = warp & 7;
    const int bq_hi = warp >> 3;
    const int ul    = lane & 15;
    const int bq_lo = lane >> 4;
    const int bq    = bq_hi * 2 + bq_lo;
    const int slot  = bq * 16 + ul;
    const int e_u   = tid & 15;
    const int e_b   = (tid >> 4) & 15;
    const int eslot = (e_b >> 2) * 16 + e_u;
    const int ej    = e_b & 3;
    const int gb    = bb * 16 + e_b;
    const int gu    = ub * 16 + e_u;
    const bool epi  = (tid < 256);
    // h-load mapping: this warp loads sources {warp*2, warp*2+1}
    const int hl_b = lane & 15;
    const int hl_q = (lane >> 4) * 2;

    for (int i = tid; i < 64 * 128; i += 512) {
        const int r = i >> 7, k4 = i & 127;
        const int g = r >> 4;
        const int uu = ub * 16 + (r & 15);
        *(float4*)(sW + r * WROW + k4 * 4) =
            *(const float4*)(Whh + ((size_t)(g * HIDn + uu)) * HIDn + k4 * 4);
    }
    if (epi) g_h[0][cta * 256 + tid] = h0[cta * 256 + tid];
    float c = 0.f, hlast = 0.f;
    if (epi) c = c0[gb * HIDn + gu];
    group_sync(bb);
    // per-warp source flag bases (lanes 0,1) + own base (tid 0)
    unsigned src_base = 0, base_self = 0;
    if (lane < 2) src_base = ld_acquire(&g_flag[(bb * 32 + warp * 2 + lane) * 32]);
    if (tid == 0)  base_self = ld_acquire(&g_flag[cta * 32]);
    group_sync(bb);   // nobody publishes before all bases are read

    const float* w0r = sW + (0 * 16 + ul) * WROW + ks * 64;
    const float* w1r = sW + (1 * 16 + ul) * WROW + ks * 64;
    const float* w2r = sW + (2 * 16 + ul) * WROW + ks * 64;
    const float* w3r = sW + (3 * 16 + ul) * WROW + ks * 64;
    const float* hb0 = sH + (bq * 4 + 0) * WROW + ks * 64;
    const float* hb1 = sH + (bq * 4 + 1) * WROW + ks * 64;
    const float* hb2 = sH + (bq * 4 + 2) * WROW + ks * 64;
    const float* hb3 = sH + (bq * 4 + 3) * WROW + ks * 64;

    for (int t = 0; t < Tn; t++) {
        // per-source wait (lanes 0,1 spin on their source CTA's flag)
        if (t > 0 && lane < 2) {
            const unsigned tgt = src_base + (unsigned)t;
            while ((int)(ld_acquire(&g_flag[(bb * 32 + warp * 2 + lane) * 32]) - tgt) < 0) { }
        }
        __syncwarp();
        // load this warp's two source columns into sH
        const float* hr = g_h[t & 1] + (size_t)bb * 16 * HIDn;
#pragma unroll
        for (int s = 0; s < 2; s++) {
            const int src = warp * 2 + s;
            const float* gsrc = hr + (size_t)hl_b * HIDn + src * 16;
            float* dsrc = sH + hl_b * WROW + src * 16;
            *(float4*)(dsrc + hl_q * 4)       = *(const float4*)(gsrc + hl_q * 4);
            *(float4*)(dsrc + (hl_q + 1) * 4) = *(const float4*)(gsrc + (hl_q + 1) * 4);
        }
        float p0 = 0.f, p1 = 0.f, p2 = 0.f, p3 = 0.f;
        if (epi) {
            const float* pb = pre + ((size_t)gb * Tn + t) * G4n + gu;
            p0 = pb[0]; p1 = pb[512]; p2 = pb[1024]; p3 = pb[1536];
        }
        __syncthreads();

        unsigned long long acc[16];
#pragma unroll
        for (int i = 0; i < 16; i++) acc[i] = 0ull;

#pragma unroll 8
        for (int q = 0; q < 16; q++) {
            const int k = q * 4;
            const ulonglong2 ha  = *(const ulonglong2*)(hb0 + k);
            const ulonglong2 hbv = *(const ulonglong2*)(hb1 + k);
            const ulonglong2 hc  = *(const ulonglong2*)(hb2 + k);
            const ulonglong2 hd  = *(const ulonglong2*)(hb3 + k);
            ulonglong2 w;
            w = *(const ulonglong2*)(w0r + k);
            fma2(acc[0], w.x, ha.x);  fma2(acc[0], w.y, ha.y);
            fma2(acc[1], w.x, hbv.x); fma2(acc[1], w.y, hbv.y);
            fma2(acc[2], w.x, hc.x);  fma2(acc[2], w.y, hc.y);
            fma2(acc[3], w.x, hd.x);  fma2(acc[3], w.y, hd.y);
            w = *(const ulonglong2*)(w1r + k);
            fma2(acc[4], w.x, ha.x);  fma2(acc[4], w.y, ha.y);
            fma2(acc[5], w.x, hbv.x); fma2(acc[5], w.y, hbv.y);
            fma2(acc[6], w.x, hc.x);  fma2(acc[6], w.y, hc.y);
            fma2(acc[7], w.x, hd.x);  fma2(acc[7], w.y, hd.y);
            w = *(const ulonglong2*)(w2r + k);
            fma2(acc[8], w.x, ha.x);  fma2(acc[8], w.y, ha.y);
            fma2(acc[9], w.x, hbv.x); fma2(acc[9], w.y, hbv.y);
            fma2(acc[10], w.x, hc.x); fma2(acc[10], w.y, hc.y);
            fma2(acc[11], w.x, hd.x); fma2(acc[11], w.y, hd.y);
            w = *(const ulonglong2*)(w3r + k);
            fma2(acc[12], w.x, ha.x); fma2(acc[12], w.y, ha.y);
            fma2(acc[13], w.x, hbv.x);fma2(acc[13], w.y, hbv.y);
            fma2(acc[14], w.x, hc.x); fma2(acc[14], w.y, hc.y);
            fma2(acc[15], w.x, hd.x); fma2(acc[15], w.y, hd.y);
        }

        float* rp = sR + (ks * 64 + slot) * RSTR;
        *(float4*)(rp + 0)  = make_float4(psum(acc[0]), psum(acc[4]), psum(acc[8]),  psum(acc[12]));
        *(float4*)(rp + 4)  = make_float4(psum(acc[1]), psum(acc[5]), psum(acc[9]),  psum(acc[13]));
        *(float4*)(rp + 8)  = make_float4(psum(acc[2]), psum(acc[6]), psum(acc[10]), psum(acc[14]));
        *(float4*)(rp + 12) = make_float4(psum(acc[3]), psum(acc[7]), psum(acc[11]), psum(acc[15]));
        __syncthreads();

        if (epi) {
            float4 s = *(const float4*)(sR + (0 * 64 + eslot) * RSTR + ej * 4);
            float gi = s.x, gf = s.y, gc = s.z, go = s.w;
#pragma unroll
            for (int kk = 1; kk < 8; kk++) {
                const float4 sk = *(const float4*)(sR + (kk * 64 + eslot) * RSTR + ej * 4);
                gi += sk.x; gf += sk.y; gc += sk.z; go += sk.w;
            }
            gi += p0; gf += p1; gc += p2; go += p3;
            const float si = __fdividef(1.f, 1.f + __expf(-gi));
            const float sf = __fdividef(1.f, 1.f + __expf(-gf));
            const float so = __fdividef(1.f, 1.f + __expf(-go));
            const float tg = 2.f * __fdividef(1.f, 1.f + __expf(-2.f * gc)) - 1.f;
            c = sf * c + si * tg;
            const float tc = 2.f * __fdividef(1.f, 1.f + __expf(-2.f * c)) - 1.f;
            const float hn = so * tc;
            hlast = hn;
            x16[((size_t)gb * Tn + t) * HIDn + gu] = __float2half_rn(hn);
            g_h[(t + 1) & 1][gb * HIDn + gu] = hn;
        }
        __syncthreads();
        if (tid == 0) st_release(&g_flag[cta * 32], base_self + (unsigned)(t + 1));
    }

    if (epi) {
        hout[gb * HIDn + gu] = hlast;
        cout[gb * HIDn + gu] = c;
    }
}

// =============================================================================
extern "C" void kernel_launch(void* const* d_in, const int* in_sizes, int n_in,
                              void* d_out, int out_size)
{
    const float* x      = (const float*)d_in[0];
    const float* states = (const float*)d_in[1];
    const float* W_enc  = (const float*)d_in[2];
    const float* ln_g   = (const float*)d_in[3];
    const float* ln_b   = (const float*)d_in[4];
    const float* Wih1   = (const float*)d_in[5];
    const float* Whh1   = (const float*)d_in[6];
    const float* bih1   = (const float*)d_in[7];
    const float* bhh1   = (const float*)d_in[8];
    const float* Wih2   = (const float*)d_in[9];
    const float* Whh2   = (const float*)d_in[10];
    const float* bih2   = (const float*)d_in[11];
    const float* bhh2   = (const float*)d_in[12];
    const float* Wlin   = (const float*)d_in[13];
    const float* blin   = (const float*)d_in[14];
    const float* W_dec  = (const float*)d_in[15];

    float* out     = (float*)d_out;
    float* dstates = out + (size_t)Bn * FRAMEn * Tn;

    float *encoded, *pre;
    __half *ah, *esth, *estl, *wh, *wl, *wd;
    cudaGetSymbolAddress((void**)&encoded, g_encoded);
    cudaGetSymbolAddress((void**)&pre,     g_pre);
    cudaGetSymbolAddress((void**)&ah,      g_ah);
    cudaGetSymbolAddress((void**)&esth,    g_esth);
    cudaGetSymbolAddress((void**)&estl,    g_estl);
    cudaGetSymbolAddress((void**)&wh,      g_wh);
    cudaGetSymbolAddress((void**)&wl,      g_wl);
    cudaGetSymbolAddress((void**)&wd,      g_wd);

    static int attr_set = 0;
    const int LSTM_SMEM = (80 * WROW + 8 * 64 * RSTR) * 4;   // 206,080 B
    if (!attr_set) {
        cudaFuncSetAttribute(lstm_kernel,
                             cudaFuncAttributeMaxDynamicSharedMemorySize, LSTM_SMEM);
        attr_set = 1;
    }

    const int BH = Bn * HIDn;
    const int BT = Bn * Tn;

    // 1) encoder (fp32 SIMT)
    gemm_enc<<<dim3(ENCn / 128, Tn / 128, Bn), 256>>>(
        x, W_enc, encoded, Tn, ENCn, FRAMEn,
        (size_t)FRAMEn * Tn, (size_t)Tn * ENCn);

    // 2) layernorm -> fp16
    ln_kernel<<<BT / 8, 256>>>(encoded, ah, ln_g, ln_b);

    // 3) pre1 (fp16 2-pass HMMA)
    split_kernel<<<(G4n * ENCn / 4 + 255) / 256, 256>>>(Wih1, wh, wl, G4n * ENCn / 4);
    gemm_h<0><<<dim3(G4n / 128, BT / 128, 1), 256>>>(
        ah, wh, wl, pre, 0, bih1, bhh1, 0, 0, BT, G4n, ENCn, 0, 0);

    // 4) LSTM layer 1 (emits x1 fp16 into ah)
    lstm_kernel<<<NBLK, 512, LSTM_SMEM>>>(
        pre, Whh1, states + 0 * BH, states + 1 * BH,
        ah, dstates + 0 * BH, dstates + 1 * BH);

    // 5) pre2
    split_kernel<<<(G4n * HIDn / 4 + 255) / 256, 256>>>(Wih2, wh, wl, G4n * HIDn / 4);
    gemm_h<0><<<dim3(G4n / 128, BT / 128, 1), 256>>>(
        ah, wh, wl, pre, 0, bih2, bhh2, 0, 0, BT, G4n, HIDn, 0, 0);

    // 6) LSTM layer 2 (emits x2 fp16 into ah)
    lstm_kernel<<<NBLK, 512, LSTM_SMEM>>>(
        pre, Whh2, states + 2 * BH, states + 3 * BH,
        ah, dstates + 2 * BH, dstates + 3 * BH);

    // 7) est = sigmoid(x2 @ Wlin^T + blin) * encoded -> fp16 hi/lo
    split_kernel<<<(ENCn * HIDn / 4 + 255) / 256, 256>>>(Wlin, wh, wl, ENCn * HIDn / 4);
    gemm_h<1><<<dim3(ENCn / 128, BT / 128, 1), 256>>>(
        ah, wh, wl, 0, encoded, blin, 0, esth, estl, BT, ENCn, HIDn, 0, 0);

    // 8) decoder (fp16 2-pass, z=batch)
    cvt16_kernel<<<(FRAMEn * ENCn / 4 + 255) / 256, 256>>>(W_dec, wd, FRAMEn * ENCn / 4);
    gemm_h<2><<<dim3(Tn / 128, FRAMEn / 128, Bn), 256>>>(
        wd, esth, estl, out, 0, 0, 0, 0, 0, FRAMEn, Tn, ENCn,
        (size_t)Tn * ENCn, (size_t)FRAMEn * Tn);
}

// round 16
// speedup vs baseline: 3.4255x; 1.4443x over previous
#include <cuda_runtime.h>
#include <cuda_fp16.h>
#include <cstdint>
#include <math.h>

#define Bn     64
#define Tn     1024
#define FRAMEn 512
#define ENCn   256
#define HIDn   512
#define G4n    2048
#define NBLK   128
#define GSIZE  32
#define APAD   40
#define HROW   520   // smem row stride in halves (1040B: 16B-aligned, conflict-free)

__device__ float g_encoded[(size_t)Bn * Tn * ENCn];
__device__ float g_pre[(size_t)Bn * Tn * G4n];
__device__ __half g_hh[2][Bn * HIDn];   // h hi ping-pong
__device__ __half g_hl[2][Bn * HIDn];   // h lo ping-pong
__device__ unsigned g_cnt[4];
__device__ unsigned g_gen[4];
__device__ unsigned g_flag[NBLK * 32];
__device__ __half g_ah[(size_t)Bn * Tn * HIDn];
__device__ __half g_esth[(size_t)Bn * Tn * ENCn];
__device__ __half g_estl[(size_t)Bn * Tn * ENCn];
__device__ __half g_wh[(size_t)G4n * HIDn];
__device__ __half g_wl[(size_t)G4n * HIDn];
__device__ __half g_wd[(size_t)FRAMEn * ENCn];

// ---------------- sync primitives ---------------------------------------------
__device__ __forceinline__ unsigned atom_add_release(unsigned* p, unsigned v) {
    unsigned o; asm volatile("atom.add.release.gpu.global.u32 %0, [%1], %2;"
                             : "=r"(o) : "l"(p), "r"(v) : "memory"); return o;
}
__device__ __forceinline__ unsigned ld_acquire(const unsigned* p) {
    unsigned v; asm volatile("ld.acquire.gpu.global.u32 %0, [%1];" : "=r"(v) : "l"(p) : "memory"); return v;
}
__device__ __forceinline__ void st_relaxed(unsigned* p, unsigned v) {
    asm volatile("st.relaxed.gpu.global.u32 [%0], %1;" :: "l"(p), "r"(v) : "memory");
}
__device__ __forceinline__ void st_release(unsigned* p, unsigned v) {
    asm volatile("st.release.gpu.global.u32 [%0], %1;" :: "l"(p), "r"(v) : "memory");
}
__device__ __forceinline__ void red_add_release(unsigned* p, unsigned v) {
    asm volatile("red.add.release.gpu.global.u32 [%0], %1;" :: "l"(p), "r"(v) : "memory");
}
__device__ __forceinline__ void group_sync(int g) {
    __syncthreads();
    if (threadIdx.x == 0) {
        const unsigned gen = ld_acquire(&g_gen[g]);
        if (atom_add_release(&g_cnt[g], 1u) == GSIZE - 1) {
            st_relaxed(&g_cnt[g], 0u);
            red_add_release(&g_gen[g], 1u);
        } else {
            while (ld_acquire(&g_gen[g]) == gen) { }
        }
    }
    __syncthreads();
}

// ---------------- f32x2 helpers (encoder) ---------------------------------------
__device__ __forceinline__ void fma2(unsigned long long& d,
                                     unsigned long long a, unsigned long long b) {
    asm("fma.rn.f32x2 %0, %1, %2, %0;" : "+l"(d) : "l"(a), "l"(b));
}
__device__ __forceinline__ unsigned long long bcast2(float v) {
    unsigned long long d; asm("mov.b64 %0, {%1, %1};" : "=l"(d) : "r"(__float_as_uint(v))); return d;
}
__device__ __forceinline__ float lo2(unsigned long long v) { return __uint_as_float((unsigned)v); }
__device__ __forceinline__ float hi2(unsigned long long v) { return __uint_as_float((unsigned)(v >> 32)); }

// ---------------- mma helpers ----------------------------------------------------
__device__ __forceinline__ uint32_t smem_u32(const void* p) {
    uint32_t a;
    asm("{ .reg .u64 t; cvta.to.shared.u64 t, %1; cvt.u32.u64 %0, t; }" : "=r"(a) : "l"(p));
    return a;
}
__device__ __forceinline__ void ldmx4(uint32_t& r0, uint32_t& r1, uint32_t& r2,
                                      uint32_t& r3, uint32_t addr) {
    asm volatile("ldmatrix.sync.aligned.m8n8.x4.shared.b16 {%0,%1,%2,%3}, [%4];"
                 : "=r"(r0), "=r"(r1), "=r"(r2), "=r"(r3) : "r"(addr));
}
__device__ __forceinline__ void mma_h(float* d, const uint32_t* a, const uint32_t* b) {
    asm volatile(
        "mma.sync.aligned.m16n8k16.row.col.f32.f16.f16.f32 "
        "{%0,%1,%2,%3}, {%4,%5,%6,%7}, {%8,%9}, {%0,%1,%2,%3};"
        : "+f"(d[0]), "+f"(d[1]), "+f"(d[2]), "+f"(d[3])
        : "r"(a[0]), "r"(a[1]), "r"(a[2]), "r"(a[3]), "r"(b[0]), "r"(b[1]));
}

// =============================================================================
// fp16 2-pass HMMA GEMM (identical to R14 passing kernel)
// =============================================================================
template <int EPI>
__global__ void __launch_bounds__(256, 2) gemm_h(
    const __half* __restrict__ A, const __half* __restrict__ Bh,
    const __half* __restrict__ Bl, float* __restrict__ C,
    const float* __restrict__ E, const float* __restrict__ b1,
    const float* __restrict__ b2, __half* __restrict__ Ch, __half* __restrict__ Cl,
    int M, int N, int K, size_t sB, size_t sC)
{
    __shared__ __half sA[128 * APAD], sBh[128 * APAD], sBl[128 * APAD];

    const int tid = threadIdx.x;
    const int wid = tid >> 5, lane = tid & 31;
    const int wm = wid >> 2, wn = wid & 3;
    const int n0 = blockIdx.x * 128;
    const size_t m0 = (size_t)blockIdx.y * 128;
    const size_t z = blockIdx.z;
    const __half* Bhb = Bh + z * sB;
    const __half* Blb = Bl + z * sB;
    float* Cb = C + z * sC;

    const uint32_t bA = smem_u32(sA), bBh = smem_u32(sBh), bBl = smem_u32(sBl);
    const int lq = lane >> 3, lr = lane & 7;
    const int aRow = (lq & 1) * 8 + lr, aK = (lq >> 1) * 8;
    const int bRow = (lq >> 1) * 8 + lr, bK = (lq & 1) * 8;

    float acc[4][4][4];
#pragma unroll
    for (int i = 0; i < 4; i++)
#pragma unroll
        for (int j = 0; j < 4; j++)
#pragma unroll
            for (int k = 0; k < 4; k++) acc[i][j][k] = 0.f;

    const int nch = K >> 5;
    for (int ch = 0; ch < nch; ch++) {
        const int k0 = ch << 5;
#pragma unroll
        for (int j = 0; j < 2; j++) {
            const int idx = tid + j * 256;
            const int r = idx >> 2, s = idx & 3;
            const size_t ga = (m0 + r) * K + k0 + s * 8;
            const size_t gb = (size_t)(n0 + r) * K + k0 + s * 8;
            *(uint4*)(sA  + r * APAD + s * 8) = *(const uint4*)(A   + ga);
            *(uint4*)(sBh + r * APAD + s * 8) = *(const uint4*)(Bhb + gb);
            *(uint4*)(sBl + r * APAD + s * 8) = *(const uint4*)(Blb + gb);
        }
        __syncthreads();

#pragma unroll
        for (int ks = 0; ks < 2; ks++) {
            uint32_t af[4][4], bhf[4][2], blf[4][2];
#pragma unroll
            for (int mt = 0; mt < 4; mt++) {
                const uint32_t off =
                    (uint32_t)((wm * 64 + mt * 16 + aRow) * APAD + ks * 16 + aK) * 2;
                ldmx4(af[mt][0], af[mt][1], af[mt][2], af[mt][3], bA + off);
            }
#pragma unroll
            for (int p = 0; p < 2; p++) {
                const uint32_t off =
                    (uint32_t)((wn * 32 + p * 16 + bRow) * APAD + ks * 16 + bK) * 2;
                uint32_t r0, r1, r2, r3;
                ldmx4(r0, r1, r2, r3, bBh + off);
                bhf[p * 2][0] = r0; bhf[p * 2][1] = r1;
                bhf[p * 2 + 1][0] = r2; bhf[p * 2 + 1][1] = r3;
                ldmx4(r0, r1, r2, r3, bBl + off);
                blf[p * 2][0] = r0; blf[p * 2][1] = r1;
                blf[p * 2 + 1][0] = r2; blf[p * 2 + 1][1] = r3;
            }
#pragma unroll
            for (int mt = 0; mt < 4; mt++)
#pragma unroll
                for (int nt = 0; nt < 4; nt++) {
                    mma_h(acc[mt][nt], af[mt], bhf[nt]);
                    mma_h(acc[mt][nt], af[mt], blf[nt]);
                }
        }
        __syncthreads();
    }

    const int g = lane >> 2;
    const int cl = (lane & 3) * 2;
#pragma unroll
    for (int nt = 0; nt < 4; nt++) {
        const int n = n0 + wn * 32 + nt * 8 + cl;
        float bx = 0.f, by = 0.f;
        if (EPI == 0) { bx = b1[n] + b2[n]; by = b1[n + 1] + b2[n + 1]; }
        if (EPI == 1) { bx = b1[n]; by = b1[n + 1]; }
#pragma unroll
        for (int mt = 0; mt < 4; mt++) {
            const size_t r0 = m0 + wm * 64 + mt * 16 + g;
#pragma unroll
            for (int hrow = 0; hrow < 2; hrow++) {
                const size_t m = r0 + hrow * 8;
                float vx = acc[mt][nt][hrow * 2]     + bx;
                float vy = acc[mt][nt][hrow * 2 + 1] + by;
                if (EPI == 1) {
                    const float2 e = *(const float2*)(E + m * N + n);
                    vx = e.x / (1.f + expf(-vx));
                    vy = e.y / (1.f + expf(-vy));
                    __half hx = __float2half_rn(vx), hy = __float2half_rn(vy);
                    __half2 hv; hv.x = hx; hv.y = hy;
                    __half2 lv;
                    lv.x = __float2half_rn(vx - __half2float(hx));
                    lv.y = __float2half_rn(vy - __half2float(hy));
                    *(__half2*)(Ch + m * N + n) = hv;
                    *(__half2*)(Cl + m * N + n) = lv;
                } else {
                    *(float2*)(Cb + m * N + n) = make_float2(vx, vy);
                }
            }
        }
    }
}

// ---------------- fp32 -> fp16 hi/lo splitter -----------------------------------
__global__ void __launch_bounds__(256) split_kernel(
    const float* __restrict__ x, __half* __restrict__ hi,
    __half* __restrict__ lo, int n4)
{
    const int i = blockIdx.x * 256 + threadIdx.x;
    if (i >= n4) return;
    const float4 v = ((const float4*)x)[i];
    __half2 a, b, c, d;
    a.x = __float2half_rn(v.x); a.y = __float2half_rn(v.y);
    b.x = __float2half_rn(v.z); b.y = __float2half_rn(v.w);
    c.x = __float2half_rn(v.x - __half2float(a.x));
    c.y = __float2half_rn(v.y - __half2float(a.y));
    d.x = __float2half_rn(v.z - __half2float(b.x));
    d.y = __float2half_rn(v.w - __half2float(b.y));
    ((__half2*)hi)[i * 2] = a; ((__half2*)hi)[i * 2 + 1] = b;
    ((__half2*)lo)[i * 2] = c; ((__half2*)lo)[i * 2 + 1] = d;
}

// ---------------- fp32 -> fp16 convert -------------------------------------------
__global__ void __launch_bounds__(256) cvt16_kernel(
    const float* __restrict__ x, __half* __restrict__ y, int n4)
{
    const int i = blockIdx.x * 256 + threadIdx.x;
    if (i >= n4) return;
    const float4 v = ((const float4*)x)[i];
    __half2 a, b;
    a.x = __float2half_rn(v.x); a.y = __float2half_rn(v.y);
    b.x = __float2half_rn(v.z); b.y = __float2half_rn(v.w);
    ((__half2*)y)[i * 2] = a; ((__half2*)y)[i * 2 + 1] = b;
}

// =============================================================================
// SIMT fp32 GEMM (encoder) — identical to R14
// =============================================================================
__global__ void __launch_bounds__(256, 2) gemm_enc(
    const float* __restrict__ A, const float* __restrict__ Bm,
    float* __restrict__ C, int M, int N, int K, size_t sA, size_t sC)
{
    __shared__ float As[2][8 * 128];
    __shared__ float Bs[2][8 * 128];

    const int tid = threadIdx.x;
    const size_t z = blockIdx.z;
    const float* Ab = A + z * sA;
    float* Cb = C + z * sC;

    const int n0 = blockIdx.x * 128;
    const int m0 = blockIdx.y * 128;
    const int tx = tid & 15, ty = tid >> 4;
    const int row = tid >> 1, half = tid & 1;
    const int kr = tid >> 5, mc = tid & 31;

    unsigned long long acc2[4][8];
#pragma unroll
    for (int ip = 0; ip < 4; ip++)
#pragma unroll
        for (int j = 0; j < 8; j++) acc2[ip][j] = 0ull;

    float4 pa = *(const float4*)(Ab + (size_t)kr * M + m0 + mc * 4);
    float4 pb = *(const float4*)(Bm + (size_t)(n0 + row) * K + half * 4);
    *(float4*)&As[0][kr * 128 + mc * 4] = pa;
    Bs[0][(half * 4 + 0) * 128 + row] = pb.x;
    Bs[0][(half * 4 + 1) * 128 + row] = pb.y;
    Bs[0][(half * 4 + 2) * 128 + row] = pb.z;
    Bs[0][(half * 4 + 3) * 128 + row] = pb.w;
    __syncthreads();

    int buf = 0;
    for (int k0 = 0; k0 < K; k0 += 8) {
        const bool more = (k0 + 8 < K);
        if (more) {
            pa = *(const float4*)(Ab + (size_t)(k0 + 8 + kr) * M + m0 + mc * 4);
            pb = *(const float4*)(Bm + (size_t)(n0 + row) * K + k0 + 8 + half * 4);
        }
#pragma unroll
        for (int kk = 0; kk < 8; kk++) {
            ulonglong2 aA = *(const ulonglong2*)&As[buf][kk * 128 + ty * 8];
            ulonglong2 aB = *(const ulonglong2*)&As[buf][kk * 128 + ty * 8 + 4];
            float bv[8];
            *(float4*)(bv)     = *(const float4*)&Bs[buf][kk * 128 + tx * 8];
            *(float4*)(bv + 4) = *(const float4*)&Bs[buf][kk * 128 + tx * 8 + 4];
#pragma unroll
            for (int j = 0; j < 8; j++) {
                const unsigned long long bj = bcast2(bv[j]);
                fma2(acc2[0][j], aA.x, bj);
                fma2(acc2[1][j], aA.y, bj);
                fma2(acc2[2][j], aB.x, bj);
                fma2(acc2[3][j], aB.y, bj);
            }
        }
        if (more) {
            const int nb = buf ^ 1;
            *(float4*)&As[nb][kr * 128 + mc * 4] = pa;
            Bs[nb][(half * 4 + 0) * 128 + row] = pb.x;
            Bs[nb][(half * 4 + 1) * 128 + row] = pb.y;
            Bs[nb][(half * 4 + 2) * 128 + row] = pb.z;
            Bs[nb][(half * 4 + 3) * 128 + row] = pb.w;
            __syncthreads();
            buf = nb;
        }
    }
#pragma unroll
    for (int ip = 0; ip < 4; ip++)
#pragma unroll
        for (int hf = 0; hf < 2; hf++) {
            const int m = m0 + ty * 8 + ip * 2 + hf;
            float* crow = Cb + (size_t)m * N;
#pragma unroll
            for (int j = 0; j < 8; j += 4) {
                const int n = n0 + tx * 8 + j;
                float4 v;
                v.x = hf ? hi2(acc2[ip][j])     : lo2(acc2[ip][j]);
                v.y = hf ? hi2(acc2[ip][j + 1]) : lo2(acc2[ip][j + 1]);
                v.z = hf ? hi2(acc2[ip][j + 2]) : lo2(acc2[ip][j + 2]);
                v.w = hf ? hi2(acc2[ip][j + 3]) : lo2(acc2[ip][j + 3]);
                *(float4*)(crow + n) = v;
            }
        }
}

// ---------------- layernorm -> fp16 (identical to R14) ---------------------------
__global__ void __launch_bounds__(256) ln_kernel(
    const float* __restrict__ in, __half* __restrict__ out16,
    const float* __restrict__ gam, const float* __restrict__ bet)
{
    const int row  = blockIdx.x * 8 + (threadIdx.x >> 5);
    const int lane = threadIdx.x & 31;
    const float* r = in + (size_t)row * ENCn + lane * 8;
    float4 a  = *(const float4*)r;
    float4 b4 = *(const float4*)(r + 4);
    float s  = a.x + a.y + a.z + a.w + b4.x + b4.y + b4.z + b4.w;
    float sq = a.x*a.x + a.y*a.y + a.z*a.z + a.w*a.w
             + b4.x*b4.x + b4.y*b4.y + b4.z*b4.z + b4.w*b4.w;
#pragma unroll
    for (int o = 16; o; o >>= 1) {
        s  += __shfl_xor_sync(0xFFFFFFFFu, s,  o);
        sq += __shfl_xor_sync(0xFFFFFFFFu, sq, o);
    }
    const float mu   = s * (1.f / 256.f);
    const float rstd = rsqrtf(sq * (1.f / 256.f) - mu * mu + 1e-5f);

    const float* gg = gam + lane * 8;
    const float* bb = bet + lane * 8;
    float4 ga = *(const float4*)gg, gb = *(const float4*)(gg + 4);
    float4 ba = *(const float4*)bb, bv = *(const float4*)(bb + 4);
    __half h8[8];
    h8[0] = __float2half_rn((a.x  - mu) * rstd * ga.x + ba.x);
    h8[1] = __float2half_rn((a.y  - mu) * rstd * ga.y + ba.y);
    h8[2] = __float2half_rn((a.z  - mu) * rstd * ga.z + ba.z);
    h8[3] = __float2half_rn((a.w  - mu) * rstd * ga.w + ba.w);
    h8[4] = __float2half_rn((b4.x - mu) * rstd * gb.x + bv.x);
    h8[5] = __float2half_rn((b4.y - mu) * rstd * gb.y + bv.y);
    h8[6] = __float2half_rn((b4.z - mu) * rstd * gb.z + bv.z);
    h8[7] = __float2half_rn((b4.w - mu) * rstd * gb.w + bv.w);
    *(uint4*)(out16 + (size_t)row * ENCn + lane * 8) = *(uint4*)h8;
}

// =============================================================================
// persistent LSTM v9: HMMA recurrence (3-pass fp16 split), per-source arrival.
// Warp = (gate wm 0..3) x (k-quarter ks 0..3). Whh hi/lo fp16 resident in SMEM.
// Staging [ks*4+g][batch][unit(20)] fp32; epilogue 256 threads, one (b,u) each.
// =============================================================================
__global__ void __launch_bounds__(512) lstm_kernel(
    const float* __restrict__ pre,
    const __half* __restrict__ WhhH, const __half* __restrict__ WhhL,
    const float* __restrict__ h0,  const float* __restrict__ c0,
    __half* __restrict__ x16, float* __restrict__ hout, float* __restrict__ cout)
{
    extern __shared__ char smx[];
    __half* sWh = (__half*)smx;              // 64 x HROW
    __half* sWl = sWh + 64 * HROW;
    __half* sHh = sWl + 64 * HROW;           // 16 x HROW
    __half* sHl = sHh + 16 * HROW;
    float*  sR  = (float*)(sHl + 16 * HROW); // [16][16][20]

    const int tid  = threadIdx.x, cta = blockIdx.x;
    const int ub   = cta & 31, bb = cta >> 5;
    const int warp = tid >> 5, lane = tid & 31;
    const int ks = warp & 3, wm = warp >> 2;
    const int lq = lane >> 3, lr = lane & 7;
    const int aRow = (lq & 1) * 8 + lr, aK = (lq >> 1) * 8;
    const int bRow = (lq >> 1) * 8 + lr, bK = (lq & 1) * 8;
    const int e_u = tid & 15, e_b = (tid >> 4) & 15;
    const bool epi = (tid < 256);
    const int gu = ub * 16 + e_u, gb = bb * 16 + e_b;
    const int hl_b = lane & 15, hl_s = lane >> 4;

    const uint32_t bWh = smem_u32(sWh), bWl = smem_u32(sWl);
    const uint32_t bHh = smem_u32(sHh), bHl = smem_u32(sHl);

    // load Whh hi/lo slice: smem row r = g*16+ul -> global row g*512 + ub*16 + ul
    for (int i = tid; i < 64 * 64; i += 512) {
        const int r = i >> 6, kq = i & 63;
        const int g = r >> 4;
        const size_t grow = (size_t)(g * HIDn + ub * 16 + (r & 15)) * HIDn + kq * 8;
        *(uint4*)(sWh + r * HROW + kq * 8) = *(const uint4*)(WhhH + grow);
        *(uint4*)(sWl + r * HROW + kq * 8) = *(const uint4*)(WhhL + grow);
    }
    // init h fp16 hi/lo + c
    float c = 0.f, hlast = 0.f;
    if (epi) {
        const float h0v = h0[gb * HIDn + gu];
        const __half hh = __float2half_rn(h0v);
        g_hh[0][gb * HIDn + gu] = hh;
        g_hl[0][gb * HIDn + gu] = __float2half_rn(h0v - __half2float(hh));
        c = c0[gb * HIDn + gu];
    }
    group_sync(bb);
    unsigned src_base = 0, base_self = 0;
    if (lane < 2) src_base = ld_acquire(&g_flag[(bb * 32 + warp * 2 + lane) * 32]);
    if (tid == 0)  base_self = ld_acquire(&g_flag[cta * 32]);
    group_sync(bb);

    for (int t = 0; t < Tn; t++) {
        if (t > 0 && lane < 2) {
            const unsigned tgt = src_base + (unsigned)t;
            while ((int)(ld_acquire(&g_flag[(bb * 32 + warp * 2 + lane) * 32]) - tgt) < 0) { }
        }
        __syncwarp();
        // load this warp's two source k-column slices (units src*16..+16)
        {
            const int src = warp * 2 + hl_s;
            const size_t gidx = (size_t)(bb * 16 + hl_b) * HIDn + src * 16;
            const int sidx = hl_b * HROW + src * 16;
            *(uint4*)(sHh + sidx)     = *(const uint4*)(g_hh[t & 1] + gidx);
            *(uint4*)(sHh + sidx + 8) = *(const uint4*)(g_hh[t & 1] + gidx + 8);
            *(uint4*)(sHl + sidx)     = *(const uint4*)(g_hl[t & 1] + gidx);
            *(uint4*)(sHl + sidx + 8) = *(const uint4*)(g_hl[t & 1] + gidx + 8);
        }
        float p0 = 0.f, p1 = 0.f, p2 = 0.f, p3 = 0.f;
        if (epi) {
            const float* pb = pre + ((size_t)gb * Tn + t) * G4n + gu;
            p0 = pb[0]; p1 = pb[512]; p2 = pb[1024]; p3 = pb[1536];
        }
        __syncthreads();

        float acc[2][4];
#pragma unroll
        for (int i = 0; i < 2; i++)
#pragma unroll
            for (int j = 0; j < 4; j++) acc[i][j] = 0.f;

#pragma unroll
        for (int kq = 0; kq < 8; kq++) {
            const int kk = ks * 128 + kq * 16;
            uint32_t ah4[4], al4[4], bh4[2][2], bl4[2][2];
            const uint32_t aoff = (uint32_t)((wm * 16 + aRow) * HROW + kk + aK) * 2;
            ldmx4(ah4[0], ah4[1], ah4[2], ah4[3], bWh + aoff);
            ldmx4(al4[0], al4[1], al4[2], al4[3], bWl + aoff);
            const uint32_t boff = (uint32_t)(bRow * HROW + kk + bK) * 2;
            uint32_t r0, r1, r2, r3;
            ldmx4(r0, r1, r2, r3, bHh + boff);
            bh4[0][0] = r0; bh4[0][1] = r1; bh4[1][0] = r2; bh4[1][1] = r3;
            ldmx4(r0, r1, r2, r3, bHl + boff);
            bl4[0][0] = r0; bl4[0][1] = r1; bl4[1][0] = r2; bl4[1][1] = r3;
#pragma unroll
            for (int nf = 0; nf < 2; nf++) {
                mma_h(acc[nf], ah4, bh4[nf]);
                mma_h(acc[nf], ah4, bl4[nf]);
                mma_h(acc[nf], al4, bh4[nf]);
            }
        }

        // staging write: sR[(ks*4+wm)*320 + batch*20 + unit]
        {
            const int g = lane >> 2, cl = (lane & 3) * 2;
            float* base = sR + (ks * 4 + wm) * 320;
#pragma unroll
            for (int nf = 0; nf < 2; nf++)
#pragma unroll
                for (int hr = 0; hr < 2; hr++) {
                    const int u = g + hr * 8;
                    const int b0 = nf * 8 + cl;
                    base[b0 * 20 + u]       = acc[nf][hr * 2];
                    base[(b0 + 1) * 20 + u] = acc[nf][hr * 2 + 1];
                }
        }
        __syncthreads();

        if (epi) {
            float gi = p0, gf = p1, gc = p2, go = p3;
#pragma unroll
            for (int k2 = 0; k2 < 4; k2++) {
                gi += sR[((k2 * 4 + 0) * 16 + e_b) * 20 + e_u];
                gf += sR[((k2 * 4 + 1) * 16 + e_b) * 20 + e_u];
                gc += sR[((k2 * 4 + 2) * 16 + e_b) * 20 + e_u];
                go += sR[((k2 * 4 + 3) * 16 + e_b) * 20 + e_u];
            }
            const float si = __fdividef(1.f, 1.f + __expf(-gi));
            const float sf = __fdividef(1.f, 1.f + __expf(-gf));
            const float so = __fdividef(1.f, 1.f + __expf(-go));
            const float tg = 2.f * __fdividef(1.f, 1.f + __expf(-2.f * gc)) - 1.f;
            c = sf * c + si * tg;
            const float tc = 2.f * __fdividef(1.f, 1.f + __expf(-2.f * c)) - 1.f;
            const float hn = so * tc;
            hlast = hn;
            x16[((size_t)gb * Tn + t) * HIDn + gu] = __float2half_rn(hn);
            const __half hh = __float2half_rn(hn);
            g_hh[(t + 1) & 1][gb * HIDn + gu] = hh;
            g_hl[(t + 1) & 1][gb * HIDn + gu] =
                __float2half_rn(hn - __half2float(hh));
        }
        __syncthreads();
        if (tid == 0) st_release(&g_flag[cta * 32], base_self + (unsigned)(t + 1));
    }

    if (epi) {
        hout[gb * HIDn + gu] = hlast;
        cout[gb * HIDn + gu] = c;
    }
}

// =============================================================================
extern "C" void kernel_launch(void* const* d_in, const int* in_sizes, int n_in,
                              void* d_out, int out_size)
{
    const float* x      = (const float*)d_in[0];
    const float* states = (const float*)d_in[1];
    const float* W_enc  = (const float*)d_in[2];
    const float* ln_g   = (const float*)d_in[3];
    const float* ln_b   = (const float*)d_in[4];
    const float* Wih1   = (const float*)d_in[5];
    const float* Whh1   = (const float*)d_in[6];
    const float* bih1   = (const float*)d_in[7];
    const float* bhh1   = (const float*)d_in[8];
    const float* Wih2   = (const float*)d_in[9];
    const float* Whh2   = (const float*)d_in[10];
    const float* bih2   = (const float*)d_in[11];
    const float* bhh2   = (const float*)d_in[12];
    const float* Wlin   = (const float*)d_in[13];
    const float* blin   = (const float*)d_in[14];
    const float* W_dec  = (const float*)d_in[15];

    float* out     = (float*)d_out;
    float* dstates = out + (size_t)Bn * FRAMEn * Tn;

    float *encoded, *pre;
    __half *ah, *esth, *estl, *wh, *wl, *wd;
    cudaGetSymbolAddress((void**)&encoded, g_encoded);
    cudaGetSymbolAddress((void**)&pre,     g_pre);
    cudaGetSymbolAddress((void**)&ah,      g_ah);
    cudaGetSymbolAddress((void**)&esth,    g_esth);
    cudaGetSymbolAddress((void**)&estl,    g_estl);
    cudaGetSymbolAddress((void**)&wh,      g_wh);
    cudaGetSymbolAddress((void**)&wl,      g_wl);
    cudaGetSymbolAddress((void**)&wd,      g_wd);

    static int attr_set = 0;
    const int LSTM_SMEM = (64 * HROW * 2 + 16 * HROW * 2) * 2 + 16 * 320 * 4; // 186,880 B
    if (!attr_set) {
        cudaFuncSetAttribute(lstm_kernel,
                             cudaFuncAttributeMaxDynamicSharedMemorySize, LSTM_SMEM);
        attr_set = 1;
    }

    const int BH = Bn * HIDn;
    const int BT = Bn * Tn;

    // 1) encoder (fp32 SIMT)
    gemm_enc<<<dim3(ENCn / 128, Tn / 128, Bn), 256>>>(
        x, W_enc, encoded, Tn, ENCn, FRAMEn,
        (size_t)FRAMEn * Tn, (size_t)Tn * ENCn);

    // 2) layernorm -> fp16
    ln_kernel<<<BT / 8, 256>>>(encoded, ah, ln_g, ln_b);

    // 3) pre1
    split_kernel<<<(G4n * ENCn / 4 + 255) / 256, 256>>>(Wih1, wh, wl, G4n * ENCn / 4);
    gemm_h<0><<<dim3(G4n / 128, BT / 128, 1), 256>>>(
        ah, wh, wl, pre, 0, bih1, bhh1, 0, 0, BT, G4n, ENCn, 0, 0);

    // 4) LSTM layer 1 (Whh1 split into wh/wl, reused after pre1 done)
    split_kernel<<<(G4n * HIDn / 4 + 255) / 256, 256>>>(Whh1, wh, wl, G4n * HIDn / 4);
    lstm_kernel<<<NBLK, 512, LSTM_SMEM>>>(
        pre, wh, wl, states + 0 * BH, states + 1 * BH,
        ah, dstates + 0 * BH, dstates + 1 * BH);

    // 5) pre2
    split_kernel<<<(G4n * HIDn / 4 + 255) / 256, 256>>>(Wih2, wh, wl, G4n * HIDn / 4);
    gemm_h<0><<<dim3(G4n / 128, BT / 128, 1), 256>>>(
        ah, wh, wl, pre, 0, bih2, bhh2, 0, 0, BT, G4n, HIDn, 0, 0);

    // 6) LSTM layer 2
    split_kernel<<<(G4n * HIDn / 4 + 255) / 256, 256>>>(Whh2, wh, wl, G4n * HIDn / 4);
    lstm_kernel<<<NBLK, 512, LSTM_SMEM>>>(
        pre, wh, wl, states + 2 * BH, states + 3 * BH,
        ah, dstates + 2 * BH, dstates + 3 * BH);

    // 7) est = sigmoid(x2 @ Wlin^T + blin) * encoded -> fp16 hi/lo
    split_kernel<<<(ENCn * HIDn / 4 + 255) / 256, 256>>>(Wlin, wh, wl, ENCn * HIDn / 4);
    gemm_h<1><<<dim3(ENCn / 128, BT / 128, 1), 256>>>(
        ah, wh, wl, 0, encoded, blin, 0, esth, estl, BT, ENCn, HIDn, 0, 0);

    // 8) decoder (fp16 2-pass, z=batch)
    cvt16_kernel<<<(FRAMEn * ENCn / 4 + 255) / 256, 256>>>(W_dec, wd, FRAMEn * ENCn / 4);
    gemm_h<2><<<dim3(Tn / 128, FRAMEn / 128, Bn), 256>>>(
        wd, esth, estl, out, 0, 0, 0, 0, 0, FRAMEn, Tn, ENCn,
        (size_t)Tn * ENCn, (size_t)FRAMEn * Tn);
}

// round 17
// speedup vs baseline: 4.1301x; 1.2057x over previous
#include <cuda_runtime.h>
#include <cuda_fp16.h>
#include <cstdint>
#include <math.h>

#define Bn     64
#define Tn     1024
#define FRAMEn 512
#define ENCn   256
#define HIDn   512
#define G4n    2048
#define NBLK   128
#define GSIZE  32
#define APAD   40
#define HROW   520

__device__ float g_encoded[(size_t)Bn * Tn * ENCn];
__device__ float g_pre[(size_t)Bn * Tn * G4n];
__device__ __half g_hh[2][Bn * HIDn];   // h fp16 ping-pong
__device__ unsigned g_cnt[4];
__device__ unsigned g_gen[4];
__device__ unsigned g_flag[NBLK * 32];
__device__ __half g_ah[(size_t)Bn * Tn * HIDn];   // xT, then ln/x1/x2
__device__ __half g_esth[(size_t)Bn * Tn * ENCn];
__device__ __half g_estl[(size_t)Bn * Tn * ENCn];
__device__ __half g_wh[(size_t)G4n * HIDn];
__device__ __half g_wl[(size_t)G4n * HIDn];
__device__ __half g_wd[(size_t)FRAMEn * ENCn];

// ---------------- sync primitives ---------------------------------------------
__device__ __forceinline__ unsigned atom_add_release(unsigned* p, unsigned v) {
    unsigned o; asm volatile("atom.add.release.gpu.global.u32 %0, [%1], %2;"
                             : "=r"(o) : "l"(p), "r"(v) : "memory"); return o;
}
__device__ __forceinline__ unsigned ld_acquire(const unsigned* p) {
    unsigned v; asm volatile("ld.acquire.gpu.global.u32 %0, [%1];" : "=r"(v) : "l"(p) : "memory"); return v;
}
__device__ __forceinline__ void st_relaxed(unsigned* p, unsigned v) {
    asm volatile("st.relaxed.gpu.global.u32 [%0], %1;" :: "l"(p), "r"(v) : "memory");
}
__device__ __forceinline__ void st_release(unsigned* p, unsigned v) {
    asm volatile("st.release.gpu.global.u32 [%0], %1;" :: "l"(p), "r"(v) : "memory");
}
__device__ __forceinline__ void red_add_release(unsigned* p, unsigned v) {
    asm volatile("red.add.release.gpu.global.u32 [%0], %1;" :: "l"(p), "r"(v) : "memory");
}
__device__ __forceinline__ void group_sync(int g) {
    __syncthreads();
    if (threadIdx.x == 0) {
        const unsigned gen = ld_acquire(&g_gen[g]);
        if (atom_add_release(&g_cnt[g], 1u) == GSIZE - 1) {
            st_relaxed(&g_cnt[g], 0u);
            red_add_release(&g_gen[g], 1u);
        } else {
            while (ld_acquire(&g_gen[g]) == gen) { }
        }
    }
    __syncthreads();
}

// ---------------- mma helpers ----------------------------------------------------
__device__ __forceinline__ uint32_t smem_u32(const void* p) {
    uint32_t a;
    asm("{ .reg .u64 t; cvta.to.shared.u64 t, %1; cvt.u32.u64 %0, t; }" : "=r"(a) : "l"(p));
    return a;
}
__device__ __forceinline__ void ldmx4(uint32_t& r0, uint32_t& r1, uint32_t& r2,
                                      uint32_t& r3, uint32_t addr) {
    asm volatile("ldmatrix.sync.aligned.m8n8.x4.shared.b16 {%0,%1,%2,%3}, [%4];"
                 : "=r"(r0), "=r"(r1), "=r"(r2), "=r"(r3) : "r"(addr));
}
__device__ __forceinline__ void mma_h(float* d, const uint32_t* a, const uint32_t* b) {
    asm volatile(
        "mma.sync.aligned.m16n8k16.row.col.f32.f16.f16.f32 "
        "{%0,%1,%2,%3}, {%4,%5,%6,%7}, {%8,%9}, {%0,%1,%2,%3};"
        : "+f"(d[0]), "+f"(d[1]), "+f"(d[2]), "+f"(d[3])
        : "r"(a[0]), "r"(a[1]), "r"(a[2]), "r"(a[3]), "r"(b[0]), "r"(b[1]));
}

// =============================================================================
// fp16 2-pass HMMA GEMM: C[M,N] = A[M,K] @ (Bh+Bl)[N,K]^T
//   EPI 0: C = acc + b1[n] + b2[n]
//   EPI 1: v = sigmoid(acc + b1[n]) * E[m,n]; emit fp16 hi/lo -> Ch/Cl
//   EPI 2: C = acc  (z-batched via sA/sB/sC strides)
// Tile 128x128, BK=32, 256 threads (8 warps 64x32), 2 CTAs/SM.
// =============================================================================
template <int EPI>
__global__ void __launch_bounds__(256, 2) gemm_h(
    const __half* __restrict__ A, const __half* __restrict__ Bh,
    const __half* __restrict__ Bl, float* __restrict__ C,
    const float* __restrict__ E, const float* __restrict__ b1,
    const float* __restrict__ b2, __half* __restrict__ Ch, __half* __restrict__ Cl,
    int M, int N, int K, size_t sA, size_t sB, size_t sC)
{
    __shared__ __half sA_s[128 * APAD], sBh[128 * APAD], sBl[128 * APAD];

    const int tid = threadIdx.x;
    const int wid = tid >> 5, lane = tid & 31;
    const int wm = wid >> 2, wn = wid & 3;
    const int n0 = blockIdx.x * 128;
    const size_t m0 = (size_t)blockIdx.y * 128;
    const size_t z = blockIdx.z;
    const __half* Ab  = A + z * sA;
    const __half* Bhb = Bh + z * sB;
    const __half* Blb = Bl + z * sB;
    float* Cb = C + z * sC;

    const uint32_t bA = smem_u32(sA_s), bBh = smem_u32(sBh), bBl = smem_u32(sBl);
    const int lq = lane >> 3, lr = lane & 7;
    const int aRow = (lq & 1) * 8 + lr, aK = (lq >> 1) * 8;
    const int bRow = (lq >> 1) * 8 + lr, bK = (lq & 1) * 8;

    float acc[4][4][4];
#pragma unroll
    for (int i = 0; i < 4; i++)
#pragma unroll
        for (int j = 0; j < 4; j++)
#pragma unroll
            for (int k = 0; k < 4; k++) acc[i][j][k] = 0.f;

    const int nch = K >> 5;
    for (int ch = 0; ch < nch; ch++) {
        const int k0 = ch << 5;
#pragma unroll
        for (int j = 0; j < 2; j++) {
            const int idx = tid + j * 256;
            const int r = idx >> 2, s = idx & 3;
            const size_t ga = (m0 + r) * K + k0 + s * 8;
            const size_t gb = (size_t)(n0 + r) * K + k0 + s * 8;
            *(uint4*)(sA_s + r * APAD + s * 8) = *(const uint4*)(Ab  + ga);
            *(uint4*)(sBh  + r * APAD + s * 8) = *(const uint4*)(Bhb + gb);
            *(uint4*)(sBl  + r * APAD + s * 8) = *(const uint4*)(Blb + gb);
        }
        __syncthreads();

#pragma unroll
        for (int ks = 0; ks < 2; ks++) {
            uint32_t af[4][4], bhf[4][2], blf[4][2];
#pragma unroll
            for (int mt = 0; mt < 4; mt++) {
                const uint32_t off =
                    (uint32_t)((wm * 64 + mt * 16 + aRow) * APAD + ks * 16 + aK) * 2;
                ldmx4(af[mt][0], af[mt][1], af[mt][2], af[mt][3], bA + off);
            }
#pragma unroll
            for (int p = 0; p < 2; p++) {
                const uint32_t off =
                    (uint32_t)((wn * 32 + p * 16 + bRow) * APAD + ks * 16 + bK) * 2;
                uint32_t r0, r1, r2, r3;
                ldmx4(r0, r1, r2, r3, bBh + off);
                bhf[p * 2][0] = r0; bhf[p * 2][1] = r1;
                bhf[p * 2 + 1][0] = r2; bhf[p * 2 + 1][1] = r3;
                ldmx4(r0, r1, r2, r3, bBl + off);
                blf[p * 2][0] = r0; blf[p * 2][1] = r1;
                blf[p * 2 + 1][0] = r2; blf[p * 2 + 1][1] = r3;
            }
#pragma unroll
            for (int mt = 0; mt < 4; mt++)
#pragma unroll
                for (int nt = 0; nt < 4; nt++) {
                    mma_h(acc[mt][nt], af[mt], bhf[nt]);
                    mma_h(acc[mt][nt], af[mt], blf[nt]);
                }
        }
        __syncthreads();
    }

    const int g = lane >> 2;
    const int cl = (lane & 3) * 2;
#pragma unroll
    for (int nt = 0; nt < 4; nt++) {
        const int n = n0 + wn * 32 + nt * 8 + cl;
        float bx = 0.f, by = 0.f;
        if (EPI == 0) { bx = b1[n] + b2[n]; by = b1[n + 1] + b2[n + 1]; }
        if (EPI == 1) { bx = b1[n]; by = b1[n + 1]; }
#pragma unroll
        for (int mt = 0; mt < 4; mt++) {
            const size_t r0 = m0 + wm * 64 + mt * 16 + g;
#pragma unroll
            for (int hrow = 0; hrow < 2; hrow++) {
                const size_t m = r0 + hrow * 8;
                float vx = acc[mt][nt][hrow * 2]     + bx;
                float vy = acc[mt][nt][hrow * 2 + 1] + by;
                if (EPI == 1) {
                    const float2 e = *(const float2*)(E + m * N + n);
                    vx = e.x / (1.f + expf(-vx));
                    vy = e.y / (1.f + expf(-vy));
                    __half hx = __float2half_rn(vx), hy = __float2half_rn(vy);
                    __half2 hv; hv.x = hx; hv.y = hy;
                    __half2 lv;
                    lv.x = __float2half_rn(vx - __half2float(hx));
                    lv.y = __float2half_rn(vy - __half2float(hy));
                    *(__half2*)(Ch + m * N + n) = hv;
                    *(__half2*)(Cl + m * N + n) = lv;
                } else {
                    *(float2*)(Cb + m * N + n) = make_float2(vx, vy);
                }
            }
        }
    }
}

// ---------------- fp32 -> fp16 hi/lo splitter -----------------------------------
__global__ void __launch_bounds__(256) split_kernel(
    const float* __restrict__ x, __half* __restrict__ hi,
    __half* __restrict__ lo, int n4)
{
    const int i = blockIdx.x * 256 + threadIdx.x;
    if (i >= n4) return;
    const float4 v = ((const float4*)x)[i];
    __half2 a, b, c, d;
    a.x = __float2half_rn(v.x); a.y = __float2half_rn(v.y);
    b.x = __float2half_rn(v.z); b.y = __float2half_rn(v.w);
    c.x = __float2half_rn(v.x - __half2float(a.x));
    c.y = __float2half_rn(v.y - __half2float(a.y));
    d.x = __float2half_rn(v.z - __half2float(b.x));
    d.y = __float2half_rn(v.w - __half2float(b.y));
    ((__half2*)hi)[i * 2] = a; ((__half2*)hi)[i * 2 + 1] = b;
    ((__half2*)lo)[i * 2] = c; ((__half2*)lo)[i * 2 + 1] = d;
}

// ---------------- fp32 -> fp16 convert -------------------------------------------
__global__ void __launch_bounds__(256) cvt16_kernel(
    const float* __restrict__ x, __half* __restrict__ y, int n4)
{
    const int i = blockIdx.x * 256 + threadIdx.x;
    if (i >= n4) return;
    const float4 v = ((const float4*)x)[i];
    __half2 a, b;
    a.x = __float2half_rn(v.x); a.y = __float2half_rn(v.y);
    b.x = __float2half_rn(v.z); b.y = __float2half_rn(v.w);
    ((__half2*)y)[i * 2] = a; ((__half2*)y)[i * 2 + 1] = b;
}

// ---------------- transpose+convert: x[b,c,t] -> xT[b,t,c] fp16 -------------------
__global__ void __launch_bounds__(256) tx16_kernel(
    const float* __restrict__ x, __half* __restrict__ y)
{
    __shared__ float tile[32][33];
    const int b  = blockIdx.z;
    const int c0 = blockIdx.y * 32;
    const int t0 = blockIdx.x * 32;
    const int tx = threadIdx.x & 31, ty = threadIdx.x >> 5;   // 32 x 8
#pragma unroll
    for (int i = 0; i < 32; i += 8)
        tile[ty + i][tx] = x[((size_t)b * FRAMEn + c0 + ty + i) * Tn + t0 + tx];
    __syncthreads();
#pragma unroll
    for (int i = 0; i < 32; i += 8)
        y[((size_t)b * Tn + t0 + ty + i) * FRAMEn + c0 + tx] =
            __float2half_rn(tile[tx][ty + i]);
}

// ---------------- layernorm -> fp16 ---------------------------------------------
__global__ void __launch_bounds__(256) ln_kernel(
    const float* __restrict__ in, __half* __restrict__ out16,
    const float* __restrict__ gam, const float* __restrict__ bet)
{
    const int row  = blockIdx.x * 8 + (threadIdx.x >> 5);
    const int lane = threadIdx.x & 31;
    const float* r = in + (size_t)row * ENCn + lane * 8;
    float4 a  = *(const float4*)r;
    float4 b4 = *(const float4*)(r + 4);
    float s  = a.x + a.y + a.z + a.w + b4.x + b4.y + b4.z + b4.w;
    float sq = a.x*a.x + a.y*a.y + a.z*a.z + a.w*a.w
             + b4.x*b4.x + b4.y*b4.y + b4.z*b4.z + b4.w*b4.w;
#pragma unroll
    for (int o = 16; o; o >>= 1) {
        s  += __shfl_xor_sync(0xFFFFFFFFu, s,  o);
        sq += __shfl_xor_sync(0xFFFFFFFFu, sq, o);
    }
    const float mu   = s * (1.f / 256.f);
    const float rstd = rsqrtf(sq * (1.f / 256.f) - mu * mu + 1e-5f);

    const float* gg = gam + lane * 8;
    const float* bb = bet + lane * 8;
    float4 ga = *(const float4*)gg, gb = *(const float4*)(gg + 4);
    float4 ba = *(const float4*)bb, bv = *(const float4*)(bb + 4);
    __half h8[8];
    h8[0] = __float2half_rn((a.x  - mu) * rstd * ga.x + ba.x);
    h8[1] = __float2half_rn((a.y  - mu) * rstd * ga.y + ba.y);
    h8[2] = __float2half_rn((a.z  - mu) * rstd * ga.z + ba.z);
    h8[3] = __float2half_rn((a.w  - mu) * rstd * ga.w + ba.w);
    h8[4] = __float2half_rn((b4.x - mu) * rstd * gb.x + bv.x);
    h8[5] = __float2half_rn((b4.y - mu) * rstd * gb.y + bv.y);
    h8[6] = __float2half_rn((b4.z - mu) * rstd * gb.z + bv.z);
    h8[7] = __float2half_rn((b4.w - mu) * rstd * gb.w + bv.w);
    *(uint4*)(out16 + (size_t)row * ENCn + lane * 8) = *(uint4*)h8;
}

// =============================================================================
// persistent LSTM v10: HMMA recurrence, 2-pass (W hi/lo split, h single fp16).
// Warp = (gate wm) x (k-quarter ks). Per-source arrival barrier.
// =============================================================================
__global__ void __launch_bounds__(512) lstm_kernel(
    const float* __restrict__ pre,
    const __half* __restrict__ WhhH, const __half* __restrict__ WhhL,
    const float* __restrict__ h0,  const float* __restrict__ c0,
    __half* __restrict__ x16, float* __restrict__ hout, float* __restrict__ cout)
{
    extern __shared__ char smx[];
    __half* sWh = (__half*)smx;              // 64 x HROW
    __half* sWl = sWh + 64 * HROW;
    __half* sHh = sWl + 64 * HROW;           // 16 x HROW
    float*  sR  = (float*)(sHh + 16 * HROW); // [16][16][20]

    const int tid  = threadIdx.x, cta = blockIdx.x;
    const int ub   = cta & 31, bb = cta >> 5;
    const int warp = tid >> 5, lane = tid & 31;
    const int ks = warp & 3, wm = warp >> 2;
    const int lq = lane >> 3, lr = lane & 7;
    const int aRow = (lq & 1) * 8 + lr, aK = (lq >> 1) * 8;
    const int bRow = (lq >> 1) * 8 + lr, bK = (lq & 1) * 8;
    const int e_u = tid & 15, e_b = (tid >> 4) & 15;
    const bool epi = (tid < 256);
    const int gu = ub * 16 + e_u, gb = bb * 16 + e_b;
    const int hl_b = lane & 15, hl_s = lane >> 4;

    const uint32_t bWh = smem_u32(sWh), bWl = smem_u32(sWl);
    const uint32_t bHh = smem_u32(sHh);

    for (int i = tid; i < 64 * 64; i += 512) {
        const int r = i >> 6, kq = i & 63;
        const int g = r >> 4;
        const size_t grow = (size_t)(g * HIDn + ub * 16 + (r & 15)) * HIDn + kq * 8;
        *(uint4*)(sWh + r * HROW + kq * 8) = *(const uint4*)(WhhH + grow);
        *(uint4*)(sWl + r * HROW + kq * 8) = *(const uint4*)(WhhL + grow);
    }
    float c = 0.f, hlast = 0.f;
    if (epi) {
        const float h0v = h0[gb * HIDn + gu];
        g_hh[0][gb * HIDn + gu] = __float2half_rn(h0v);
        c = c0[gb * HIDn + gu];
    }
    group_sync(bb);
    unsigned src_base = 0, base_self = 0;
    if (lane < 2) src_base = ld_acquire(&g_flag[(bb * 32 + warp * 2 + lane) * 32]);
    if (tid == 0)  base_self = ld_acquire(&g_flag[cta * 32]);
    group_sync(bb);

    for (int t = 0; t < Tn; t++) {
        if (t > 0 && lane < 2) {
            const unsigned tgt = src_base + (unsigned)t;
            while ((int)(ld_acquire(&g_flag[(bb * 32 + warp * 2 + lane) * 32]) - tgt) < 0) { }
        }
        __syncwarp();
        {
            const int src = warp * 2 + hl_s;
            const size_t gidx = (size_t)(bb * 16 + hl_b) * HIDn + src * 16;
            const int sidx = hl_b * HROW + src * 16;
            *(uint4*)(sHh + sidx)     = *(const uint4*)(g_hh[t & 1] + gidx);
            *(uint4*)(sHh + sidx + 8) = *(const uint4*)(g_hh[t & 1] + gidx + 8);
        }
        float p0 = 0.f, p1 = 0.f, p2 = 0.f, p3 = 0.f;
        if (epi) {
            const float* pb = pre + ((size_t)gb * Tn + t) * G4n + gu;
            p0 = pb[0]; p1 = pb[512]; p2 = pb[1024]; p3 = pb[1536];
        }
        __syncthreads();

        float acc[2][4];
#pragma unroll
        for (int i = 0; i < 2; i++)
#pragma unroll
            for (int j = 0; j < 4; j++) acc[i][j] = 0.f;

#pragma unroll
        for (int kq = 0; kq < 8; kq++) {
            const int kk = ks * 128 + kq * 16;
            uint32_t ah4[4], al4[4], bh4[2][2];
            const uint32_t aoff = (uint32_t)((wm * 16 + aRow) * HROW + kk + aK) * 2;
            ldmx4(ah4[0], ah4[1], ah4[2], ah4[3], bWh + aoff);
            ldmx4(al4[0], al4[1], al4[2], al4[3], bWl + aoff);
            const uint32_t boff = (uint32_t)(bRow * HROW + kk + bK) * 2;
            uint32_t r0, r1, r2, r3;
            ldmx4(r0, r1, r2, r3, bHh + boff);
            bh4[0][0] = r0; bh4[0][1] = r1; bh4[1][0] = r2; bh4[1][1] = r3;
#pragma unroll
            for (int nf = 0; nf < 2; nf++) {
                mma_h(acc[nf], ah4, bh4[nf]);
                mma_h(acc[nf], al4, bh4[nf]);
            }
        }

        {
            const int g = lane >> 2, cl = (lane & 3) * 2;
            float* base = sR + (ks * 4 + wm) * 320;
#pragma unroll
            for (int nf = 0; nf < 2; nf++)
#pragma unroll
                for (int hr = 0; hr < 2; hr++) {
                    const int u = g + hr * 8;
                    const int b0 = nf * 8 + cl;
                    base[b0 * 20 + u]       = acc[nf][hr * 2];
                    base[(b0 + 1) * 20 + u] = acc[nf][hr * 2 + 1];
                }
        }
        __syncthreads();

        if (epi) {
            float gi = p0, gf = p1, gc = p2, go = p3;
#pragma unroll
            for (int k2 = 0; k2 < 4; k2++) {
                gi += sR[((k2 * 4 + 0) * 16 + e_b) * 20 + e_u];
                gf += sR[((k2 * 4 + 1) * 16 + e_b) * 20 + e_u];
                gc += sR[((k2 * 4 + 2) * 16 + e_b) * 20 + e_u];
                go += sR[((k2 * 4 + 3) * 16 + e_b) * 20 + e_u];
            }
            const float si = __fdividef(1.f, 1.f + __expf(-gi));
            const float sf = __fdividef(1.f, 1.f + __expf(-gf));
            const float so = __fdividef(1.f, 1.f + __expf(-go));
            const float tg = 2.f * __fdividef(1.f, 1.f + __expf(-2.f * gc)) - 1.f;
            c = sf * c + si * tg;
            const float tc = 2.f * __fdividef(1.f, 1.f + __expf(-2.f * c)) - 1.f;
            const float hn = so * tc;
            hlast = hn;
            const __half hh = __float2half_rn(hn);
            x16[((size_t)gb * Tn + t) * HIDn + gu] = hh;
            g_hh[(t + 1) & 1][gb * HIDn + gu] = hh;
        }
        __syncthreads();
        if (tid == 0) st_release(&g_flag[cta * 32], base_self + (unsigned)(t + 1));
    }

    if (epi) {
        hout[gb * HIDn + gu] = hlast;
        cout[gb * HIDn + gu] = c;
    }
}

// =============================================================================
extern "C" void kernel_launch(void* const* d_in, const int* in_sizes, int n_in,
                              void* d_out, int out_size)
{
    const float* x      = (const float*)d_in[0];
    const float* states = (const float*)d_in[1];
    const float* W_enc  = (const float*)d_in[2];
    const float* ln_g   = (const float*)d_in[3];
    const float* ln_b   = (const float*)d_in[4];
    const float* Wih1   = (const float*)d_in[5];
    const float* Whh1   = (const float*)d_in[6];
    const float* bih1   = (const float*)d_in[7];
    const float* bhh1   = (const float*)d_in[8];
    const float* Wih2   = (const float*)d_in[9];
    const float* Whh2   = (const float*)d_in[10];
    const float* bih2   = (const float*)d_in[11];
    const float* bhh2   = (const float*)d_in[12];
    const float* Wlin   = (const float*)d_in[13];
    const float* blin   = (const float*)d_in[14];
    const float* W_dec  = (const float*)d_in[15];

    float* out     = (float*)d_out;
    float* dstates = out + (size_t)Bn * FRAMEn * Tn;

    float *encoded, *pre;
    __half *ah, *esth, *estl, *wh, *wl, *wd;
    cudaGetSymbolAddress((void**)&encoded, g_encoded);
    cudaGetSymbolAddress((void**)&pre,     g_pre);
    cudaGetSymbolAddress((void**)&ah,      g_ah);
    cudaGetSymbolAddress((void**)&esth,    g_esth);
    cudaGetSymbolAddress((void**)&estl,    g_estl);
    cudaGetSymbolAddress((void**)&wh,      g_wh);
    cudaGetSymbolAddress((void**)&wl,      g_wl);
    cudaGetSymbolAddress((void**)&wd,      g_wd);

    static int attr_set = 0;
    const int LSTM_SMEM = (64 * 2 + 16) * HROW * 2 + 16 * 320 * 4;   // 170,240 B
    if (!attr_set) {
        cudaFuncSetAttribute(lstm_kernel,
                             cudaFuncAttributeMaxDynamicSharedMemorySize, LSTM_SMEM);
        attr_set = 1;
    }

    const int BH = Bn * HIDn;
    const int BT = Bn * Tn;

    // 1) encoder: xT fp16 (into g_ah), then fp16 2-pass HMMA (z = batch)
    tx16_kernel<<<dim3(Tn / 32, FRAMEn / 32, Bn), 256>>>(x, ah);
    split_kernel<<<(ENCn * FRAMEn / 4 + 255) / 256, 256>>>(W_enc, wh, wl,
                                                           ENCn * FRAMEn / 4);
    gemm_h<2><<<dim3(ENCn / 128, Tn / 128, Bn), 256>>>(
        ah, wh, wl, encoded, 0, 0, 0, 0, 0, Tn, ENCn, FRAMEn,
        (size_t)Tn * FRAMEn, 0, (size_t)Tn * ENCn);

    // 2) layernorm -> fp16 (overwrites g_ah; xT is dead)
    ln_kernel<<<BT / 8, 256>>>(encoded, ah, ln_g, ln_b);

    // 3) pre1
    split_kernel<<<(G4n * ENCn / 4 + 255) / 256, 256>>>(Wih1, wh, wl, G4n * ENCn / 4);
    gemm_h<0><<<dim3(G4n / 128, BT / 128, 1), 256>>>(
        ah, wh, wl, pre, 0, bih1, bhh1, 0, 0, BT, G4n, ENCn, 0, 0, 0);

    // 4) LSTM layer 1
    split_kernel<<<(G4n * HIDn / 4 + 255) / 256, 256>>>(Whh1, wh, wl, G4n * HIDn / 4);
    lstm_kernel<<<NBLK, 512, LSTM_SMEM>>>(
        pre, wh, wl, states + 0 * BH, states + 1 * BH,
        ah, dstates + 0 * BH, dstates + 1 * BH);

    // 5) pre2
    split_kernel<<<(G4n * HIDn / 4 + 255) / 256, 256>>>(Wih2, wh, wl, G4n * HIDn / 4);
    gemm_h<0><<<dim3(G4n / 128, BT / 128, 1), 256>>>(
        ah, wh, wl, pre, 0, bih2, bhh2, 0, 0, BT, G4n, HIDn, 0, 0, 0);

    // 6) LSTM layer 2
    split_kernel<<<(G4n * HIDn / 4 + 255) / 256, 256>>>(Whh2, wh, wl, G4n * HIDn / 4);
    lstm_kernel<<<NBLK, 512, LSTM_SMEM>>>(
        pre, wh, wl, states + 2 * BH, states + 3 * BH,
        ah, dstates + 2 * BH, dstates + 3 * BH);

    // 7) est = sigmoid(x2 @ Wlin^T + blin) * encoded -> fp16 hi/lo
    split_kernel<<<(ENCn * HIDn / 4 + 255) / 256, 256>>>(Wlin, wh, wl, ENCn * HIDn / 4);
    gemm_h<1><<<dim3(ENCn / 128, BT / 128, 1), 256>>>(
        ah, wh, wl, 0, encoded, blin, 0, esth, estl, BT, ENCn, HIDn, 0, 0, 0);

    // 8) decoder (fp16 2-pass, z = batch on B/C)
    cvt16_kernel<<<(FRAMEn * ENCn / 4 + 255) / 256, 256>>>(W_dec, wd, FRAMEn * ENCn / 4);
    gemm_h<2><<<dim3(Tn / 128, FRAMEn / 128, Bn), 256>>>(
        wd, esth, estl, out, 0, 0, 0, 0, 0, FRAMEn, Tn, ENCn,
        0, (size_t)Tn * ENCn, (size_t)FRAMEn * Tn);
}